// round 7
// baseline (speedup 1.0000x reference)
#include <cuda_runtime.h>
#include <cuda_bf16.h>
#include <math.h>
#include <stdint.h>

// ---------------------------------------------------------------------------
// Problem constants
// ---------------------------------------------------------------------------
#define T_STEPS 512
#define BATCH   256
#define INF     1024
#define HIDDEN  1024
#define WROW    (INF + HIDDEN)
#define NCLS    512
#define BH      (BATCH * HIDDEN)      // 262144
#define TB      (T_STEPS * BATCH)     // 131072
#define NCTAS   128                   // persistent recurrence grid

// ---------------------------------------------------------------------------
// Device-global scratch (allocation-free rule)
// ---------------------------------------------------------------------------
__device__ float g_A[(size_t)T_STEPS * BH];           // x-projection + b_ih (fp32)
__device__ float g_Hlast[BH];                          // final hidden state (fp32)
__device__ __nv_bfloat16 g_Xh[(size_t)TB * INF];      // X split hi
__device__ __nv_bfloat16 g_Xl[(size_t)TB * INF];      // X split lo
__device__ __nv_bfloat16 g_Hh[(size_t)T_STEPS * BH];  // H split hi
__device__ __nv_bfloat16 g_Hl[(size_t)T_STEPS * BH];  // H split lo
__device__ __nv_bfloat16 g_Wih_h[HIDDEN * WROW];      // W_ih hi (row stride WROW)
__device__ __nv_bfloat16 g_Wih_l[HIDDEN * WROW];
__device__ __nv_bfloat16 g_Who_h[NCLS * HIDDEN];      // W_ho hi
__device__ __nv_bfloat16 g_Who_l[NCLS * HIDDEN];
__device__ __nv_bfloat16 g_h0h[BH];                   // h0 split hi
__device__ __nv_bfloat16 g_h0l[BH];
// Fine-grained dataflow flags: g_flag[m][n] = (#steps published by CTA(m,n)),
// monotonic across graph replays (each CTA reads its own base at entry).
__device__ unsigned g_flag[4][32];

// ---------------------------------------------------------------------------
// Portable PTX helpers (sm_80+ features only)
// ---------------------------------------------------------------------------
__device__ __forceinline__ uint32_t smem_to_u32(const void* p) {
    uint32_t a;
    asm("{ .reg .u64 t; cvta.to.shared.u64 t, %1; cvt.u32.u64 %0, t; }"
        : "=r"(a) : "l"(p));
    return a;
}

__device__ __forceinline__ void cp16(uint32_t dst, const void* src) {
    asm volatile("cp.async.cg.shared.global [%0], [%1], 16;"
                 :: "r"(dst), "l"(__cvta_generic_to_global(src)));
}
#define CP_COMMIT()  asm volatile("cp.async.commit_group;" ::: "memory")
#define CP_WAIT(n)   asm volatile("cp.async.wait_group %0;" :: "n"(n) : "memory")

#define LDSM4(r0, r1, r2, r3, addr) \
    asm volatile("ldmatrix.sync.aligned.m8n8.x4.shared.b16 {%0,%1,%2,%3}, [%4];" \
                 : "=r"(r0), "=r"(r1), "=r"(r2), "=r"(r3) : "r"(addr))
#define LDSM2(r0, r1, addr) \
    asm volatile("ldmatrix.sync.aligned.m8n8.x2.shared.b16 {%0,%1}, [%2];" \
                 : "=r"(r0), "=r"(r1) : "r"(addr))

// D[16x8] += A[16x16] * B[16x8]^(col)  -- bf16 in, fp32 accum
__device__ __forceinline__ void mma_bf16(float* c, const uint32_t* a, const uint32_t* b) {
    asm volatile(
        "mma.sync.aligned.m16n8k16.row.col.f32.bf16.bf16.f32 "
        "{%0,%1,%2,%3}, {%4,%5,%6,%7}, {%8,%9}, {%0,%1,%2,%3};"
        : "+f"(c[0]), "+f"(c[1]), "+f"(c[2]), "+f"(c[3])
        : "r"(a[0]), "r"(a[1]), "r"(a[2]), "r"(a[3]), "r"(b[0]), "r"(b[1]));
}

// ---------------------------------------------------------------------------
// fp32 -> (hi, lo) bf16 split
// ---------------------------------------------------------------------------
__device__ __forceinline__ void split1(float v, __nv_bfloat16& h, __nv_bfloat16& l) {
    h = __float2bfloat16(v);
    l = __float2bfloat16(v - __bfloat162float(h));
}

__device__ __forceinline__ void split4_store(float4 v, __nv_bfloat16* hi, __nv_bfloat16* lo)
{
    __nv_bfloat16 h0, h1, h2, h3, l0, l1, l2, l3;
    split1(v.x, h0, l0); split1(v.y, h1, l1);
    split1(v.z, h2, l2); split1(v.w, h3, l3);
    __nv_bfloat162 t;
    t.x = h0; t.y = h1; *(__nv_bfloat162*)(hi)     = t;
    t.x = h2; t.y = h3; *(__nv_bfloat162*)(hi + 2) = t;
    t.x = l0; t.y = l1; *(__nv_bfloat162*)(lo)     = t;
    t.x = l2; t.y = l3; *(__nv_bfloat162*)(lo + 2) = t;
}

// X split (contiguous)
__global__ void split_mat(const float* __restrict__ src, long n,
                          __nv_bfloat16* __restrict__ hi, __nv_bfloat16* __restrict__ lo)
{
    for (long i = blockIdx.x * (long)blockDim.x + threadIdx.x; i < n / 4;
         i += (long)gridDim.x * blockDim.x) {
        long e = i * 4;
        split4_store(*(const float4*)(src + e), hi + e, lo + e);
    }
}

// Fused parameter split: W_ih + W_ho + h0 in one launch (all contiguous)
__global__ void split_params(const float* __restrict__ W_ih,
                             const float* __restrict__ W_ho,
                             const float* __restrict__ h0)
{
    const long n1 = (long)HIDDEN * WROW / 4;
    const long n2 = (long)NCLS * HIDDEN / 4;
    const long n3 = (long)BH / 4;
    for (long i = blockIdx.x * (long)blockDim.x + threadIdx.x; i < n1 + n2 + n3;
         i += (long)gridDim.x * blockDim.x) {
        const float* s; __nv_bfloat16 *hi, *lo; long e;
        if (i < n1)            { s = W_ih; hi = g_Wih_h; lo = g_Wih_l; e = i * 4; }
        else if (i < n1 + n2)  { s = W_ho; hi = g_Who_h; lo = g_Who_l; e = (i - n1) * 4; }
        else                   { s = h0;   hi = g_h0h;   lo = g_h0l;   e = (i - n1 - n2) * 4; }
        split4_store(*(const float4*)(s + e), hi + e, lo + e);
    }
}

// ---------------------------------------------------------------------------
// mma.sync bf16x3 GEMM (phases 1 & 3 -- at legacy-HMMA x3 roofline, unchanged)
// ---------------------------------------------------------------------------
#define ROWB   80
#define G_MAT  (128 * ROWB)
#define G_STG  (4 * G_MAT)
#define G_SMEM (2 * G_STG)           // 81920

__global__ void __launch_bounds__(256, 1)
gemm_mma_x3(const __nv_bfloat16* __restrict__ Ah, const __nv_bfloat16* __restrict__ Al, long lda,
            const __nv_bfloat16* __restrict__ Bh, const __nv_bfloat16* __restrict__ Bl, long ldb,
            const float* __restrict__ bias, float* __restrict__ C, long ldc, int K)
{
    extern __shared__ char smem[];
    const uint32_t sb = smem_to_u32(smem);
    const int tid = threadIdx.x, lane = tid & 31, wid = tid >> 5;
    const int wm = wid & 3, wn = wid >> 2;
    const long bm = (long)blockIdx.y * 128;
    const long bn = (long)blockIdx.x * 128;

    float c[2][8][4];
#pragma unroll
    for (int m = 0; m < 2; m++)
#pragma unroll
        for (int n = 0; n < 8; n++)
#pragma unroll
            for (int j = 0; j < 4; j++) c[m][n][j] = 0.0f;

    const uint32_t a_rb = (uint32_t)(lane & 15) * ROWB + (uint32_t)(lane >> 4) * 16;
    const uint32_t b_rb = (uint32_t)(lane & 7) * ROWB + (uint32_t)((lane >> 3) & 1) * 16;

    auto load_chunk = [&](int kc, int stage) {
        uint32_t base = sb + stage * G_STG;
#pragma unroll
        for (int it = 0; it < 2; it++) {
            int u = tid + it * 256;
            int row = u >> 2, seg = u & 3;
            uint32_t so = row * ROWB + seg * 16;
            long ga = (bm + row) * lda + kc + seg * 8;
            long gb = (bn + row) * ldb + kc + seg * 8;
            cp16(base + so,             Ah + ga);
            cp16(base + G_MAT + so,     Al + ga);
            cp16(base + 2 * G_MAT + so, Bh + gb);
            cp16(base + 3 * G_MAT + so, Bl + gb);
        }
    };

    const int nchunk = K >> 5;
    load_chunk(0, 0);
    CP_COMMIT();

    for (int ch = 0; ch < nchunk; ch++) {
        if (ch + 1 < nchunk) {
            load_chunk((ch + 1) << 5, (ch + 1) & 1);
            CP_COMMIT();
            CP_WAIT(1);
        } else {
            CP_WAIT(0);
        }
        __syncthreads();

        const uint32_t base = sb + (ch & 1) * G_STG;
#pragma unroll
        for (int k16 = 0; k16 < 2; k16++) {
            const uint32_t kb = k16 * 32;
            uint32_t ah[2][4], al[2][4], bh[8][2], bl[8][2];
#pragma unroll
            for (int m = 0; m < 2; m++) {
                uint32_t ra = base + (uint32_t)(wm * 32 + m * 16) * ROWB + kb + a_rb;
                LDSM4(ah[m][0], ah[m][1], ah[m][2], ah[m][3], ra);
                LDSM4(al[m][0], al[m][1], al[m][2], al[m][3], ra + G_MAT);
            }
#pragma unroll
            for (int n = 0; n < 8; n++) {
                uint32_t rb = base + 2 * G_MAT + (uint32_t)(wn * 64 + n * 8) * ROWB + kb + b_rb;
                LDSM2(bh[n][0], bh[n][1], rb);
                LDSM2(bl[n][0], bl[n][1], rb + G_MAT);
            }
#pragma unroll
            for (int m = 0; m < 2; m++)
#pragma unroll
                for (int n = 0; n < 8; n++) {
                    mma_bf16(c[m][n], ah[m], bh[n]);
                    mma_bf16(c[m][n], al[m], bh[n]);
                    mma_bf16(c[m][n], ah[m], bl[n]);
                }
        }
        __syncthreads();
    }

#pragma unroll
    for (int m = 0; m < 2; m++) {
        long r0 = bm + wm * 32 + m * 16 + (lane >> 2);
        long r1 = r0 + 8;
#pragma unroll
        for (int n = 0; n < 8; n++) {
            long col = bn + wn * 64 + n * 8 + (lane & 3) * 2;
            float bx = bias[col], by = bias[col + 1];
            float2 v0 = { c[m][n][0] + bx, c[m][n][1] + by };
            float2 v1 = { c[m][n][2] + bx, c[m][n][3] + by };
            *(float2*)(C + r0 * ldc + col) = v0;
            *(float2*)(C + r1 * ldc + col) = v1;
        }
    }
}

// ---------------------------------------------------------------------------
// Persistent recurrence v4:  h_t = tanh(g_A[t] + h_{t-1} @ W_h^T)
// 128 CTAs = (m in 0..3) x (n in 0..31); CTA tile 64(batch) x 32(hidden).
// W_h hi+lo resident in smem.  Per chunk (BK=128) waits only on the 4
// producer flags covering that k-range -- NO global barrier.  Chunks are
// consumed in rotated order starting at the CTA's own tile.
// ---------------------------------------------------------------------------
#define A_ROWB     272                        // 256B data + 16 pad
#define RB_ROWB    2064                       // 2048B data + 16 pad
#define RB_SZ      (32 * RB_ROWB)             // 66048 per matrix
#define R_OFF_BL   RB_SZ
#define R_OFF_STG  (2 * RB_SZ)                // 132096
#define RA_SZ      (64 * A_ROWB)              // 17408 per matrix
#define R_STG      (2 * RA_SZ)                // 34816 (Ah | Al)
#define R_SMEM     (R_OFF_STG + 2 * R_STG)    // 201728

__global__ void __launch_bounds__(256, 1)
rnn_recur()
{
    extern __shared__ char smem[];
    const uint32_t sb = smem_to_u32(smem);
    const int tid = threadIdx.x, lane = tid & 31, wid = tid >> 5;
    const int wm = wid & 3, wn = wid >> 2;        // 4 x 2 warp grid
    const int gm = blockIdx.x >> 5;               // m group (0..3)
    const int gn = blockIdx.x & 31;               // n tile  (0..31)
    const int bm = gm * 64;
    const int bn = gn * 32;

    // Own flag base (only self writes it; all flags equal at launch)
    const unsigned base = *(volatile unsigned*)&g_flag[gm][gn];
    // Register cache of producer flags (threads 0-3 track lane tid of each chunk)
    unsigned fcache[8];
#pragma unroll
    for (int i = 0; i < 8; i++) fcache[i] = base;

    const uint32_t a_rb = (uint32_t)(lane & 15) * A_ROWB + (uint32_t)(lane >> 4) * 16;
    const uint32_t b_rb = (uint32_t)(lane & 7) * RB_ROWB + (uint32_t)((lane >> 3) & 1) * 16;

    // ---- Resident W_h tiles: 32 rows x 1024 bf16, hi then lo
    for (int u = tid; u < 4096; u += 256) {
        int row = u >> 7, seg = u & 127;
        size_t g = (size_t)(bn + row) * WROW + INF + seg * 8;
        cp16(sb + row * RB_ROWB + seg * 16,            g_Wih_h + g);
        cp16(sb + R_OFF_BL + row * RB_ROWB + seg * 16, g_Wih_l + g);
    }
    CP_COMMIT();

    const int sa_row = tid >> 2, sa_seg4 = (tid & 3) * 4;
    const int warp_base = wm * 16;
    const uint32_t bboff = (uint32_t)(wn * 16) * RB_ROWB;
    const int start = gn >> 2;                    // rotation: own chunk first

    for (int t = 0; t < T_STEPS; t++) {
        const __nv_bfloat16* hh = (t == 0) ? g_h0h : (g_Hh + (size_t)(t - 1) * BH);
        const __nv_bfloat16* hl = (t == 0) ? g_h0l : (g_Hl + (size_t)(t - 1) * BH);
        const size_t ob = (size_t)t * BH;
        const unsigned target = base + (unsigned)t;   // producers published t steps

        // Epilogue pre-activation prefetch (independent of h_{t-1})
        const int er0 = bm + wm * 16 + (lane >> 2);
        const int ec0 = bn + wn * 16 + (lane & 3) * 2;
        float2 pre[2][2];
#pragma unroll
        for (int n = 0; n < 2; n++) {
            pre[n][0] = *(const float2*)(g_A + ob + (size_t)er0       * HIDDEN + ec0 + n * 8);
            pre[n][1] = *(const float2*)(g_A + ob + (size_t)(er0 + 8) * HIDDEN + ec0 + n * 8);
        }

        float c[2][4];
#pragma unroll
        for (int n = 0; n < 2; n++)
#pragma unroll
            for (int j = 0; j < 4; j++) c[n][j] = 0.0f;

        // wait for the 4 producers of chunk cc (no-op at t==0 and when cached)
        auto wait_chunk = [&](int cc) {
            if (tid < 4) {
                if (fcache[cc] < target) {
                    volatile unsigned* f = &g_flag[gm][cc * 4 + tid];
                    unsigned v;
                    while ((v = *f) < target) __nanosleep(32);
                    fcache[cc] = v;
                    __threadfence();
                }
            }
            __syncthreads();
        };

        auto load_chunk = [&](int cc, int stage) {
            uint32_t sbase = sb + R_OFF_STG + stage * R_STG;
            uint32_t so = sa_row * A_ROWB + sa_seg4 * 16;
            size_t g = (size_t)(bm + sa_row) * HIDDEN + (cc << 7) + sa_seg4 * 8;
#pragma unroll
            for (int s = 0; s < 4; s++) {
                cp16(sbase + so + s * 16,         hh + g + s * 8);
                cp16(sbase + RA_SZ + so + s * 16, hl + g + s * 8);
            }
        };

        wait_chunk(start);
        load_chunk(start, 0);
        CP_COMMIT();

        for (int i = 0; i < 8; i++) {
            const int cc = (start + i) & 7;
            if (i < 7) {
                const int ccn = (start + i + 1) & 7;
                wait_chunk(ccn);                      // includes __syncthreads
                load_chunk(ccn, (i + 1) & 1);
                CP_COMMIT();
                CP_WAIT(1);
            } else {
                CP_WAIT(0);
            }
            __syncthreads();

            const uint32_t abase = sb + R_OFF_STG + (i & 1) * R_STG
                                   + (uint32_t)warp_base * A_ROWB + a_rb;
            const uint32_t bbase = sb + bboff + (uint32_t)(cc << 8) + b_rb;

            uint32_t ah[2][4], al[2][4], bh[2][2][2], bl[2][2][2];

#define R_LDSM(k16, buf) do { \
        uint32_t _ra = abase + (uint32_t)((k16) * 32); \
        LDSM4(ah[buf][0], ah[buf][1], ah[buf][2], ah[buf][3], _ra); \
        LDSM4(al[buf][0], al[buf][1], al[buf][2], al[buf][3], _ra + RA_SZ); \
        uint32_t _rb0 = bbase + (uint32_t)((k16) * 32); \
        LDSM2(bh[buf][0][0], bh[buf][0][1], _rb0); \
        LDSM2(bl[buf][0][0], bl[buf][0][1], _rb0 + R_OFF_BL); \
        uint32_t _rb1 = _rb0 + 8 * RB_ROWB; \
        LDSM2(bh[buf][1][0], bh[buf][1][1], _rb1); \
        LDSM2(bl[buf][1][0], bl[buf][1][1], _rb1 + R_OFF_BL); \
    } while (0)

            R_LDSM(0, 0);
#pragma unroll
            for (int k16 = 0; k16 < 8; k16++) {
                if (k16 < 7) R_LDSM(k16 + 1, (k16 + 1) & 1);
                const int b = k16 & 1;
#pragma unroll
                for (int n = 0; n < 2; n++) {
                    mma_bf16(c[n], ah[b], bh[b][n]);
                    mma_bf16(c[n], al[b], bh[b][n]);
                    mma_bf16(c[n], ah[b], bl[b][n]);
                }
            }
#undef R_LDSM
        }

        // Epilogue: tanh(acc + pre), split to bf16 hi/lo, publish flag
        {
            const int r0 = er0, r1 = er0 + 8;
#pragma unroll
            for (int n = 0; n < 2; n++) {
                const int col = ec0 + n * 8;
                float h00 = tanhf(c[n][0] + pre[n][0].x);
                float h01 = tanhf(c[n][1] + pre[n][0].y);
                float h10 = tanhf(c[n][2] + pre[n][1].x);
                float h11 = tanhf(c[n][3] + pre[n][1].y);

                __nv_bfloat16 hb, lb;
                __nv_bfloat162 th, tl;
                split1(h00, hb, lb); th.x = hb; tl.x = lb;
                split1(h01, hb, lb); th.y = hb; tl.y = lb;
                *(__nv_bfloat162*)(g_Hh + ob + (size_t)r0 * HIDDEN + col) = th;
                *(__nv_bfloat162*)(g_Hl + ob + (size_t)r0 * HIDDEN + col) = tl;
                split1(h10, hb, lb); th.x = hb; tl.x = lb;
                split1(h11, hb, lb); th.y = hb; tl.y = lb;
                *(__nv_bfloat162*)(g_Hh + ob + (size_t)r1 * HIDDEN + col) = th;
                *(__nv_bfloat162*)(g_Hl + ob + (size_t)r1 * HIDDEN + col) = tl;

                if (t == T_STEPS - 1) {
                    float2 f0 = { h00, h01 }, f1 = { h10, h11 };
                    *(float2*)(g_Hlast + (size_t)r0 * HIDDEN + col) = f0;
                    *(float2*)(g_Hlast + (size_t)r1 * HIDDEN + col) = f1;
                }
            }
        }
        __syncthreads();          // all stores of this CTA done
        __threadfence();          // publish to device scope
        if (tid == 0)
            atomicExch(&g_flag[gm][gn], base + (unsigned)t + 1u);
    }
}

// ---------------------------------------------------------------------------
// In-place softmax over rows of 512 floats
// ---------------------------------------------------------------------------
__global__ void softmax512(float* __restrict__ O)
{
    __shared__ float red[4];
    long row = blockIdx.x;
    float4* p = (float4*)(O + row * (long)NCLS);
    float4 v = p[threadIdx.x];

    float m = fmaxf(fmaxf(v.x, v.y), fmaxf(v.z, v.w));
#pragma unroll
    for (int o = 16; o > 0; o >>= 1)
        m = fmaxf(m, __shfl_xor_sync(0xffffffffu, m, o));
    int warp = threadIdx.x >> 5;
    if ((threadIdx.x & 31) == 0) red[warp] = m;
    __syncthreads();
    m = fmaxf(fmaxf(red[0], red[1]), fmaxf(red[2], red[3]));

    float4 e;
    e.x = __expf(v.x - m);
    e.y = __expf(v.y - m);
    e.z = __expf(v.z - m);
    e.w = __expf(v.w - m);
    float s = e.x + e.y + e.z + e.w;
#pragma unroll
    for (int o = 16; o > 0; o >>= 1)
        s += __shfl_xor_sync(0xffffffffu, s, o);
    __syncthreads();
    if ((threadIdx.x & 31) == 0) red[warp] = s;
    __syncthreads();
    s = red[0] + red[1] + red[2] + red[3];

    float inv = 1.0f / s;
    e.x *= inv; e.y *= inv; e.z *= inv; e.w *= inv;
    p[threadIdx.x] = e;
}

// ---------------------------------------------------------------------------
// Launch (7 graph nodes; rnn_recur is the 4th kernel -> gets ncu-captured)
// ---------------------------------------------------------------------------
extern "C" void kernel_launch(void* const* d_in, const int* in_sizes, int n_in,
                              void* d_out, int out_size)
{
    const float* x    = (const float*)d_in[0];
    const float* h0   = (const float*)d_in[1];
    const float* W_ih = (const float*)d_in[2];
    const float* b_ih = (const float*)d_in[3];
    const float* W_ho = (const float*)d_in[4];
    const float* b_ho = (const float*)d_in[5];
    float*       out  = (float*)d_out;

    float *pA, *pHlast;
    __nv_bfloat16 *pXh, *pXl, *pHh, *pHl, *pWih_h, *pWih_l, *pWoh, *pWol;
    cudaGetSymbolAddress((void**)&pA,     g_A);
    cudaGetSymbolAddress((void**)&pHlast, g_Hlast);
    cudaGetSymbolAddress((void**)&pXh,    g_Xh);
    cudaGetSymbolAddress((void**)&pXl,    g_Xl);
    cudaGetSymbolAddress((void**)&pHh,    g_Hh);
    cudaGetSymbolAddress((void**)&pHl,    g_Hl);
    cudaGetSymbolAddress((void**)&pWih_h, g_Wih_h);
    cudaGetSymbolAddress((void**)&pWih_l, g_Wih_l);
    cudaGetSymbolAddress((void**)&pWoh,   g_Who_h);
    cudaGetSymbolAddress((void**)&pWol,   g_Who_l);

    cudaFuncSetAttribute(gemm_mma_x3,
                         cudaFuncAttributeMaxDynamicSharedMemorySize, G_SMEM);
    cudaFuncSetAttribute(rnn_recur,
                         cudaFuncAttributeMaxDynamicSharedMemorySize, R_SMEM);

    // #1: X split; #2: fused param splits (W_ih, W_ho, h0)
    split_mat<<<4096, 256>>>(x, (long)TB * INF, pXh, pXl);
    split_params<<<1024, 256>>>(W_ih, W_ho, h0);

    // #3: Phase 1 -- g_A = X @ Wx^T + b_ih
    {
        dim3 grid(HIDDEN / 128, TB / 128);   // (8, 1024)
        gemm_mma_x3<<<grid, 256, G_SMEM>>>(pXh, pXl, INF,
                                           pWih_h, pWih_l, WROW,
                                           b_ih, pA, HIDDEN, INF);
    }

    // #4: Phase 2 -- persistent recurrence (flag-based dataflow, no grid barrier)
    rnn_recur<<<NCTAS, 256, R_SMEM>>>();

    // #5/#6: Phase 3 -- out = H @ W_ho^T + b_ho, then in-place softmax
    {
        dim3 grid(NCLS / 128, TB / 128);     // (4, 1024)
        gemm_mma_x3<<<grid, 256, G_SMEM>>>(pHh, pHl, HIDDEN,
                                           pWoh, pWol, HIDDEN,
                                           b_ho, out, NCLS, HIDDEN);
        softmax512<<<TB, 128>>>(out);
    }

    // #7: h_last
    cudaMemcpyAsync(out + (long)TB * NCLS, pHlast,
                    (size_t)BH * sizeof(float), cudaMemcpyDeviceToDevice);
}

// round 8
// speedup vs baseline: 1.4149x; 1.4149x over previous
#include <cuda_runtime.h>
#include <cuda_bf16.h>
#include <math.h>
#include <stdint.h>

// ---------------------------------------------------------------------------
// Problem constants
// ---------------------------------------------------------------------------
#define T_STEPS 512
#define BATCH   256
#define INF     1024
#define HIDDEN  1024
#define WROW    (INF + HIDDEN)
#define NCLS    512
#define BH      (BATCH * HIDDEN)      // 262144
#define TB      (T_STEPS * BATCH)     // 131072
#define NCTAS   128                   // persistent recurrence grid
#define NGRP    8                     // independent recurrence groups
#define GRP_CTAS 16                   // CTAs per group

// ---------------------------------------------------------------------------
// Device-global scratch (allocation-free rule)
// ---------------------------------------------------------------------------
__device__ float g_A[(size_t)T_STEPS * BH];           // x-projection + b_ih (fp32)
__device__ float g_Hlast[BH];                          // final hidden state (fp32)
__device__ __nv_bfloat16 g_Xh[(size_t)TB * INF];      // X split hi
__device__ __nv_bfloat16 g_Xl[(size_t)TB * INF];      // X split lo
__device__ __nv_bfloat16 g_Hh[(size_t)T_STEPS * BH];  // H split hi
__device__ __nv_bfloat16 g_Hl[(size_t)T_STEPS * BH];  // H split lo
__device__ __nv_bfloat16 g_Wih_h[HIDDEN * WROW];      // W_ih hi (row stride WROW)
__device__ __nv_bfloat16 g_Wih_l[HIDDEN * WROW];
__device__ __nv_bfloat16 g_Who_h[NCLS * HIDDEN];      // W_ho hi
__device__ __nv_bfloat16 g_Who_l[NCLS * HIDDEN];
__device__ __nv_bfloat16 g_h0h[BH];                   // h0 split hi
__device__ __nv_bfloat16 g_h0l[BH];
// Per-group barrier state, padded to separate cache lines; gens monotonic
// across graph replays (each CTA reads its group's base before first arrival).
__device__ unsigned g_gcnt[NGRP * 32];
__device__ unsigned g_ggen[NGRP * 32];

// ---------------------------------------------------------------------------
// Portable PTX helpers (sm_80+ features only)
// ---------------------------------------------------------------------------
__device__ __forceinline__ uint32_t smem_to_u32(const void* p) {
    uint32_t a;
    asm("{ .reg .u64 t; cvta.to.shared.u64 t, %1; cvt.u32.u64 %0, t; }"
        : "=r"(a) : "l"(p));
    return a;
}

__device__ __forceinline__ void cp16(uint32_t dst, const void* src) {
    asm volatile("cp.async.cg.shared.global [%0], [%1], 16;"
                 :: "r"(dst), "l"(__cvta_generic_to_global(src)));
}
#define CP_COMMIT()  asm volatile("cp.async.commit_group;" ::: "memory")
#define CP_WAIT(n)   asm volatile("cp.async.wait_group %0;" :: "n"(n) : "memory")

#define LDSM4(r0, r1, r2, r3, addr) \
    asm volatile("ldmatrix.sync.aligned.m8n8.x4.shared.b16 {%0,%1,%2,%3}, [%4];" \
                 : "=r"(r0), "=r"(r1), "=r"(r2), "=r"(r3) : "r"(addr))
#define LDSM2(r0, r1, addr) \
    asm volatile("ldmatrix.sync.aligned.m8n8.x2.shared.b16 {%0,%1}, [%2];" \
                 : "=r"(r0), "=r"(r1) : "r"(addr))

// D[16x8] += A[16x16] * B[16x8]^(col)  -- bf16 in, fp32 accum
__device__ __forceinline__ void mma_bf16(float* c, const uint32_t* a, const uint32_t* b) {
    asm volatile(
        "mma.sync.aligned.m16n8k16.row.col.f32.bf16.bf16.f32 "
        "{%0,%1,%2,%3}, {%4,%5,%6,%7}, {%8,%9}, {%0,%1,%2,%3};"
        : "+f"(c[0]), "+f"(c[1]), "+f"(c[2]), "+f"(c[3])
        : "r"(a[0]), "r"(a[1]), "r"(a[2]), "r"(a[3]), "r"(b[0]), "r"(b[1]));
}

// ---------------------------------------------------------------------------
// fp32 -> (hi, lo) bf16 split
// ---------------------------------------------------------------------------
__device__ __forceinline__ void split1(float v, __nv_bfloat16& h, __nv_bfloat16& l) {
    h = __float2bfloat16(v);
    l = __float2bfloat16(v - __bfloat162float(h));
}

__device__ __forceinline__ void split4_store(float4 v, __nv_bfloat16* hi, __nv_bfloat16* lo)
{
    __nv_bfloat16 h0, h1, h2, h3, l0, l1, l2, l3;
    split1(v.x, h0, l0); split1(v.y, h1, l1);
    split1(v.z, h2, l2); split1(v.w, h3, l3);
    __nv_bfloat162 t;
    t.x = h0; t.y = h1; *(__nv_bfloat162*)(hi)     = t;
    t.x = h2; t.y = h3; *(__nv_bfloat162*)(hi + 2) = t;
    t.x = l0; t.y = l1; *(__nv_bfloat162*)(lo)     = t;
    t.x = l2; t.y = l3; *(__nv_bfloat162*)(lo + 2) = t;
}

// X split (contiguous)
__global__ void split_mat(const float* __restrict__ src, long n,
                          __nv_bfloat16* __restrict__ hi, __nv_bfloat16* __restrict__ lo)
{
    for (long i = blockIdx.x * (long)blockDim.x + threadIdx.x; i < n / 4;
         i += (long)gridDim.x * blockDim.x) {
        long e = i * 4;
        split4_store(*(const float4*)(src + e), hi + e, lo + e);
    }
}

// Fused parameter split: W_ih + W_ho + h0 in one launch (all contiguous)
__global__ void split_params(const float* __restrict__ W_ih,
                             const float* __restrict__ W_ho,
                             const float* __restrict__ h0)
{
    const long n1 = (long)HIDDEN * WROW / 4;
    const long n2 = (long)NCLS * HIDDEN / 4;
    const long n3 = (long)BH / 4;
    for (long i = blockIdx.x * (long)blockDim.x + threadIdx.x; i < n1 + n2 + n3;
         i += (long)gridDim.x * blockDim.x) {
        const float* s; __nv_bfloat16 *hi, *lo; long e;
        if (i < n1)            { s = W_ih; hi = g_Wih_h; lo = g_Wih_l; e = i * 4; }
        else if (i < n1 + n2)  { s = W_ho; hi = g_Who_h; lo = g_Who_l; e = (i - n1) * 4; }
        else                   { s = h0;   hi = g_h0h;   lo = g_h0l;   e = (i - n1 - n2) * 4; }
        split4_store(*(const float4*)(s + e), hi + e, lo + e);
    }
}

// ---------------------------------------------------------------------------
// mma.sync bf16x3 GEMM (phases 1 & 3 -- at legacy-HMMA x3 roofline, unchanged)
// ---------------------------------------------------------------------------
#define ROWB   80
#define G_MAT  (128 * ROWB)
#define G_STG  (4 * G_MAT)
#define G_SMEM (2 * G_STG)           // 81920

__global__ void __launch_bounds__(256, 1)
gemm_mma_x3(const __nv_bfloat16* __restrict__ Ah, const __nv_bfloat16* __restrict__ Al, long lda,
            const __nv_bfloat16* __restrict__ Bh, const __nv_bfloat16* __restrict__ Bl, long ldb,
            const float* __restrict__ bias, float* __restrict__ C, long ldc, int K)
{
    extern __shared__ char smem[];
    const uint32_t sb = smem_to_u32(smem);
    const int tid = threadIdx.x, lane = tid & 31, wid = tid >> 5;
    const int wm = wid & 3, wn = wid >> 2;
    const long bm = (long)blockIdx.y * 128;
    const long bn = (long)blockIdx.x * 128;

    float c[2][8][4];
#pragma unroll
    for (int m = 0; m < 2; m++)
#pragma unroll
        for (int n = 0; n < 8; n++)
#pragma unroll
            for (int j = 0; j < 4; j++) c[m][n][j] = 0.0f;

    const uint32_t a_rb = (uint32_t)(lane & 15) * ROWB + (uint32_t)(lane >> 4) * 16;
    const uint32_t b_rb = (uint32_t)(lane & 7) * ROWB + (uint32_t)((lane >> 3) & 1) * 16;

    auto load_chunk = [&](int kc, int stage) {
        uint32_t base = sb + stage * G_STG;
#pragma unroll
        for (int it = 0; it < 2; it++) {
            int u = tid + it * 256;
            int row = u >> 2, seg = u & 3;
            uint32_t so = row * ROWB + seg * 16;
            long ga = (bm + row) * lda + kc + seg * 8;
            long gb = (bn + row) * ldb + kc + seg * 8;
            cp16(base + so,             Ah + ga);
            cp16(base + G_MAT + so,     Al + ga);
            cp16(base + 2 * G_MAT + so, Bh + gb);
            cp16(base + 3 * G_MAT + so, Bl + gb);
        }
    };

    const int nchunk = K >> 5;
    load_chunk(0, 0);
    CP_COMMIT();

    for (int ch = 0; ch < nchunk; ch++) {
        if (ch + 1 < nchunk) {
            load_chunk((ch + 1) << 5, (ch + 1) & 1);
            CP_COMMIT();
            CP_WAIT(1);
        } else {
            CP_WAIT(0);
        }
        __syncthreads();

        const uint32_t base = sb + (ch & 1) * G_STG;
#pragma unroll
        for (int k16 = 0; k16 < 2; k16++) {
            const uint32_t kb = k16 * 32;
            uint32_t ah[2][4], al[2][4], bh[8][2], bl[8][2];
#pragma unroll
            for (int m = 0; m < 2; m++) {
                uint32_t ra = base + (uint32_t)(wm * 32 + m * 16) * ROWB + kb + a_rb;
                LDSM4(ah[m][0], ah[m][1], ah[m][2], ah[m][3], ra);
                LDSM4(al[m][0], al[m][1], al[m][2], al[m][3], ra + G_MAT);
            }
#pragma unroll
            for (int n = 0; n < 8; n++) {
                uint32_t rb = base + 2 * G_MAT + (uint32_t)(wn * 64 + n * 8) * ROWB + kb + b_rb;
                LDSM2(bh[n][0], bh[n][1], rb);
                LDSM2(bl[n][0], bl[n][1], rb + G_MAT);
            }
#pragma unroll
            for (int m = 0; m < 2; m++)
#pragma unroll
                for (int n = 0; n < 8; n++) {
                    mma_bf16(c[m][n], ah[m], bh[n]);
                    mma_bf16(c[m][n], al[m], bh[n]);
                    mma_bf16(c[m][n], ah[m], bl[n]);
                }
        }
        __syncthreads();
    }

#pragma unroll
    for (int m = 0; m < 2; m++) {
        long r0 = bm + wm * 32 + m * 16 + (lane >> 2);
        long r1 = r0 + 8;
#pragma unroll
        for (int n = 0; n < 8; n++) {
            long col = bn + wn * 64 + n * 8 + (lane & 3) * 2;
            float bx = bias[col], by = bias[col + 1];
            float2 v0 = { c[m][n][0] + bx, c[m][n][1] + by };
            float2 v1 = { c[m][n][2] + bx, c[m][n][3] + by };
            *(float2*)(C + r0 * ldc + col) = v0;
            *(float2*)(C + r1 * ldc + col) = v1;
        }
    }
}

// ---------------------------------------------------------------------------
// Per-group barrier (16 CTAs). Groups are fully decoupled closed systems:
// group g produces AND consumes only h rows [32g, 32g+32).
// ---------------------------------------------------------------------------
__device__ __forceinline__ void group_bar(int g, unsigned& lgen)
{
    __syncthreads();
    if (threadIdx.x == 0) {
        __threadfence();
        if (atomicAdd(&g_gcnt[g * 32], 1u) == GRP_CTAS - 1) {
            atomicExch(&g_gcnt[g * 32], 0u);
            __threadfence();
            atomicAdd(&g_ggen[g * 32], 1u);
        } else {
            while (*(volatile unsigned*)&g_ggen[g * 32] == lgen) { __nanosleep(32); }
            __threadfence();
        }
        lgen++;
    }
    __syncthreads();
}

// ---------------------------------------------------------------------------
// Persistent recurrence (R5 structure + group barriers + BK=64):
//   h_t = tanh(g_A[t] + h_{t-1} @ W_h^T)
// 128 CTAs = 8 groups x 16; CTA tile 32(batch) x 64(hidden); warps 2M x 4N.
// W_h hi tile (64 x 1024 bf16 = 129 KB) resident in smem.
// Streams per chunk (BK=64): Ah (4KB), Al (4KB), Bl (9KB), double-buffered.
// ---------------------------------------------------------------------------
#define ROWB2     144                        // 128B data + 16 pad (streamed)
#define RB_ROWB   2064                       // 2048B data + 16 pad (resident)
#define RBH_SZ    (64 * RB_ROWB)             // 132096
#define RA2_SZ    (32 * ROWB2)               // 4608 per A matrix
#define RBL2_SZ   (64 * ROWB2)               // 9216
#define R2_STG    (2 * RA2_SZ + RBL2_SZ)     // 18432  (Ah | Al | Bl)
#define R2_SMEM   (RBH_SZ + 2 * R2_STG)      // 168960

__global__ void __launch_bounds__(256, 1)
rnn_recur()
{
    extern __shared__ char smem[];
    const uint32_t sb = smem_to_u32(smem);
    const int tid = threadIdx.x, lane = tid & 31, wid = tid >> 5;
    const int wm = wid & 1, wn = wid >> 1;       // 2 x 4 warp grid
    const int grp = blockIdx.x >> 4;             // group (0..7)
    const int bm  = grp * 32;                    // batch rows [bm, bm+32)
    const int bn  = (blockIdx.x & 15) * 64;      // hidden cols [bn, bn+64)

    const uint32_t a_rb  = (uint32_t)(lane & 15) * ROWB2 + (uint32_t)(lane >> 4) * 16;
    const uint32_t bl_rb = (uint32_t)(lane & 7) * ROWB2 + (uint32_t)((lane >> 3) & 1) * 16;
    const uint32_t bh_rb = (uint32_t)(lane & 7) * RB_ROWB + (uint32_t)((lane >> 3) & 1) * 16;

    // ---- Resident W_h hi tile: 64 rows x 1024 bf16 (8192 x 16B units)
    for (int u = tid; u < 8192; u += 256) {
        int row = u >> 7, seg = u & 127;
        cp16(sb + row * RB_ROWB + seg * 16,
             g_Wih_h + (size_t)(bn + row) * WROW + INF + seg * 8);
    }
    CP_COMMIT();

    unsigned lgen = *(volatile unsigned*)&g_ggen[grp * 32];

    for (int t = 0; t < T_STEPS; t++) {
        const __nv_bfloat16* hh = (t == 0) ? g_h0h : (g_Hh + (size_t)(t - 1) * BH);
        const __nv_bfloat16* hl = (t == 0) ? g_h0l : (g_Hl + (size_t)(t - 1) * BH);
        const size_t ob = (size_t)t * BH;

        float c[2][4];
#pragma unroll
        for (int n = 0; n < 2; n++)
#pragma unroll
            for (int j = 0; j < 4; j++) c[n][j] = 0.0f;

        auto load_chunk = [&](int kc, int stage) {
            uint32_t base = sb + RBH_SZ + stage * R2_STG;
            // A hi / A lo: 32 rows x 8 segs = 256 units each
            {
                int row = tid >> 3, seg = tid & 7;
                uint32_t so = row * ROWB2 + seg * 16;
                size_t g = (size_t)(bm + row) * HIDDEN + kc + seg * 8;
                cp16(base + so,          hh + g);
                cp16(base + RA2_SZ + so, hl + g);
            }
            // B lo: 64 rows x 8 segs = 512 units (2/thread)
#pragma unroll
            for (int it = 0; it < 2; it++) {
                int u = tid + it * 256;
                int row = u >> 3, seg = u & 7;
                cp16(base + 2 * RA2_SZ + row * ROWB2 + seg * 16,
                     g_Wih_l + (size_t)(bn + row) * WROW + INF + kc + seg * 8);
            }
        };

        load_chunk(0, 0);
        CP_COMMIT();

        for (int ch = 0; ch < HIDDEN / 64; ch++) {     // 16 chunks
            if (ch + 1 < HIDDEN / 64) {
                load_chunk((ch + 1) << 6, (ch + 1) & 1);
                CP_COMMIT();
                CP_WAIT(1);
            } else {
                CP_WAIT(0);
            }
            __syncthreads();

            const uint32_t base = sb + RBH_SZ + (ch & 1) * R2_STG;
            const uint32_t kres = (uint32_t)(ch << 7);   // 128B per chunk in resident rows
#pragma unroll
            for (int k16 = 0; k16 < 4; k16++) {
                const uint32_t kb = k16 * 32;
                uint32_t ah[4], al[4], bh[2][2], bl[2][2];
                uint32_t ra = base + (uint32_t)(wm * 16) * ROWB2 + kb + a_rb;
                LDSM4(ah[0], ah[1], ah[2], ah[3], ra);
                LDSM4(al[0], al[1], al[2], al[3], ra + RA2_SZ);
#pragma unroll
                for (int n = 0; n < 2; n++) {
                    uint32_t rres = sb + (uint32_t)(wn * 16 + n * 8) * RB_ROWB
                                    + kres + kb + bh_rb;
                    LDSM2(bh[n][0], bh[n][1], rres);
                    uint32_t rbl = base + 2 * RA2_SZ + (uint32_t)(wn * 16 + n * 8) * ROWB2
                                   + kb + bl_rb;
                    LDSM2(bl[n][0], bl[n][1], rbl);
                }
#pragma unroll
                for (int n = 0; n < 2; n++) {
                    mma_bf16(c[n], ah, bh[n]);
                    mma_bf16(c[n], al, bh[n]);
                    mma_bf16(c[n], ah, bl[n]);
                }
            }
            __syncthreads();
        }

        // Epilogue: tanh(acc + pre), split to bf16 hi/lo
        {
            const int r0 = bm + wm * 16 + (lane >> 2);
            const int r1 = r0 + 8;
#pragma unroll
            for (int n = 0; n < 2; n++) {
                const int col = bn + wn * 16 + n * 8 + (lane & 3) * 2;
                float2 p0 = *(const float2*)(g_A + ob + (size_t)r0 * HIDDEN + col);
                float2 p1 = *(const float2*)(g_A + ob + (size_t)r1 * HIDDEN + col);
                float h00 = tanhf(c[n][0] + p0.x);
                float h01 = tanhf(c[n][1] + p0.y);
                float h10 = tanhf(c[n][2] + p1.x);
                float h11 = tanhf(c[n][3] + p1.y);

                __nv_bfloat16 hb, lb;
                __nv_bfloat162 th, tl;
                split1(h00, hb, lb); th.x = hb; tl.x = lb;
                split1(h01, hb, lb); th.y = hb; tl.y = lb;
                *(__nv_bfloat162*)(g_Hh + ob + (size_t)r0 * HIDDEN + col) = th;
                *(__nv_bfloat162*)(g_Hl + ob + (size_t)r0 * HIDDEN + col) = tl;
                split1(h10, hb, lb); th.x = hb; tl.x = lb;
                split1(h11, hb, lb); th.y = hb; tl.y = lb;
                *(__nv_bfloat162*)(g_Hh + ob + (size_t)r1 * HIDDEN + col) = th;
                *(__nv_bfloat162*)(g_Hl + ob + (size_t)r1 * HIDDEN + col) = tl;

                if (t == T_STEPS - 1) {
                    float2 f0 = { h00, h01 }, f1 = { h10, h11 };
                    *(float2*)(g_Hlast + (size_t)r0 * HIDDEN + col) = f0;
                    *(float2*)(g_Hlast + (size_t)r1 * HIDDEN + col) = f1;
                }
            }
        }

        group_bar(grp, lgen);   // 16-CTA rendezvous; groups fully decoupled
    }
}

// ---------------------------------------------------------------------------
// In-place softmax over rows of 512 floats
// ---------------------------------------------------------------------------
__global__ void softmax512(float* __restrict__ O)
{
    __shared__ float red[4];
    long row = blockIdx.x;
    float4* p = (float4*)(O + row * (long)NCLS);
    float4 v = p[threadIdx.x];

    float m = fmaxf(fmaxf(v.x, v.y), fmaxf(v.z, v.w));
#pragma unroll
    for (int o = 16; o > 0; o >>= 1)
        m = fmaxf(m, __shfl_xor_sync(0xffffffffu, m, o));
    int warp = threadIdx.x >> 5;
    if ((threadIdx.x & 31) == 0) red[warp] = m;
    __syncthreads();
    m = fmaxf(fmaxf(red[0], red[1]), fmaxf(red[2], red[3]));

    float4 e;
    e.x = __expf(v.x - m);
    e.y = __expf(v.y - m);
    e.z = __expf(v.z - m);
    e.w = __expf(v.w - m);
    float s = e.x + e.y + e.z + e.w;
#pragma unroll
    for (int o = 16; o > 0; o >>= 1)
        s += __shfl_xor_sync(0xffffffffu, s, o);
    __syncthreads();
    if ((threadIdx.x & 31) == 0) red[warp] = s;
    __syncthreads();
    s = red[0] + red[1] + red[2] + red[3];

    float inv = 1.0f / s;
    e.x *= inv; e.y *= inv; e.z *= inv; e.w *= inv;
    p[threadIdx.x] = e;
}

// ---------------------------------------------------------------------------
// Launch (7 graph nodes)
// ---------------------------------------------------------------------------
extern "C" void kernel_launch(void* const* d_in, const int* in_sizes, int n_in,
                              void* d_out, int out_size)
{
    const float* x    = (const float*)d_in[0];
    const float* h0   = (const float*)d_in[1];
    const float* W_ih = (const float*)d_in[2];
    const float* b_ih = (const float*)d_in[3];
    const float* W_ho = (const float*)d_in[4];
    const float* b_ho = (const float*)d_in[5];
    float*       out  = (float*)d_out;

    float *pA, *pHlast;
    __nv_bfloat16 *pXh, *pXl, *pHh, *pHl, *pWih_h, *pWih_l, *pWoh, *pWol;
    cudaGetSymbolAddress((void**)&pA,     g_A);
    cudaGetSymbolAddress((void**)&pHlast, g_Hlast);
    cudaGetSymbolAddress((void**)&pXh,    g_Xh);
    cudaGetSymbolAddress((void**)&pXl,    g_Xl);
    cudaGetSymbolAddress((void**)&pHh,    g_Hh);
    cudaGetSymbolAddress((void**)&pHl,    g_Hl);
    cudaGetSymbolAddress((void**)&pWih_h, g_Wih_h);
    cudaGetSymbolAddress((void**)&pWih_l, g_Wih_l);
    cudaGetSymbolAddress((void**)&pWoh,   g_Who_h);
    cudaGetSymbolAddress((void**)&pWol,   g_Who_l);

    cudaFuncSetAttribute(gemm_mma_x3,
                         cudaFuncAttributeMaxDynamicSharedMemorySize, G_SMEM);
    cudaFuncSetAttribute(rnn_recur,
                         cudaFuncAttributeMaxDynamicSharedMemorySize, R2_SMEM);

    // #1: X split; #2: fused param splits (W_ih, W_ho, h0)
    split_mat<<<4096, 256>>>(x, (long)TB * INF, pXh, pXl);
    split_params<<<1024, 256>>>(W_ih, W_ho, h0);

    // #3: Phase 1 -- g_A = X @ Wx^T + b_ih
    {
        dim3 grid(HIDDEN / 128, TB / 128);   // (8, 1024)
        gemm_mma_x3<<<grid, 256, G_SMEM>>>(pXh, pXl, INF,
                                           pWih_h, pWih_l, WROW,
                                           b_ih, pA, HIDDEN, INF);
    }

    // #4: Phase 2 -- persistent recurrence (8 decoupled groups, BK=64)
    rnn_recur<<<NCTAS, 256, R2_SMEM>>>();

    // #5/#6: Phase 3 -- out = H @ W_ho^T + b_ho, then in-place softmax
    {
        dim3 grid(NCLS / 128, TB / 128);     // (4, 1024)
        gemm_mma_x3<<<grid, 256, G_SMEM>>>(pHh, pHl, HIDDEN,
                                           pWoh, pWol, HIDDEN,
                                           b_ho, out, NCLS, HIDDEN);
        softmax512<<<TB, 128>>>(out);
    }

    // #7: h_last
    cudaMemcpyAsync(out + (long)TB * NCLS, pHlast,
                    (size_t)BH * sizeof(float), cudaMemcpyDeviceToDevice);
}

// round 9
// speedup vs baseline: 1.4493x; 1.0243x over previous
#include <cuda_runtime.h>
#include <cuda_bf16.h>
#include <math.h>
#include <stdint.h>

// ---------------------------------------------------------------------------
// Problem constants
// ---------------------------------------------------------------------------
#define T_STEPS 512
#define BATCH   256
#define INF     1024
#define HIDDEN  1024
#define WROW    (INF + HIDDEN)
#define NCLS    512
#define BH      (BATCH * HIDDEN)      // 262144
#define TB      (T_STEPS * BATCH)     // 131072
#define NCTAS   128                   // persistent recurrence grid
#define NGRP    8                     // independent recurrence groups
#define GRP_CTAS 16                   // CTAs per group

// ---------------------------------------------------------------------------
// Device-global scratch (allocation-free rule)
// ---------------------------------------------------------------------------
__device__ float g_A[(size_t)T_STEPS * BH];           // x-projection + b_ih (fp32)
__device__ float g_Hlast[BH];                          // final hidden state (fp32)
__device__ __nv_bfloat16 g_Xh[(size_t)TB * INF];      // X split hi
__device__ __nv_bfloat16 g_Xl[(size_t)TB * INF];      // X split lo
__device__ __nv_bfloat16 g_Hh[(size_t)T_STEPS * BH];  // H split hi
__device__ __nv_bfloat16 g_Hl[(size_t)T_STEPS * BH];  // H split lo
__device__ __nv_bfloat16 g_Wih_h[HIDDEN * WROW];      // W_ih hi (row stride WROW)
__device__ __nv_bfloat16 g_Wih_l[HIDDEN * WROW];
__device__ __nv_bfloat16 g_Who_h[NCLS * HIDDEN];      // W_ho hi
__device__ __nv_bfloat16 g_Who_l[NCLS * HIDDEN];
__device__ __nv_bfloat16 g_h0h[BH];                   // h0 split hi
__device__ __nv_bfloat16 g_h0l[BH];
// Per-group barrier state, line-padded; gens monotonic across graph replays.
__device__ unsigned g_gcnt[NGRP * 32];
__device__ unsigned g_ggen[NGRP * 32];

// ---------------------------------------------------------------------------
// Portable PTX helpers (sm_80+ features only)
// ---------------------------------------------------------------------------
__device__ __forceinline__ uint32_t smem_to_u32(const void* p) {
    uint32_t a;
    asm("{ .reg .u64 t; cvta.to.shared.u64 t, %1; cvt.u32.u64 %0, t; }"
        : "=r"(a) : "l"(p));
    return a;
}

__device__ __forceinline__ void cp16(uint32_t dst, const void* src) {
    asm volatile("cp.async.cg.shared.global [%0], [%1], 16;"
                 :: "r"(dst), "l"(__cvta_generic_to_global(src)));
}
#define CP_COMMIT()  asm volatile("cp.async.commit_group;" ::: "memory")
#define CP_WAIT(n)   asm volatile("cp.async.wait_group %0;" :: "n"(n) : "memory")

#define LDSM4(r0, r1, r2, r3, addr) \
    asm volatile("ldmatrix.sync.aligned.m8n8.x4.shared.b16 {%0,%1,%2,%3}, [%4];" \
                 : "=r"(r0), "=r"(r1), "=r"(r2), "=r"(r3) : "r"(addr))

// D[16x8] += A[16x16] * B[16x8]^(col)  -- bf16 in, fp32 accum
__device__ __forceinline__ void mma_bf16(float* c, const uint32_t* a, const uint32_t* b) {
    asm volatile(
        "mma.sync.aligned.m16n8k16.row.col.f32.bf16.bf16.f32 "
        "{%0,%1,%2,%3}, {%4,%5,%6,%7}, {%8,%9}, {%0,%1,%2,%3};"
        : "+f"(c[0]), "+f"(c[1]), "+f"(c[2]), "+f"(c[3])
        : "r"(a[0]), "r"(a[1]), "r"(a[2]), "r"(a[3]), "r"(b[0]), "r"(b[1]));
}

// ---------------------------------------------------------------------------
// fp32 -> (hi, lo) bf16 split
// ---------------------------------------------------------------------------
__device__ __forceinline__ void split1(float v, __nv_bfloat16& h, __nv_bfloat16& l) {
    h = __float2bfloat16(v);
    l = __float2bfloat16(v - __bfloat162float(h));
}

__device__ __forceinline__ void split4_store(float4 v, __nv_bfloat16* hi, __nv_bfloat16* lo)
{
    __nv_bfloat16 h0, h1, h2, h3, l0, l1, l2, l3;
    split1(v.x, h0, l0); split1(v.y, h1, l1);
    split1(v.z, h2, l2); split1(v.w, h3, l3);
    __nv_bfloat162 t;
    t.x = h0; t.y = h1; *(__nv_bfloat162*)(hi)     = t;
    t.x = h2; t.y = h3; *(__nv_bfloat162*)(hi + 2) = t;
    t.x = l0; t.y = l1; *(__nv_bfloat162*)(lo)     = t;
    t.x = l2; t.y = l3; *(__nv_bfloat162*)(lo + 2) = t;
}

// X split (contiguous)
__global__ void split_mat(const float* __restrict__ src, long n,
                          __nv_bfloat16* __restrict__ hi, __nv_bfloat16* __restrict__ lo)
{
    for (long i = blockIdx.x * (long)blockDim.x + threadIdx.x; i < n / 4;
         i += (long)gridDim.x * blockDim.x) {
        long e = i * 4;
        split4_store(*(const float4*)(src + e), hi + e, lo + e);
    }
}

// Fused parameter split: W_ih + W_ho + h0 in one launch (all contiguous)
__global__ void split_params(const float* __restrict__ W_ih,
                             const float* __restrict__ W_ho,
                             const float* __restrict__ h0)
{
    const long n1 = (long)HIDDEN * WROW / 4;
    const long n2 = (long)NCLS * HIDDEN / 4;
    const long n3 = (long)BH / 4;
    for (long i = blockIdx.x * (long)blockDim.x + threadIdx.x; i < n1 + n2 + n3;
         i += (long)gridDim.x * blockDim.x) {
        const float* s; __nv_bfloat16 *hi, *lo; long e;
        if (i < n1)            { s = W_ih; hi = g_Wih_h; lo = g_Wih_l; e = i * 4; }
        else if (i < n1 + n2)  { s = W_ho; hi = g_Who_h; lo = g_Who_l; e = (i - n1) * 4; }
        else                   { s = h0;   hi = g_h0h;   lo = g_h0l;   e = (i - n1 - n2) * 4; }
        split4_store(*(const float4*)(s + e), hi + e, lo + e);
    }
}

// ---------------------------------------------------------------------------
// mma.sync bf16x3 GEMM (phases 1 & 3).
// CTA tile 128x128, BK=32, 8 warps (4M x 2N), 2-stage cp.async,
// single __syncthreads per chunk, ldmatrix.x4 for B (n-tile pairs).
// ---------------------------------------------------------------------------
#define ROWB   80
#define G_MAT  (128 * ROWB)
#define G_STG  (4 * G_MAT)
#define G_SMEM (2 * G_STG)           // 81920

__global__ void __launch_bounds__(256, 1)
gemm_mma_x3(const __nv_bfloat16* __restrict__ Ah, const __nv_bfloat16* __restrict__ Al, long lda,
            const __nv_bfloat16* __restrict__ Bh, const __nv_bfloat16* __restrict__ Bl, long ldb,
            const float* __restrict__ bias, float* __restrict__ C, long ldc, int K)
{
    extern __shared__ char smem[];
    const uint32_t sb = smem_to_u32(smem);
    const int tid = threadIdx.x, lane = tid & 31, wid = tid >> 5;
    const int wm = wid & 3, wn = wid >> 2;
    const long bm = (long)blockIdx.y * 128;
    const long bn = (long)blockIdx.x * 128;

    float c[2][8][4];
#pragma unroll
    for (int m = 0; m < 2; m++)
#pragma unroll
        for (int n = 0; n < 8; n++)
#pragma unroll
            for (int j = 0; j < 4; j++) c[m][n][j] = 0.0f;

    const uint32_t a_rb = (uint32_t)(lane & 15) * ROWB + (uint32_t)(lane >> 4) * 16;
    // x4-B layout: lanes 0-7 -> (n0,k0), 8-15 -> (n0,k1), 16-23 -> (n1,k0), 24-31 -> (n1,k1)
    const uint32_t b4_rb = (uint32_t)((lane & 7) + ((lane >> 4) << 3)) * ROWB
                           + (uint32_t)((lane >> 3) & 1) * 16;

    auto load_chunk = [&](int kc, int stage) {
        uint32_t base = sb + stage * G_STG;
#pragma unroll
        for (int it = 0; it < 2; it++) {
            int u = tid + it * 256;
            int row = u >> 2, seg = u & 3;
            uint32_t so = row * ROWB + seg * 16;
            long ga = (bm + row) * lda + kc + seg * 8;
            long gb = (bn + row) * ldb + kc + seg * 8;
            cp16(base + so,             Ah + ga);
            cp16(base + G_MAT + so,     Al + ga);
            cp16(base + 2 * G_MAT + so, Bh + gb);
            cp16(base + 3 * G_MAT + so, Bl + gb);
        }
    };

    const int nchunk = K >> 5;
    load_chunk(0, 0);
    CP_COMMIT();

    for (int ch = 0; ch < nchunk; ch++) {
        CP_WAIT(0);
        __syncthreads();          // data of ch visible; all warps done with ch-1
        if (ch + 1 < nchunk) {
            load_chunk((ch + 1) << 5, (ch + 1) & 1);
            CP_COMMIT();
        }

        const uint32_t base = sb + (ch & 1) * G_STG;
#pragma unroll
        for (int k16 = 0; k16 < 2; k16++) {
            const uint32_t kb = k16 * 32;
            uint32_t ah[2][4], al[2][4], bh[8][2], bl[8][2];
#pragma unroll
            for (int m = 0; m < 2; m++) {
                uint32_t ra = base + (uint32_t)(wm * 32 + m * 16) * ROWB + kb + a_rb;
                LDSM4(ah[m][0], ah[m][1], ah[m][2], ah[m][3], ra);
                LDSM4(al[m][0], al[m][1], al[m][2], al[m][3], ra + G_MAT);
            }
#pragma unroll
            for (int p = 0; p < 4; p++) {
                uint32_t rb = base + 2 * G_MAT + (uint32_t)(wn * 64 + p * 16) * ROWB + kb + b4_rb;
                LDSM4(bh[2*p][0], bh[2*p][1], bh[2*p+1][0], bh[2*p+1][1], rb);
                LDSM4(bl[2*p][0], bl[2*p][1], bl[2*p+1][0], bl[2*p+1][1], rb + G_MAT);
            }
#pragma unroll
            for (int m = 0; m < 2; m++)
#pragma unroll
                for (int n = 0; n < 8; n++) {
                    mma_bf16(c[m][n], ah[m], bh[n]);
                    mma_bf16(c[m][n], al[m], bh[n]);
                    mma_bf16(c[m][n], ah[m], bl[n]);
                }
        }
    }

#pragma unroll
    for (int m = 0; m < 2; m++) {
        long r0 = bm + wm * 32 + m * 16 + (lane >> 2);
        long r1 = r0 + 8;
#pragma unroll
        for (int n = 0; n < 8; n++) {
            long col = bn + wn * 64 + n * 8 + (lane & 3) * 2;
            float bx = bias[col], by = bias[col + 1];
            float2 v0 = { c[m][n][0] + bx, c[m][n][1] + by };
            float2 v1 = { c[m][n][2] + bx, c[m][n][3] + by };
            *(float2*)(C + r0 * ldc + col) = v0;
            *(float2*)(C + r1 * ldc + col) = v1;
        }
    }
}

// ---------------------------------------------------------------------------
// Per-group barrier (16 CTAs); groups fully decoupled closed systems.
// ---------------------------------------------------------------------------
__device__ __forceinline__ void group_bar(int g, unsigned& lgen)
{
    __syncthreads();
    if (threadIdx.x == 0) {
        __threadfence();
        if (atomicAdd(&g_gcnt[g * 32], 1u) == GRP_CTAS - 1) {
            atomicExch(&g_gcnt[g * 32], 0u);
            __threadfence();
            atomicAdd(&g_ggen[g * 32], 1u);
        } else {
            while (*(volatile unsigned*)&g_ggen[g * 32] == lgen) { __nanosleep(32); }
            __threadfence();
        }
        lgen++;
    }
    __syncthreads();
}

// ---------------------------------------------------------------------------
// Persistent recurrence:  h_t = tanh(g_A[t] + h_{t-1} @ W_h^T)
// 128 CTAs = 8 groups x 16; CTA tile 32(batch) x 64(hidden); warps 2M x 4N.
// W_h hi tile resident in smem.  BK=64, single sync per chunk, x4-B ldmatrix,
// fragment double-buffering across the 4 k16 iterations.
// ---------------------------------------------------------------------------
#define ROWB2     144                        // 128B data + 16 pad (streamed)
#define RB_ROWB   2064                       // 2048B data + 16 pad (resident)
#define RBH_SZ    (64 * RB_ROWB)             // 132096
#define RA2_SZ    (32 * ROWB2)               // 4608 per A matrix
#define RBL2_SZ   (64 * ROWB2)               // 9216
#define R2_STG    (2 * RA2_SZ + RBL2_SZ)     // 18432  (Ah | Al | Bl)
#define R2_SMEM   (RBH_SZ + 2 * R2_STG)      // 168960

__global__ void __launch_bounds__(256, 1)
rnn_recur()
{
    extern __shared__ char smem[];
    const uint32_t sb = smem_to_u32(smem);
    const int tid = threadIdx.x, lane = tid & 31, wid = tid >> 5;
    const int wm = wid & 1, wn = wid >> 1;       // 2 x 4 warp grid
    const int grp = blockIdx.x >> 4;             // group (0..7)
    const int bm  = grp * 32;                    // batch rows [bm, bm+32)
    const int bn  = (blockIdx.x & 15) * 64;      // hidden cols [bn, bn+64)

    const uint32_t a_rb  = (uint32_t)(lane & 15) * ROWB2 + (uint32_t)(lane >> 4) * 16;
    const uint32_t b4h_rb = (uint32_t)((lane & 7) + ((lane >> 4) << 3)) * RB_ROWB
                            + (uint32_t)((lane >> 3) & 1) * 16;
    const uint32_t b4l_rb = (uint32_t)((lane & 7) + ((lane >> 4) << 3)) * ROWB2
                            + (uint32_t)((lane >> 3) & 1) * 16;

    // ---- Resident W_h hi tile: 64 rows x 1024 bf16 (8192 x 16B units)
    for (int u = tid; u < 8192; u += 256) {
        int row = u >> 7, seg = u & 127;
        cp16(sb + row * RB_ROWB + seg * 16,
             g_Wih_h + (size_t)(bn + row) * WROW + INF + seg * 8);
    }
    CP_COMMIT();

    unsigned lgen = *(volatile unsigned*)&g_ggen[grp * 32];

    for (int t = 0; t < T_STEPS; t++) {
        const __nv_bfloat16* hh = (t == 0) ? g_h0h : (g_Hh + (size_t)(t - 1) * BH);
        const __nv_bfloat16* hl = (t == 0) ? g_h0l : (g_Hl + (size_t)(t - 1) * BH);
        const size_t ob = (size_t)t * BH;

        float c[2][4];
#pragma unroll
        for (int n = 0; n < 2; n++)
#pragma unroll
            for (int j = 0; j < 4; j++) c[n][j] = 0.0f;

        auto load_chunk = [&](int kc, int stage) {
            uint32_t base = sb + RBH_SZ + stage * R2_STG;
            // A hi / A lo: 32 rows x 8 segs = 256 units each
            {
                int row = tid >> 3, seg = tid & 7;
                uint32_t so = row * ROWB2 + seg * 16;
                size_t g = (size_t)(bm + row) * HIDDEN + kc + seg * 8;
                cp16(base + so,          hh + g);
                cp16(base + RA2_SZ + so, hl + g);
            }
            // B lo: 64 rows x 8 segs = 512 units (2/thread)
#pragma unroll
            for (int it = 0; it < 2; it++) {
                int u = tid + it * 256;
                int row = u >> 3, seg = u & 7;
                cp16(base + 2 * RA2_SZ + row * ROWB2 + seg * 16,
                     g_Wih_l + (size_t)(bn + row) * WROW + INF + kc + seg * 8);
            }
        };

        load_chunk(0, 0);
        CP_COMMIT();

        for (int ch = 0; ch < HIDDEN / 64; ch++) {     // 16 chunks
            CP_WAIT(0);
            __syncthreads();       // chunk ch visible; all warps done with ch-1
            if (ch + 1 < HIDDEN / 64) {
                load_chunk((ch + 1) << 6, (ch + 1) & 1);
                CP_COMMIT();
            }

            const uint32_t base  = sb + RBH_SZ + (ch & 1) * R2_STG;
            const uint32_t abase = base + (uint32_t)(wm * 16) * ROWB2 + a_rb;
            const uint32_t bhb   = sb + (uint32_t)(wn * 16) * RB_ROWB
                                   + (uint32_t)(ch << 7) + b4h_rb;
            const uint32_t blb   = base + 2 * RA2_SZ + (uint32_t)(wn * 16) * ROWB2 + b4l_rb;

            // Fragment-pipelined k16 loop (4 iters, double-buffered)
            uint32_t ah[2][4], al[2][4], bh[2][2][2], bl[2][2][2];

#define R_LD(k16, buf) do { \
        uint32_t _ra = abase + (uint32_t)((k16) * 32); \
        LDSM4(ah[buf][0], ah[buf][1], ah[buf][2], ah[buf][3], _ra); \
        LDSM4(al[buf][0], al[buf][1], al[buf][2], al[buf][3], _ra + RA2_SZ); \
        LDSM4(bh[buf][0][0], bh[buf][0][1], bh[buf][1][0], bh[buf][1][1], \
              bhb + (uint32_t)((k16) * 32)); \
        LDSM4(bl[buf][0][0], bl[buf][0][1], bl[buf][1][0], bl[buf][1][1], \
              blb + (uint32_t)((k16) * 32)); \
    } while (0)

            R_LD(0, 0);
#pragma unroll
            for (int k16 = 0; k16 < 4; k16++) {
                if (k16 < 3) R_LD(k16 + 1, (k16 + 1) & 1);
                const int b = k16 & 1;
#pragma unroll
                for (int n = 0; n < 2; n++) {
                    mma_bf16(c[n], ah[b], bh[b][n]);
                    mma_bf16(c[n], al[b], bh[b][n]);
                    mma_bf16(c[n], ah[b], bl[b][n]);
                }
            }
#undef R_LD
        }

        // Epilogue: tanh(acc + pre), split to bf16 hi/lo
        {
            const int r0 = bm + wm * 16 + (lane >> 2);
            const int r1 = r0 + 8;
#pragma unroll
            for (int n = 0; n < 2; n++) {
                const int col = bn + wn * 16 + n * 8 + (lane & 3) * 2;
                float2 p0 = *(const float2*)(g_A + ob + (size_t)r0 * HIDDEN + col);
                float2 p1 = *(const float2*)(g_A + ob + (size_t)r1 * HIDDEN + col);
                float h00 = tanhf(c[n][0] + p0.x);
                float h01 = tanhf(c[n][1] + p0.y);
                float h10 = tanhf(c[n][2] + p1.x);
                float h11 = tanhf(c[n][3] + p1.y);

                __nv_bfloat16 hb, lb;
                __nv_bfloat162 th, tl;
                split1(h00, hb, lb); th.x = hb; tl.x = lb;
                split1(h01, hb, lb); th.y = hb; tl.y = lb;
                *(__nv_bfloat162*)(g_Hh + ob + (size_t)r0 * HIDDEN + col) = th;
                *(__nv_bfloat162*)(g_Hl + ob + (size_t)r0 * HIDDEN + col) = tl;
                split1(h10, hb, lb); th.x = hb; tl.x = lb;
                split1(h11, hb, lb); th.y = hb; tl.y = lb;
                *(__nv_bfloat162*)(g_Hh + ob + (size_t)r1 * HIDDEN + col) = th;
                *(__nv_bfloat162*)(g_Hl + ob + (size_t)r1 * HIDDEN + col) = tl;

                if (t == T_STEPS - 1) {
                    float2 f0 = { h00, h01 }, f1 = { h10, h11 };
                    *(float2*)(g_Hlast + (size_t)r0 * HIDDEN + col) = f0;
                    *(float2*)(g_Hlast + (size_t)r1 * HIDDEN + col) = f1;
                }
            }
        }

        group_bar(grp, lgen);   // 16-CTA rendezvous; groups fully decoupled
    }
}

// ---------------------------------------------------------------------------
// In-place softmax over rows of 512 floats
// ---------------------------------------------------------------------------
__global__ void softmax512(float* __restrict__ O)
{
    __shared__ float red[4];
    long row = blockIdx.x;
    float4* p = (float4*)(O + row * (long)NCLS);
    float4 v = p[threadIdx.x];

    float m = fmaxf(fmaxf(v.x, v.y), fmaxf(v.z, v.w));
#pragma unroll
    for (int o = 16; o > 0; o >>= 1)
        m = fmaxf(m, __shfl_xor_sync(0xffffffffu, m, o));
    int warp = threadIdx.x >> 5;
    if ((threadIdx.x & 31) == 0) red[warp] = m;
    __syncthreads();
    m = fmaxf(fmaxf(red[0], red[1]), fmaxf(red[2], red[3]));

    float4 e;
    e.x = __expf(v.x - m);
    e.y = __expf(v.y - m);
    e.z = __expf(v.z - m);
    e.w = __expf(v.w - m);
    float s = e.x + e.y + e.z + e.w;
#pragma unroll
    for (int o = 16; o > 0; o >>= 1)
        s += __shfl_xor_sync(0xffffffffu, s, o);
    __syncthreads();
    if ((threadIdx.x & 31) == 0) red[warp] = s;
    __syncthreads();
    s = red[0] + red[1] + red[2] + red[3];

    float inv = 1.0f / s;
    e.x *= inv; e.y *= inv; e.z *= inv; e.w *= inv;
    p[threadIdx.x] = e;
}

// ---------------------------------------------------------------------------
// Launch (7 graph nodes)
// ---------------------------------------------------------------------------
extern "C" void kernel_launch(void* const* d_in, const int* in_sizes, int n_in,
                              void* d_out, int out_size)
{
    const float* x    = (const float*)d_in[0];
    const float* h0   = (const float*)d_in[1];
    const float* W_ih = (const float*)d_in[2];
    const float* b_ih = (const float*)d_in[3];
    const float* W_ho = (const float*)d_in[4];
    const float* b_ho = (const float*)d_in[5];
    float*       out  = (float*)d_out;

    float *pA, *pHlast;
    __nv_bfloat16 *pXh, *pXl, *pHh, *pHl, *pWih_h, *pWih_l, *pWoh, *pWol;
    cudaGetSymbolAddress((void**)&pA,     g_A);
    cudaGetSymbolAddress((void**)&pHlast, g_Hlast);
    cudaGetSymbolAddress((void**)&pXh,    g_Xh);
    cudaGetSymbolAddress((void**)&pXl,    g_Xl);
    cudaGetSymbolAddress((void**)&pHh,    g_Hh);
    cudaGetSymbolAddress((void**)&pHl,    g_Hl);
    cudaGetSymbolAddress((void**)&pWih_h, g_Wih_h);
    cudaGetSymbolAddress((void**)&pWih_l, g_Wih_l);
    cudaGetSymbolAddress((void**)&pWoh,   g_Who_h);
    cudaGetSymbolAddress((void**)&pWol,   g_Who_l);

    cudaFuncSetAttribute(gemm_mma_x3,
                         cudaFuncAttributeMaxDynamicSharedMemorySize, G_SMEM);
    cudaFuncSetAttribute(rnn_recur,
                         cudaFuncAttributeMaxDynamicSharedMemorySize, R2_SMEM);

    // #1: X split; #2: fused param splits (W_ih, W_ho, h0)
    split_mat<<<4096, 256>>>(x, (long)TB * INF, pXh, pXl);
    split_params<<<1024, 256>>>(W_ih, W_ho, h0);

    // #3: Phase 1 -- g_A = X @ Wx^T + b_ih
    {
        dim3 grid(HIDDEN / 128, TB / 128);   // (8, 1024)
        gemm_mma_x3<<<grid, 256, G_SMEM>>>(pXh, pXl, INF,
                                           pWih_h, pWih_l, WROW,
                                           b_ih, pA, HIDDEN, INF);
    }

    // #4: Phase 2 -- persistent recurrence (8 decoupled groups, BK=64)
    rnn_recur<<<NCTAS, 256, R2_SMEM>>>();

    // #5/#6: Phase 3 -- out = H @ W_ho^T + b_ho, then in-place softmax
    {
        dim3 grid(NCLS / 128, TB / 128);     // (4, 1024)
        gemm_mma_x3<<<grid, 256, G_SMEM>>>(pHh, pHl, HIDDEN,
                                           pWoh, pWol, HIDDEN,
                                           b_ho, out, NCLS, HIDDEN);
        softmax512<<<TB, 128>>>(out);
    }

    // #7: h_last
    cudaMemcpyAsync(out + (long)TB * NCLS, pHlast,
                    (size_t)BH * sizeof(float), cudaMemcpyDeviceToDevice);
}

// round 10
// speedup vs baseline: 1.6047x; 1.1072x over previous
#include <cuda_runtime.h>
#include <cuda_fp16.h>
#include <math.h>
#include <stdint.h>

// ---------------------------------------------------------------------------
// Problem constants
// ---------------------------------------------------------------------------
#define T_STEPS 512
#define BATCH   256
#define INF     1024
#define HIDDEN  1024
#define WROW    (INF + HIDDEN)
#define NCLS    512
#define BH      (BATCH * HIDDEN)      // 262144
#define TB      (T_STEPS * BATCH)     // 131072
#define NCTAS   128                   // persistent recurrence grid
#define NGRP    8                     // independent recurrence groups
#define GRP_CTAS 16                   // CTAs per group

// ---------------------------------------------------------------------------
// Device-global scratch (allocation-free rule)
// ---------------------------------------------------------------------------
__device__ float g_A[(size_t)T_STEPS * BH];       // x-projection + b_ih (fp32)
__device__ float g_Hlast[BH];                      // final hidden state (fp32)
__device__ __half g_Xh[(size_t)TB * INF];         // X hi (fp16; lo not needed, B exact in x2)
__device__ __half g_Hh[(size_t)T_STEPS * BH];     // H split hi (fp16)
__device__ __half g_Hl[(size_t)T_STEPS * BH];     // H split lo (fp16, recurrence x3)
__device__ __half g_Wih_h[HIDDEN * WROW];         // W_ih hi (row stride WROW)
__device__ __half g_Wih_l[HIDDEN * WROW];
__device__ __half g_Who_h[NCLS * HIDDEN];         // W_ho hi
__device__ __half g_Who_l[NCLS * HIDDEN];
__device__ __half g_h0h[BH];                      // h0 split hi
__device__ __half g_h0l[BH];
// Per-group barrier state, line-padded; gens monotonic across graph replays.
__device__ unsigned g_gcnt[NGRP * 32];
__device__ unsigned g_ggen[NGRP * 32];

// ---------------------------------------------------------------------------
// Portable PTX helpers (sm_80+ features only)
// ---------------------------------------------------------------------------
__device__ __forceinline__ uint32_t smem_to_u32(const void* p) {
    uint32_t a;
    asm("{ .reg .u64 t; cvta.to.shared.u64 t, %1; cvt.u32.u64 %0, t; }"
        : "=r"(a) : "l"(p));
    return a;
}

__device__ __forceinline__ void cp16(uint32_t dst, const void* src) {
    asm volatile("cp.async.cg.shared.global [%0], [%1], 16;"
                 :: "r"(dst), "l"(__cvta_generic_to_global(src)));
}
#define CP_COMMIT()  asm volatile("cp.async.commit_group;" ::: "memory")
#define CP_WAIT(n)   asm volatile("cp.async.wait_group %0;" :: "n"(n) : "memory")

#define LDSM4(r0, r1, r2, r3, addr) \
    asm volatile("ldmatrix.sync.aligned.m8n8.x4.shared.b16 {%0,%1,%2,%3}, [%4];" \
                 : "=r"(r0), "=r"(r1), "=r"(r2), "=r"(r3) : "r"(addr))

// D[16x8] += A[16x16] * B[16x8]^(col)  -- fp16 in, fp32 accum
__device__ __forceinline__ void mma_f16(float* c, const uint32_t* a, const uint32_t* b) {
    asm volatile(
        "mma.sync.aligned.m16n8k16.row.col.f32.f16.f16.f32 "
        "{%0,%1,%2,%3}, {%4,%5,%6,%7}, {%8,%9}, {%0,%1,%2,%3};"
        : "+f"(c[0]), "+f"(c[1]), "+f"(c[2]), "+f"(c[3])
        : "r"(a[0]), "r"(a[1]), "r"(a[2]), "r"(a[3]), "r"(b[0]), "r"(b[1]));
}

// ---------------------------------------------------------------------------
// fp32 -> (hi, lo) fp16 split
// ---------------------------------------------------------------------------
__device__ __forceinline__ void split1h(float v, __half& h, __half& l) {
    h = __float2half_rn(v);
    l = __float2half_rn(v - __half2float(h));
}

__device__ __forceinline__ void split4_store(float4 v, __half* hi, __half* lo)
{
    __half h0, h1, h2, h3, l0, l1, l2, l3;
    split1h(v.x, h0, l0); split1h(v.y, h1, l1);
    split1h(v.z, h2, l2); split1h(v.w, h3, l3);
    __half2 t;
    t.x = h0; t.y = h1; *(__half2*)(hi)     = t;
    t.x = h2; t.y = h3; *(__half2*)(hi + 2) = t;
    t.x = l0; t.y = l1; *(__half2*)(lo)     = t;
    t.x = l2; t.y = l3; *(__half2*)(lo + 2) = t;
}

// X: hi-only split (phase-1 x2 keeps B exact, drops A residual)
__global__ void split_hi(const float* __restrict__ src, long n, __half* __restrict__ hi)
{
    for (long i = blockIdx.x * (long)blockDim.x + threadIdx.x; i < n / 4;
         i += (long)gridDim.x * blockDim.x) {
        long e = i * 4;
        float4 v = *(const float4*)(src + e);
        __half2 a, b;
        a.x = __float2half_rn(v.x); a.y = __float2half_rn(v.y);
        b.x = __float2half_rn(v.z); b.y = __float2half_rn(v.w);
        *(__half2*)(hi + e)     = a;
        *(__half2*)(hi + e + 2) = b;
    }
}

// Fused parameter split: W_ih + W_ho + h0 in one launch (all contiguous)
__global__ void split_params(const float* __restrict__ W_ih,
                             const float* __restrict__ W_ho,
                             const float* __restrict__ h0)
{
    const long n1 = (long)HIDDEN * WROW / 4;
    const long n2 = (long)NCLS * HIDDEN / 4;
    const long n3 = (long)BH / 4;
    for (long i = blockIdx.x * (long)blockDim.x + threadIdx.x; i < n1 + n2 + n3;
         i += (long)gridDim.x * blockDim.x) {
        const float* s; __half *hi, *lo; long e;
        if (i < n1)            { s = W_ih; hi = g_Wih_h; lo = g_Wih_l; e = i * 4; }
        else if (i < n1 + n2)  { s = W_ho; hi = g_Who_h; lo = g_Who_l; e = (i - n1) * 4; }
        else                   { s = h0;   hi = g_h0h;   lo = g_h0l;   e = (i - n1 - n2) * 4; }
        split4_store(*(const float4*)(s + e), hi + e, lo + e);
    }
}

// ---------------------------------------------------------------------------
// mma.sync fp16 x2 GEMM (phases 1 & 3):
//   C[m,n] = sum_k A_hi[m,k] * (Bh + Bl)[n,k] + bias[n]
// (B exact hi+lo; error = A_lo*B ~ 2^-11.)  CTA tile 128x128, BK=32,
// 8 warps (4M x 2N), 2-stage cp.async, 1 sync/chunk, x4-B ldmatrix.
// ---------------------------------------------------------------------------
#define ROWB   80
#define G_MAT  (128 * ROWB)          // 10240
#define G_STG  (3 * G_MAT)           // A | Bh | Bl = 30720
#define G_SMEM (2 * G_STG)           // 61440

__global__ void __launch_bounds__(256, 1)
gemm_mma_x2(const __half* __restrict__ A, long lda,
            const __half* __restrict__ Bh, const __half* __restrict__ Bl, long ldb,
            const float* __restrict__ bias, float* __restrict__ C, long ldc, int K)
{
    extern __shared__ char smem[];
    const uint32_t sb = smem_to_u32(smem);
    const int tid = threadIdx.x, lane = tid & 31, wid = tid >> 5;
    const int wm = wid & 3, wn = wid >> 2;
    const long bm = (long)blockIdx.y * 128;
    const long bn = (long)blockIdx.x * 128;

    float c[2][8][4];
#pragma unroll
    for (int m = 0; m < 2; m++)
#pragma unroll
        for (int n = 0; n < 8; n++)
#pragma unroll
            for (int j = 0; j < 4; j++) c[m][n][j] = 0.0f;

    const uint32_t a_rb = (uint32_t)(lane & 15) * ROWB + (uint32_t)(lane >> 4) * 16;
    // x4-B layout: lanes 0-7 -> (n0,k0), 8-15 -> (n0,k1), 16-23 -> (n1,k0), 24-31 -> (n1,k1)
    const uint32_t b4_rb = (uint32_t)((lane & 7) + ((lane >> 4) << 3)) * ROWB
                           + (uint32_t)((lane >> 3) & 1) * 16;

    auto load_chunk = [&](int kc, int stage) {
        uint32_t base = sb + stage * G_STG;
#pragma unroll
        for (int it = 0; it < 2; it++) {
            int u = tid + it * 256;
            int row = u >> 2, seg = u & 3;
            uint32_t so = row * ROWB + seg * 16;
            long ga = (bm + row) * lda + kc + seg * 8;
            long gb = (bn + row) * ldb + kc + seg * 8;
            cp16(base + so,             A  + ga);
            cp16(base + G_MAT + so,     Bh + gb);
            cp16(base + 2 * G_MAT + so, Bl + gb);
        }
    };

    const int nchunk = K >> 5;
    load_chunk(0, 0);
    CP_COMMIT();

    for (int ch = 0; ch < nchunk; ch++) {
        CP_WAIT(0);
        __syncthreads();          // data of ch visible; all warps done with ch-1
        if (ch + 1 < nchunk) {
            load_chunk((ch + 1) << 5, (ch + 1) & 1);
            CP_COMMIT();
        }

        const uint32_t base = sb + (ch & 1) * G_STG;
#pragma unroll
        for (int k16 = 0; k16 < 2; k16++) {
            const uint32_t kb = k16 * 32;
            uint32_t ah[2][4], bh[8][2], bl[8][2];
#pragma unroll
            for (int m = 0; m < 2; m++) {
                uint32_t ra = base + (uint32_t)(wm * 32 + m * 16) * ROWB + kb + a_rb;
                LDSM4(ah[m][0], ah[m][1], ah[m][2], ah[m][3], ra);
            }
#pragma unroll
            for (int p = 0; p < 4; p++) {
                uint32_t rb = base + G_MAT + (uint32_t)(wn * 64 + p * 16) * ROWB + kb + b4_rb;
                LDSM4(bh[2*p][0], bh[2*p][1], bh[2*p+1][0], bh[2*p+1][1], rb);
                LDSM4(bl[2*p][0], bl[2*p][1], bl[2*p+1][0], bl[2*p+1][1], rb + G_MAT);
            }
#pragma unroll
            for (int m = 0; m < 2; m++)
#pragma unroll
                for (int n = 0; n < 8; n++) {
                    mma_f16(c[m][n], ah[m], bh[n]);
                    mma_f16(c[m][n], ah[m], bl[n]);
                }
        }
    }

#pragma unroll
    for (int m = 0; m < 2; m++) {
        long r0 = bm + wm * 32 + m * 16 + (lane >> 2);
        long r1 = r0 + 8;
#pragma unroll
        for (int n = 0; n < 8; n++) {
            long col = bn + wn * 64 + n * 8 + (lane & 3) * 2;
            float bx = bias[col], by = bias[col + 1];
            float2 v0 = { c[m][n][0] + bx, c[m][n][1] + by };
            float2 v1 = { c[m][n][2] + bx, c[m][n][3] + by };
            *(float2*)(C + r0 * ldc + col) = v0;
            *(float2*)(C + r1 * ldc + col) = v1;
        }
    }
}

// ---------------------------------------------------------------------------
// Per-group barrier (16 CTAs); groups fully decoupled closed systems.
// ---------------------------------------------------------------------------
__device__ __forceinline__ void group_bar(int g, unsigned& lgen)
{
    __syncthreads();
    if (threadIdx.x == 0) {
        __threadfence();
        if (atomicAdd(&g_gcnt[g * 32], 1u) == GRP_CTAS - 1) {
            atomicExch(&g_gcnt[g * 32], 0u);
            __threadfence();
            atomicAdd(&g_ggen[g * 32], 1u);
        } else {
            while (*(volatile unsigned*)&g_ggen[g * 32] == lgen) { __nanosleep(32); }
            __threadfence();
        }
        lgen++;
    }
    __syncthreads();
}

// ---------------------------------------------------------------------------
// Persistent recurrence (fp16 x3 -- per-step error ~2^-22, compounding-safe):
//   h_t = tanh(g_A[t] + h_{t-1} @ W_h^T)
// 128 CTAs = 8 groups x 16; CTA tile 32(batch) x 64(hidden); warps 2M x 4N.
// W_h hi resident in smem; streams A hi/lo + B lo per BK=64 chunk.
// ---------------------------------------------------------------------------
#define ROWB2     144                        // 128B data + 16 pad (streamed)
#define RB_ROWB   2064                       // 2048B data + 16 pad (resident)
#define RBH_SZ    (64 * RB_ROWB)             // 132096
#define RA2_SZ    (32 * ROWB2)               // 4608 per A matrix
#define RBL2_SZ   (64 * ROWB2)               // 9216
#define R2_STG    (2 * RA2_SZ + RBL2_SZ)     // 18432  (Ah | Al | Bl)
#define R2_SMEM   (RBH_SZ + 2 * R2_STG)      // 168960

__global__ void __launch_bounds__(256, 1)
rnn_recur()
{
    extern __shared__ char smem[];
    const uint32_t sb = smem_to_u32(smem);
    const int tid = threadIdx.x, lane = tid & 31, wid = tid >> 5;
    const int wm = wid & 1, wn = wid >> 1;       // 2 x 4 warp grid
    const int grp = blockIdx.x >> 4;             // group (0..7)
    const int bm  = grp * 32;                    // batch rows [bm, bm+32)
    const int bn  = (blockIdx.x & 15) * 64;      // hidden cols [bn, bn+64)

    const uint32_t a_rb  = (uint32_t)(lane & 15) * ROWB2 + (uint32_t)(lane >> 4) * 16;
    const uint32_t b4h_rb = (uint32_t)((lane & 7) + ((lane >> 4) << 3)) * RB_ROWB
                            + (uint32_t)((lane >> 3) & 1) * 16;
    const uint32_t b4l_rb = (uint32_t)((lane & 7) + ((lane >> 4) << 3)) * ROWB2
                            + (uint32_t)((lane >> 3) & 1) * 16;

    // ---- Resident W_h hi tile: 64 rows x 1024 fp16 (8192 x 16B units)
    for (int u = tid; u < 8192; u += 256) {
        int row = u >> 7, seg = u & 127;
        cp16(sb + row * RB_ROWB + seg * 16,
             g_Wih_h + (size_t)(bn + row) * WROW + INF + seg * 8);
    }
    CP_COMMIT();

    unsigned lgen = *(volatile unsigned*)&g_ggen[grp * 32];

    for (int t = 0; t < T_STEPS; t++) {
        const __half* hh = (t == 0) ? g_h0h : (g_Hh + (size_t)(t - 1) * BH);
        const __half* hl = (t == 0) ? g_h0l : (g_Hl + (size_t)(t - 1) * BH);
        const size_t ob = (size_t)t * BH;

        float c[2][4];
#pragma unroll
        for (int n = 0; n < 2; n++)
#pragma unroll
            for (int j = 0; j < 4; j++) c[n][j] = 0.0f;

        auto load_chunk = [&](int kc, int stage) {
            uint32_t base = sb + RBH_SZ + stage * R2_STG;
            // A hi / A lo: 32 rows x 8 segs = 256 units each
            {
                int row = tid >> 3, seg = tid & 7;
                uint32_t so = row * ROWB2 + seg * 16;
                size_t g = (size_t)(bm + row) * HIDDEN + kc + seg * 8;
                cp16(base + so,          hh + g);
                cp16(base + RA2_SZ + so, hl + g);
            }
            // B lo: 64 rows x 8 segs = 512 units (2/thread)
#pragma unroll
            for (int it = 0; it < 2; it++) {
                int u = tid + it * 256;
                int row = u >> 3, seg = u & 7;
                cp16(base + 2 * RA2_SZ + row * ROWB2 + seg * 16,
                     g_Wih_l + (size_t)(bn + row) * WROW + INF + kc + seg * 8);
            }
        };

        load_chunk(0, 0);
        CP_COMMIT();

        for (int ch = 0; ch < HIDDEN / 64; ch++) {     // 16 chunks
            CP_WAIT(0);
            __syncthreads();       // chunk ch visible; all warps done with ch-1
            if (ch + 1 < HIDDEN / 64) {
                load_chunk((ch + 1) << 6, (ch + 1) & 1);
                CP_COMMIT();
            }

            const uint32_t base  = sb + RBH_SZ + (ch & 1) * R2_STG;
            const uint32_t abase = base + (uint32_t)(wm * 16) * ROWB2 + a_rb;
            const uint32_t bhb   = sb + (uint32_t)(wn * 16) * RB_ROWB
                                   + (uint32_t)(ch << 7) + b4h_rb;
            const uint32_t blb   = base + 2 * RA2_SZ + (uint32_t)(wn * 16) * ROWB2 + b4l_rb;

            // Fragment-pipelined k16 loop (4 iters, double-buffered)
            uint32_t ah[2][4], al[2][4], bh[2][2][2], bl[2][2][2];

#define R_LD(k16, buf) do { \
        uint32_t _ra = abase + (uint32_t)((k16) * 32); \
        LDSM4(ah[buf][0], ah[buf][1], ah[buf][2], ah[buf][3], _ra); \
        LDSM4(al[buf][0], al[buf][1], al[buf][2], al[buf][3], _ra + RA2_SZ); \
        LDSM4(bh[buf][0][0], bh[buf][0][1], bh[buf][1][0], bh[buf][1][1], \
              bhb + (uint32_t)((k16) * 32)); \
        LDSM4(bl[buf][0][0], bl[buf][0][1], bl[buf][1][0], bl[buf][1][1], \
              blb + (uint32_t)((k16) * 32)); \
    } while (0)

            R_LD(0, 0);
#pragma unroll
            for (int k16 = 0; k16 < 4; k16++) {
                if (k16 < 3) R_LD(k16 + 1, (k16 + 1) & 1);
                const int b = k16 & 1;
#pragma unroll
                for (int n = 0; n < 2; n++) {
                    mma_f16(c[n], ah[b], bh[b][n]);
                    mma_f16(c[n], al[b], bh[b][n]);
                    mma_f16(c[n], ah[b], bl[b][n]);
                }
            }
#undef R_LD
        }

        // Epilogue: tanh(acc + pre), split to fp16 hi/lo
        {
            const int r0 = bm + wm * 16 + (lane >> 2);
            const int r1 = r0 + 8;
#pragma unroll
            for (int n = 0; n < 2; n++) {
                const int col = bn + wn * 16 + n * 8 + (lane & 3) * 2;
                float2 p0 = *(const float2*)(g_A + ob + (size_t)r0 * HIDDEN + col);
                float2 p1 = *(const float2*)(g_A + ob + (size_t)r1 * HIDDEN + col);
                float h00 = tanhf(c[n][0] + p0.x);
                float h01 = tanhf(c[n][1] + p0.y);
                float h10 = tanhf(c[n][2] + p1.x);
                float h11 = tanhf(c[n][3] + p1.y);

                __half hb, lb;
                __half2 th, tl;
                split1h(h00, hb, lb); th.x = hb; tl.x = lb;
                split1h(h01, hb, lb); th.y = hb; tl.y = lb;
                *(__half2*)(g_Hh + ob + (size_t)r0 * HIDDEN + col) = th;
                *(__half2*)(g_Hl + ob + (size_t)r0 * HIDDEN + col) = tl;
                split1h(h10, hb, lb); th.x = hb; tl.x = lb;
                split1h(h11, hb, lb); th.y = hb; tl.y = lb;
                *(__half2*)(g_Hh + ob + (size_t)r1 * HIDDEN + col) = th;
                *(__half2*)(g_Hl + ob + (size_t)r1 * HIDDEN + col) = tl;

                if (t == T_STEPS - 1) {
                    float2 f0 = { h00, h01 }, f1 = { h10, h11 };
                    *(float2*)(g_Hlast + (size_t)r0 * HIDDEN + col) = f0;
                    *(float2*)(g_Hlast + (size_t)r1 * HIDDEN + col) = f1;
                }
            }
        }

        group_bar(grp, lgen);   // 16-CTA rendezvous; groups fully decoupled
    }
}

// ---------------------------------------------------------------------------
// In-place softmax over rows of 512 floats
// ---------------------------------------------------------------------------
__global__ void softmax512(float* __restrict__ O)
{
    __shared__ float red[4];
    long row = blockIdx.x;
    float4* p = (float4*)(O + row * (long)NCLS);
    float4 v = p[threadIdx.x];

    float m = fmaxf(fmaxf(v.x, v.y), fmaxf(v.z, v.w));
#pragma unroll
    for (int o = 16; o > 0; o >>= 1)
        m = fmaxf(m, __shfl_xor_sync(0xffffffffu, m, o));
    int warp = threadIdx.x >> 5;
    if ((threadIdx.x & 31) == 0) red[warp] = m;
    __syncthreads();
    m = fmaxf(fmaxf(red[0], red[1]), fmaxf(red[2], red[3]));

    float4 e;
    e.x = __expf(v.x - m);
    e.y = __expf(v.y - m);
    e.z = __expf(v.z - m);
    e.w = __expf(v.w - m);
    float s = e.x + e.y + e.z + e.w;
#pragma unroll
    for (int o = 16; o > 0; o >>= 1)
        s += __shfl_xor_sync(0xffffffffu, s, o);
    __syncthreads();
    if ((threadIdx.x & 31) == 0) red[warp] = s;
    __syncthreads();
    s = red[0] + red[1] + red[2] + red[3];

    float inv = 1.0f / s;
    e.x *= inv; e.y *= inv; e.z *= inv; e.w *= inv;
    p[threadIdx.x] = e;
}

// ---------------------------------------------------------------------------
// Launch (7 graph nodes)
// ---------------------------------------------------------------------------
extern "C" void kernel_launch(void* const* d_in, const int* in_sizes, int n_in,
                              void* d_out, int out_size)
{
    const float* x    = (const float*)d_in[0];
    const float* h0   = (const float*)d_in[1];
    const float* W_ih = (const float*)d_in[2];
    const float* b_ih = (const float*)d_in[3];
    const float* W_ho = (const float*)d_in[4];
    const float* b_ho = (const float*)d_in[5];
    float*       out  = (float*)d_out;

    float *pA, *pHlast;
    __half *pXh, *pHh, *pHl, *pWih_h, *pWih_l, *pWoh, *pWol;
    cudaGetSymbolAddress((void**)&pA,     g_A);
    cudaGetSymbolAddress((void**)&pHlast, g_Hlast);
    cudaGetSymbolAddress((void**)&pXh,    g_Xh);
    cudaGetSymbolAddress((void**)&pHh,    g_Hh);
    cudaGetSymbolAddress((void**)&pHl,    g_Hl);
    cudaGetSymbolAddress((void**)&pWih_h, g_Wih_h);
    cudaGetSymbolAddress((void**)&pWih_l, g_Wih_l);
    cudaGetSymbolAddress((void**)&pWoh,   g_Who_h);
    cudaGetSymbolAddress((void**)&pWol,   g_Who_l);

    cudaFuncSetAttribute(gemm_mma_x2,
                         cudaFuncAttributeMaxDynamicSharedMemorySize, G_SMEM);
    cudaFuncSetAttribute(rnn_recur,
                         cudaFuncAttributeMaxDynamicSharedMemorySize, R2_SMEM);

    // #1: X hi-split; #2: fused param splits (W_ih, W_ho, h0; fp16 hi/lo)
    split_hi<<<4096, 256>>>(x, (long)TB * INF, pXh);
    split_params<<<1024, 256>>>(W_ih, W_ho, h0);

    // #3: Phase 1 -- g_A = Xh @ (Wx_h + Wx_l)^T + b_ih   (fp16 x2)
    {
        dim3 grid(HIDDEN / 128, TB / 128);   // (8, 1024)
        gemm_mma_x2<<<grid, 256, G_SMEM>>>(pXh, INF,
                                           pWih_h, pWih_l, WROW,
                                           b_ih, pA, HIDDEN, INF);
    }

    // #4: Phase 2 -- persistent recurrence (fp16 x3, 8 decoupled groups)
    rnn_recur<<<NCTAS, 256, R2_SMEM>>>();

    // #5/#6: Phase 3 -- out = Hh @ (Who_h + Who_l)^T + b_ho (fp16 x2), softmax
    {
        dim3 grid(NCLS / 128, TB / 128);     // (4, 1024)
        gemm_mma_x2<<<grid, 256, G_SMEM>>>(pHh, HIDDEN,
                                           pWoh, pWol, HIDDEN,
                                           b_ho, out, NCLS, HIDDEN);
        softmax512<<<TB, 128>>>(out);
    }

    // #7: h_last
    cudaMemcpyAsync(out + (long)TB * NCLS, pHlast,
                    (size_t)BH * sizeof(float), cudaMemcpyDeviceToDevice);
}

// round 11
// speedup vs baseline: 1.7906x; 1.1159x over previous
#include <cuda_runtime.h>
#include <cuda_fp16.h>
#include <math.h>
#include <stdint.h>

// ---------------------------------------------------------------------------
// Problem constants
// ---------------------------------------------------------------------------
#define T_STEPS 512
#define BATCH   256
#define INF     1024
#define HIDDEN  1024
#define WROW    (INF + HIDDEN)
#define NCLS    512
#define BH      (BATCH * HIDDEN)      // 262144
#define TB      (T_STEPS * BATCH)     // 131072
#define NCTAS   128                   // persistent recurrence grid
#define NGRP    8                     // independent recurrence groups
#define GRP_CTAS 16                   // CTAs per group

// ---------------------------------------------------------------------------
// Device-global scratch (allocation-free rule)
// ---------------------------------------------------------------------------
__device__ float g_A[(size_t)T_STEPS * BH];       // x-projection + b_ih (fp32)
__device__ float g_Hlast[BH];                      // final hidden state (fp32)
__device__ __half g_Xh[(size_t)TB * INF];         // X hi (fp16)
__device__ __half g_Hh[(size_t)T_STEPS * BH];     // H hi (fp16; lo not needed, x2)
__device__ __half g_Wih_h[HIDDEN * WROW];         // W_ih hi (row stride WROW)
__device__ __half g_Wih_l[HIDDEN * WROW];
__device__ __half g_Who_h[NCLS * HIDDEN];         // W_ho hi
__device__ __half g_Who_l[NCLS * HIDDEN];
__device__ __half g_h0h[BH];                      // h0 hi
// Per-group barrier state, line-padded; gens monotonic across graph replays.
__device__ unsigned g_gcnt[NGRP * 32];
__device__ unsigned g_ggen[NGRP * 32];

// ---------------------------------------------------------------------------
// Portable PTX helpers (sm_80+ features only)
// ---------------------------------------------------------------------------
__device__ __forceinline__ uint32_t smem_to_u32(const void* p) {
    uint32_t a;
    asm("{ .reg .u64 t; cvta.to.shared.u64 t, %1; cvt.u32.u64 %0, t; }"
        : "=r"(a) : "l"(p));
    return a;
}

__device__ __forceinline__ void cp16(uint32_t dst, const void* src) {
    asm volatile("cp.async.cg.shared.global [%0], [%1], 16;"
                 :: "r"(dst), "l"(__cvta_generic_to_global(src)));
}
#define CP_COMMIT()  asm volatile("cp.async.commit_group;" ::: "memory")
#define CP_WAIT(n)   asm volatile("cp.async.wait_group %0;" :: "n"(n) : "memory")

#define LDSM4(r0, r1, r2, r3, addr) \
    asm volatile("ldmatrix.sync.aligned.m8n8.x4.shared.b16 {%0,%1,%2,%3}, [%4];" \
                 : "=r"(r0), "=r"(r1), "=r"(r2), "=r"(r3) : "r"(addr))

// D[16x8] += A[16x16] * B[16x8]^(col)  -- fp16 in, fp32 accum
__device__ __forceinline__ void mma_f16(float* c, const uint32_t* a, const uint32_t* b) {
    asm volatile(
        "mma.sync.aligned.m16n8k16.row.col.f32.f16.f16.f32 "
        "{%0,%1,%2,%3}, {%4,%5,%6,%7}, {%8,%9}, {%0,%1,%2,%3};"
        : "+f"(c[0]), "+f"(c[1]), "+f"(c[2]), "+f"(c[3])
        : "r"(a[0]), "r"(a[1]), "r"(a[2]), "r"(a[3]), "r"(b[0]), "r"(b[1]));
}

// ---------------------------------------------------------------------------
// fp32 -> (hi, lo) fp16 split
// ---------------------------------------------------------------------------
__device__ __forceinline__ void split1h(float v, __half& h, __half& l) {
    h = __float2half_rn(v);
    l = __float2half_rn(v - __half2float(h));
}

__device__ __forceinline__ void split4_store(float4 v, __half* hi, __half* lo)
{
    __half h0, h1, h2, h3, l0, l1, l2, l3;
    split1h(v.x, h0, l0); split1h(v.y, h1, l1);
    split1h(v.z, h2, l2); split1h(v.w, h3, l3);
    __half2 t;
    t.x = h0; t.y = h1; *(__half2*)(hi)     = t;
    t.x = h2; t.y = h3; *(__half2*)(hi + 2) = t;
    t.x = l0; t.y = l1; *(__half2*)(lo)     = t;
    t.x = l2; t.y = l3; *(__half2*)(lo + 2) = t;
}

// hi-only fp16 conversion (X, h0)
__global__ void split_hi(const float* __restrict__ src, long n, __half* __restrict__ hi)
{
    for (long i = blockIdx.x * (long)blockDim.x + threadIdx.x; i < n / 4;
         i += (long)gridDim.x * blockDim.x) {
        long e = i * 4;
        float4 v = *(const float4*)(src + e);
        __half2 a, b;
        a.x = __float2half_rn(v.x); a.y = __float2half_rn(v.y);
        b.x = __float2half_rn(v.z); b.y = __float2half_rn(v.w);
        *(__half2*)(hi + e)     = a;
        *(__half2*)(hi + e + 2) = b;
    }
}

// Fused parameter split: W_ih + W_ho (hi/lo) + h0 (hi only), one launch
__global__ void split_params(const float* __restrict__ W_ih,
                             const float* __restrict__ W_ho,
                             const float* __restrict__ h0)
{
    const long n1 = (long)HIDDEN * WROW / 4;
    const long n2 = (long)NCLS * HIDDEN / 4;
    const long n3 = (long)BH / 4;
    for (long i = blockIdx.x * (long)blockDim.x + threadIdx.x; i < n1 + n2 + n3;
         i += (long)gridDim.x * blockDim.x) {
        if (i < n1 + n2) {
            const float* s; __half *hi, *lo; long e;
            if (i < n1) { s = W_ih; hi = g_Wih_h; lo = g_Wih_l; e = i * 4; }
            else        { s = W_ho; hi = g_Who_h; lo = g_Who_l; e = (i - n1) * 4; }
            split4_store(*(const float4*)(s + e), hi + e, lo + e);
        } else {
            long e = (i - n1 - n2) * 4;
            float4 v = *(const float4*)(h0 + e);
            __half2 a, b;
            a.x = __float2half_rn(v.x); a.y = __float2half_rn(v.y);
            b.x = __float2half_rn(v.z); b.y = __float2half_rn(v.w);
            *(__half2*)(g_h0h + e)     = a;
            *(__half2*)(g_h0h + e + 2) = b;
        }
    }
}

// ---------------------------------------------------------------------------
// mma.sync fp16 x2 GEMM (phases 1 & 3):
//   C[m,n] = sum_k A_hi[m,k] * (Bh + Bl)[n,k] + bias[n]
// CTA tile 128x128, BK=32, 8 warps (4M x 2N), 2-stage cp.async,
// 1 sync/chunk, x4-B ldmatrix.
// ---------------------------------------------------------------------------
#define ROWB   80
#define G_MAT  (128 * ROWB)          // 10240
#define G_STG  (3 * G_MAT)           // A | Bh | Bl = 30720
#define G_SMEM (2 * G_STG)           // 61440

__global__ void __launch_bounds__(256, 1)
gemm_mma_x2(const __half* __restrict__ A, long lda,
            const __half* __restrict__ Bh, const __half* __restrict__ Bl, long ldb,
            const float* __restrict__ bias, float* __restrict__ C, long ldc, int K)
{
    extern __shared__ char smem[];
    const uint32_t sb = smem_to_u32(smem);
    const int tid = threadIdx.x, lane = tid & 31, wid = tid >> 5;
    const int wm = wid & 3, wn = wid >> 2;
    const long bm = (long)blockIdx.y * 128;
    const long bn = (long)blockIdx.x * 128;

    float c[2][8][4];
#pragma unroll
    for (int m = 0; m < 2; m++)
#pragma unroll
        for (int n = 0; n < 8; n++)
#pragma unroll
            for (int j = 0; j < 4; j++) c[m][n][j] = 0.0f;

    const uint32_t a_rb = (uint32_t)(lane & 15) * ROWB + (uint32_t)(lane >> 4) * 16;
    const uint32_t b4_rb = (uint32_t)((lane & 7) + ((lane >> 4) << 3)) * ROWB
                           + (uint32_t)((lane >> 3) & 1) * 16;

    auto load_chunk = [&](int kc, int stage) {
        uint32_t base = sb + stage * G_STG;
#pragma unroll
        for (int it = 0; it < 2; it++) {
            int u = tid + it * 256;
            int row = u >> 2, seg = u & 3;
            uint32_t so = row * ROWB + seg * 16;
            long ga = (bm + row) * lda + kc + seg * 8;
            long gb = (bn + row) * ldb + kc + seg * 8;
            cp16(base + so,             A  + ga);
            cp16(base + G_MAT + so,     Bh + gb);
            cp16(base + 2 * G_MAT + so, Bl + gb);
        }
    };

    const int nchunk = K >> 5;
    load_chunk(0, 0);
    CP_COMMIT();

    for (int ch = 0; ch < nchunk; ch++) {
        CP_WAIT(0);
        __syncthreads();
        if (ch + 1 < nchunk) {
            load_chunk((ch + 1) << 5, (ch + 1) & 1);
            CP_COMMIT();
        }

        const uint32_t base = sb + (ch & 1) * G_STG;
#pragma unroll
        for (int k16 = 0; k16 < 2; k16++) {
            const uint32_t kb = k16 * 32;
            uint32_t ah[2][4], bh[8][2], bl[8][2];
#pragma unroll
            for (int m = 0; m < 2; m++) {
                uint32_t ra = base + (uint32_t)(wm * 32 + m * 16) * ROWB + kb + a_rb;
                LDSM4(ah[m][0], ah[m][1], ah[m][2], ah[m][3], ra);
            }
#pragma unroll
            for (int p = 0; p < 4; p++) {
                uint32_t rb = base + G_MAT + (uint32_t)(wn * 64 + p * 16) * ROWB + kb + b4_rb;
                LDSM4(bh[2*p][0], bh[2*p][1], bh[2*p+1][0], bh[2*p+1][1], rb);
                LDSM4(bl[2*p][0], bl[2*p][1], bl[2*p+1][0], bl[2*p+1][1], rb + G_MAT);
            }
#pragma unroll
            for (int m = 0; m < 2; m++)
#pragma unroll
                for (int n = 0; n < 8; n++) {
                    mma_f16(c[m][n], ah[m], bh[n]);
                    mma_f16(c[m][n], ah[m], bl[n]);
                }
        }
    }

#pragma unroll
    for (int m = 0; m < 2; m++) {
        long r0 = bm + wm * 32 + m * 16 + (lane >> 2);
        long r1 = r0 + 8;
#pragma unroll
        for (int n = 0; n < 8; n++) {
            long col = bn + wn * 64 + n * 8 + (lane & 3) * 2;
            float bx = bias[col], by = bias[col + 1];
            float2 v0 = { c[m][n][0] + bx, c[m][n][1] + by };
            float2 v1 = { c[m][n][2] + bx, c[m][n][3] + by };
            *(float2*)(C + r0 * ldc + col) = v0;
            *(float2*)(C + r1 * ldc + col) = v1;
        }
    }
}

// ---------------------------------------------------------------------------
// Per-group barrier (16 CTAs); groups fully decoupled closed systems.
// ---------------------------------------------------------------------------
__device__ __forceinline__ void group_bar(int g, unsigned& lgen)
{
    __syncthreads();
    if (threadIdx.x == 0) {
        __threadfence();
        if (atomicAdd(&g_gcnt[g * 32], 1u) == GRP_CTAS - 1) {
            atomicExch(&g_gcnt[g * 32], 0u);
            __threadfence();
            atomicAdd(&g_ggen[g * 32], 1u);
        } else {
            while (*(volatile unsigned*)&g_ggen[g * 32] == lgen) { __nanosleep(32); }
            __threadfence();
        }
        lgen++;
    }
    __syncthreads();
}

// ---------------------------------------------------------------------------
// Persistent recurrence (fp16 x2: h_hi @ (W_h + W_l)):
//   h_t = tanh(g_A[t] + h_{t-1} @ W_h^T)
// 128 CTAs = 8 groups x 16; CTA tile 32(batch) x 64(hidden); warps 2M x 4N.
// W_h hi resident in smem; streams A hi + W lo per BK=64 chunk.
// ---------------------------------------------------------------------------
#define ROWB2     144                        // 128B data + 16 pad (streamed)
#define RB_ROWB   2064                       // 2048B data + 16 pad (resident)
#define RBH_SZ    (64 * RB_ROWB)             // 132096
#define RA2_SZ    (32 * ROWB2)               // 4608 (A hi)
#define RBL2_SZ   (64 * ROWB2)               // 9216
#define R2_STG    (RA2_SZ + RBL2_SZ)         // 13824  (Ah | Bl)
#define R2_SMEM   (RBH_SZ + 2 * R2_STG)      // 159744

__global__ void __launch_bounds__(256, 1)
rnn_recur()
{
    extern __shared__ char smem[];
    const uint32_t sb = smem_to_u32(smem);
    const int tid = threadIdx.x, lane = tid & 31, wid = tid >> 5;
    const int wm = wid & 1, wn = wid >> 1;       // 2 x 4 warp grid
    const int grp = blockIdx.x >> 4;             // group (0..7)
    const int bm  = grp * 32;                    // batch rows [bm, bm+32)
    const int bn  = (blockIdx.x & 15) * 64;      // hidden cols [bn, bn+64)

    const uint32_t a_rb  = (uint32_t)(lane & 15) * ROWB2 + (uint32_t)(lane >> 4) * 16;
    const uint32_t b4h_rb = (uint32_t)((lane & 7) + ((lane >> 4) << 3)) * RB_ROWB
                            + (uint32_t)((lane >> 3) & 1) * 16;
    const uint32_t b4l_rb = (uint32_t)((lane & 7) + ((lane >> 4) << 3)) * ROWB2
                            + (uint32_t)((lane >> 3) & 1) * 16;

    // ---- Resident W_h hi tile: 64 rows x 1024 fp16 (8192 x 16B units)
    for (int u = tid; u < 8192; u += 256) {
        int row = u >> 7, seg = u & 127;
        cp16(sb + row * RB_ROWB + seg * 16,
             g_Wih_h + (size_t)(bn + row) * WROW + INF + seg * 8);
    }
    CP_COMMIT();

    unsigned lgen = *(volatile unsigned*)&g_ggen[grp * 32];

    for (int t = 0; t < T_STEPS; t++) {
        const __half* hh = (t == 0) ? g_h0h : (g_Hh + (size_t)(t - 1) * BH);
        const size_t ob = (size_t)t * BH;

        float c[2][4];
#pragma unroll
        for (int n = 0; n < 2; n++)
#pragma unroll
            for (int j = 0; j < 4; j++) c[n][j] = 0.0f;

        auto load_chunk = [&](int kc, int stage) {
            uint32_t base = sb + RBH_SZ + stage * R2_STG;
            // A hi: 32 rows x 8 segs = 256 units (1/thread)
            {
                int row = tid >> 3, seg = tid & 7;
                cp16(base + row * ROWB2 + seg * 16,
                     hh + (size_t)(bm + row) * HIDDEN + kc + seg * 8);
            }
            // W lo: 64 rows x 8 segs = 512 units (2/thread)
#pragma unroll
            for (int it = 0; it < 2; it++) {
                int u = tid + it * 256;
                int row = u >> 3, seg = u & 7;
                cp16(base + RA2_SZ + row * ROWB2 + seg * 16,
                     g_Wih_l + (size_t)(bn + row) * WROW + INF + kc + seg * 8);
            }
        };

        load_chunk(0, 0);
        CP_COMMIT();

        for (int ch = 0; ch < HIDDEN / 64; ch++) {     // 16 chunks
            CP_WAIT(0);
            __syncthreads();       // chunk ch visible; all warps done with ch-1
            if (ch + 1 < HIDDEN / 64) {
                load_chunk((ch + 1) << 6, (ch + 1) & 1);
                CP_COMMIT();
            }

            const uint32_t base  = sb + RBH_SZ + (ch & 1) * R2_STG;
            const uint32_t abase = base + (uint32_t)(wm * 16) * ROWB2 + a_rb;
            const uint32_t bhb   = sb + (uint32_t)(wn * 16) * RB_ROWB
                                   + (uint32_t)(ch << 7) + b4h_rb;
            const uint32_t blb   = base + RA2_SZ + (uint32_t)(wn * 16) * ROWB2 + b4l_rb;

            // Fragment-pipelined k16 loop (4 iters, double-buffered)
            uint32_t ah[2][4], bh[2][2][2], bl[2][2][2];

#define R_LD(k16, buf) do { \
        uint32_t _ra = abase + (uint32_t)((k16) * 32); \
        LDSM4(ah[buf][0], ah[buf][1], ah[buf][2], ah[buf][3], _ra); \
        LDSM4(bh[buf][0][0], bh[buf][0][1], bh[buf][1][0], bh[buf][1][1], \
              bhb + (uint32_t)((k16) * 32)); \
        LDSM4(bl[buf][0][0], bl[buf][0][1], bl[buf][1][0], bl[buf][1][1], \
              blb + (uint32_t)((k16) * 32)); \
    } while (0)

            R_LD(0, 0);
#pragma unroll
            for (int k16 = 0; k16 < 4; k16++) {
                if (k16 < 3) R_LD(k16 + 1, (k16 + 1) & 1);
                const int b = k16 & 1;
#pragma unroll
                for (int n = 0; n < 2; n++) {
                    mma_f16(c[n], ah[b], bh[b][n]);
                    mma_f16(c[n], ah[b], bl[b][n]);
                }
            }
#undef R_LD
        }

        // Epilogue: tanh(acc + pre), store fp16 hi
        {
            const int r0 = bm + wm * 16 + (lane >> 2);
            const int r1 = r0 + 8;
#pragma unroll
            for (int n = 0; n < 2; n++) {
                const int col = bn + wn * 16 + n * 8 + (lane & 3) * 2;
                float2 p0 = *(const float2*)(g_A + ob + (size_t)r0 * HIDDEN + col);
                float2 p1 = *(const float2*)(g_A + ob + (size_t)r1 * HIDDEN + col);
                float h00 = tanhf(c[n][0] + p0.x);
                float h01 = tanhf(c[n][1] + p0.y);
                float h10 = tanhf(c[n][2] + p1.x);
                float h11 = tanhf(c[n][3] + p1.y);

                __half2 th;
                th.x = __float2half_rn(h00); th.y = __float2half_rn(h01);
                *(__half2*)(g_Hh + ob + (size_t)r0 * HIDDEN + col) = th;
                th.x = __float2half_rn(h10); th.y = __float2half_rn(h11);
                *(__half2*)(g_Hh + ob + (size_t)r1 * HIDDEN + col) = th;

                if (t == T_STEPS - 1) {
                    float2 f0 = { h00, h01 }, f1 = { h10, h11 };
                    *(float2*)(g_Hlast + (size_t)r0 * HIDDEN + col) = f0;
                    *(float2*)(g_Hlast + (size_t)r1 * HIDDEN + col) = f1;
                }
            }
        }

        group_bar(grp, lgen);   // 16-CTA rendezvous; groups fully decoupled
    }
}

// ---------------------------------------------------------------------------
// In-place softmax over rows of 512 floats
// ---------------------------------------------------------------------------
__global__ void softmax512(float* __restrict__ O)
{
    __shared__ float red[4];
    long row = blockIdx.x;
    float4* p = (float4*)(O + row * (long)NCLS);
    float4 v = p[threadIdx.x];

    float m = fmaxf(fmaxf(v.x, v.y), fmaxf(v.z, v.w));
#pragma unroll
    for (int o = 16; o > 0; o >>= 1)
        m = fmaxf(m, __shfl_xor_sync(0xffffffffu, m, o));
    int warp = threadIdx.x >> 5;
    if ((threadIdx.x & 31) == 0) red[warp] = m;
    __syncthreads();
    m = fmaxf(fmaxf(red[0], red[1]), fmaxf(red[2], red[3]));

    float4 e;
    e.x = __expf(v.x - m);
    e.y = __expf(v.y - m);
    e.z = __expf(v.z - m);
    e.w = __expf(v.w - m);
    float s = e.x + e.y + e.z + e.w;
#pragma unroll
    for (int o = 16; o > 0; o >>= 1)
        s += __shfl_xor_sync(0xffffffffu, s, o);
    __syncthreads();
    if ((threadIdx.x & 31) == 0) red[warp] = s;
    __syncthreads();
    s = red[0] + red[1] + red[2] + red[3];

    float inv = 1.0f / s;
    e.x *= inv; e.y *= inv; e.z *= inv; e.w *= inv;
    p[threadIdx.x] = e;
}

// ---------------------------------------------------------------------------
// Launch (7 graph nodes)
// ---------------------------------------------------------------------------
extern "C" void kernel_launch(void* const* d_in, const int* in_sizes, int n_in,
                              void* d_out, int out_size)
{
    const float* x    = (const float*)d_in[0];
    const float* h0   = (const float*)d_in[1];
    const float* W_ih = (const float*)d_in[2];
    const float* b_ih = (const float*)d_in[3];
    const float* W_ho = (const float*)d_in[4];
    const float* b_ho = (const float*)d_in[5];
    float*       out  = (float*)d_out;

    float *pA, *pHlast;
    __half *pXh, *pHh, *pWih_h, *pWih_l, *pWoh, *pWol;
    cudaGetSymbolAddress((void**)&pA,     g_A);
    cudaGetSymbolAddress((void**)&pHlast, g_Hlast);
    cudaGetSymbolAddress((void**)&pXh,    g_Xh);
    cudaGetSymbolAddress((void**)&pHh,    g_Hh);
    cudaGetSymbolAddress((void**)&pWih_h, g_Wih_h);
    cudaGetSymbolAddress((void**)&pWih_l, g_Wih_l);
    cudaGetSymbolAddress((void**)&pWoh,   g_Who_h);
    cudaGetSymbolAddress((void**)&pWol,   g_Who_l);

    cudaFuncSetAttribute(gemm_mma_x2,
                         cudaFuncAttributeMaxDynamicSharedMemorySize, G_SMEM);
    cudaFuncSetAttribute(rnn_recur,
                         cudaFuncAttributeMaxDynamicSharedMemorySize, R2_SMEM);

    // #1: X hi-split; #2: fused param splits
    split_hi<<<4096, 256>>>(x, (long)TB * INF, pXh);
    split_params<<<1024, 256>>>(W_ih, W_ho, h0);

    // #3: Phase 1 -- g_A = Xh @ (Wx_h + Wx_l)^T + b_ih   (fp16 x2)
    {
        dim3 grid(HIDDEN / 128, TB / 128);   // (8, 1024)
        gemm_mma_x2<<<grid, 256, G_SMEM>>>(pXh, INF,
                                           pWih_h, pWih_l, WROW,
                                           b_ih, pA, HIDDEN, INF);
    }

    // #4: Phase 2 -- persistent recurrence (fp16 x2, 8 decoupled groups)
    rnn_recur<<<NCTAS, 256, R2_SMEM>>>();

    // #5/#6: Phase 3 -- out = Hh @ (Who_h + Who_l)^T + b_ho (fp16 x2), softmax
    {
        dim3 grid(NCLS / 128, TB / 128);     // (4, 1024)
        gemm_mma_x2<<<grid, 256, G_SMEM>>>(pHh, HIDDEN,
                                           pWoh, pWol, HIDDEN,
                                           b_ho, out, NCLS, HIDDEN);
        softmax512<<<TB, 128>>>(out);
    }

    // #7: h_last
    cudaMemcpyAsync(out + (long)TB * NCLS, pHlast,
                    (size_t)BH * sizeof(float), cudaMemcpyDeviceToDevice);
}

// round 12
// speedup vs baseline: 2.2162x; 1.2377x over previous
#include <cuda_runtime.h>
#include <cuda_fp16.h>
#include <math.h>
#include <stdint.h>

// ---------------------------------------------------------------------------
// Problem constants
// ---------------------------------------------------------------------------
#define T_STEPS 512
#define BATCH   256
#define INF     1024
#define HIDDEN  1024
#define WROW    (INF + HIDDEN)
#define NCLS    512
#define BH      (BATCH * HIDDEN)      // 262144
#define TB      (T_STEPS * BATCH)     // 131072
#define NCTAS   128                   // persistent recurrence grid
#define NGRP    8                     // independent recurrence groups
#define GRP_CTAS 16                   // CTAs per group

// ---------------------------------------------------------------------------
// Device-global scratch (allocation-free rule)
// ---------------------------------------------------------------------------
__device__ float g_A[(size_t)T_STEPS * BH];       // x-projection + b_ih (fp32)
__device__ float g_Hlast[BH];                      // final hidden state (fp32)
__device__ __half g_Xh[(size_t)TB * INF];         // X hi (fp16)
__device__ __half g_Hh[(size_t)T_STEPS * BH];     // H hi (fp16)
__device__ __half g_Wih_h[HIDDEN * WROW];         // W_ih hi (row stride WROW)
__device__ __half g_Wih_l[HIDDEN * WROW];         // W_ih lo (phase 1 only)
__device__ __half g_Who_h[NCLS * HIDDEN];         // W_ho hi
__device__ __half g_Who_l[NCLS * HIDDEN];
__device__ __half g_h0h[BH];                      // h0 hi
// Per-group barrier state, line-padded; gens monotonic across graph replays.
__device__ unsigned g_gcnt[NGRP * 32];
__device__ unsigned g_ggen[NGRP * 32];

// ---------------------------------------------------------------------------
// Portable PTX helpers (sm_80+ features only)
// ---------------------------------------------------------------------------
__device__ __forceinline__ uint32_t smem_to_u32(const void* p) {
    uint32_t a;
    asm("{ .reg .u64 t; cvta.to.shared.u64 t, %1; cvt.u32.u64 %0, t; }"
        : "=r"(a) : "l"(p));
    return a;
}

__device__ __forceinline__ void cp16(uint32_t dst, const void* src) {
    asm volatile("cp.async.cg.shared.global [%0], [%1], 16;"
                 :: "r"(dst), "l"(__cvta_generic_to_global(src)));
}
#define CP_COMMIT()  asm volatile("cp.async.commit_group;" ::: "memory")
#define CP_WAIT(n)   asm volatile("cp.async.wait_group %0;" :: "n"(n) : "memory")

#define LDSM4(r0, r1, r2, r3, addr) \
    asm volatile("ldmatrix.sync.aligned.m8n8.x4.shared.b16 {%0,%1,%2,%3}, [%4];" \
                 : "=r"(r0), "=r"(r1), "=r"(r2), "=r"(r3) : "r"(addr))

// D[16x8] += A[16x16] * B[16x8]^(col)  -- fp16 in, fp32 accum
__device__ __forceinline__ void mma_f16(float* c, const uint32_t* a, const uint32_t* b) {
    asm volatile(
        "mma.sync.aligned.m16n8k16.row.col.f32.f16.f16.f32 "
        "{%0,%1,%2,%3}, {%4,%5,%6,%7}, {%8,%9}, {%0,%1,%2,%3};"
        : "+f"(c[0]), "+f"(c[1]), "+f"(c[2]), "+f"(c[3])
        : "r"(a[0]), "r"(a[1]), "r"(a[2]), "r"(a[3]), "r"(b[0]), "r"(b[1]));
}

// ---------------------------------------------------------------------------
// fp32 -> (hi, lo) fp16 split
// ---------------------------------------------------------------------------
__device__ __forceinline__ void split1h(float v, __half& h, __half& l) {
    h = __float2half_rn(v);
    l = __float2half_rn(v - __half2float(h));
}

__device__ __forceinline__ void split4_store(float4 v, __half* hi, __half* lo)
{
    __half h0, h1, h2, h3, l0, l1, l2, l3;
    split1h(v.x, h0, l0); split1h(v.y, h1, l1);
    split1h(v.z, h2, l2); split1h(v.w, h3, l3);
    __half2 t;
    t.x = h0; t.y = h1; *(__half2*)(hi)     = t;
    t.x = h2; t.y = h3; *(__half2*)(hi + 2) = t;
    t.x = l0; t.y = l1; *(__half2*)(lo)     = t;
    t.x = l2; t.y = l3; *(__half2*)(lo + 2) = t;
}

// hi-only fp16 conversion (X, h0)
__global__ void split_hi(const float* __restrict__ src, long n, __half* __restrict__ hi)
{
    for (long i = blockIdx.x * (long)blockDim.x + threadIdx.x; i < n / 4;
         i += (long)gridDim.x * blockDim.x) {
        long e = i * 4;
        float4 v = *(const float4*)(src + e);
        __half2 a, b;
        a.x = __float2half_rn(v.x); a.y = __float2half_rn(v.y);
        b.x = __float2half_rn(v.z); b.y = __float2half_rn(v.w);
        *(__half2*)(hi + e)     = a;
        *(__half2*)(hi + e + 2) = b;
    }
}

// Fused parameter split: W_ih + W_ho (hi/lo) + h0 (hi only), one launch
__global__ void split_params(const float* __restrict__ W_ih,
                             const float* __restrict__ W_ho,
                             const float* __restrict__ h0)
{
    const long n1 = (long)HIDDEN * WROW / 4;
    const long n2 = (long)NCLS * HIDDEN / 4;
    const long n3 = (long)BH / 4;
    for (long i = blockIdx.x * (long)blockDim.x + threadIdx.x; i < n1 + n2 + n3;
         i += (long)gridDim.x * blockDim.x) {
        if (i < n1 + n2) {
            const float* s; __half *hi, *lo; long e;
            if (i < n1) { s = W_ih; hi = g_Wih_h; lo = g_Wih_l; e = i * 4; }
            else        { s = W_ho; hi = g_Who_h; lo = g_Who_l; e = (i - n1) * 4; }
            split4_store(*(const float4*)(s + e), hi + e, lo + e);
        } else {
            long e = (i - n1 - n2) * 4;
            float4 v = *(const float4*)(h0 + e);
            __half2 a, b;
            a.x = __float2half_rn(v.x); a.y = __float2half_rn(v.y);
            b.x = __float2half_rn(v.z); b.y = __float2half_rn(v.w);
            *(__half2*)(g_h0h + e)     = a;
            *(__half2*)(g_h0h + e + 2) = b;
        }
    }
}

// ---------------------------------------------------------------------------
// mma.sync fp16 x2 GEMM (phases 1 & 3):
//   C[m,n] = sum_k A_hi[m,k] * (Bh + Bl)[n,k] + bias[n]
// CTA tile 128x128, BK=32, 8 warps (4M x 2N), 2-stage cp.async,
// 1 sync/chunk, x4-B ldmatrix.
// ---------------------------------------------------------------------------
#define ROWB   80
#define G_MAT  (128 * ROWB)          // 10240
#define G_STG  (3 * G_MAT)           // A | Bh | Bl = 30720
#define G_SMEM (2 * G_STG)           // 61440

__global__ void __launch_bounds__(256, 1)
gemm_mma_x2(const __half* __restrict__ A, long lda,
            const __half* __restrict__ Bh, const __half* __restrict__ Bl, long ldb,
            const float* __restrict__ bias, float* __restrict__ C, long ldc, int K)
{
    extern __shared__ char smem[];
    const uint32_t sb = smem_to_u32(smem);
    const int tid = threadIdx.x, lane = tid & 31, wid = tid >> 5;
    const int wm = wid & 3, wn = wid >> 2;
    const long bm = (long)blockIdx.y * 128;
    const long bn = (long)blockIdx.x * 128;

    float c[2][8][4];
#pragma unroll
    for (int m = 0; m < 2; m++)
#pragma unroll
        for (int n = 0; n < 8; n++)
#pragma unroll
            for (int j = 0; j < 4; j++) c[m][n][j] = 0.0f;

    const uint32_t a_rb = (uint32_t)(lane & 15) * ROWB + (uint32_t)(lane >> 4) * 16;
    const uint32_t b4_rb = (uint32_t)((lane & 7) + ((lane >> 4) << 3)) * ROWB
                           + (uint32_t)((lane >> 3) & 1) * 16;

    auto load_chunk = [&](int kc, int stage) {
        uint32_t base = sb + stage * G_STG;
#pragma unroll
        for (int it = 0; it < 2; it++) {
            int u = tid + it * 256;
            int row = u >> 2, seg = u & 3;
            uint32_t so = row * ROWB + seg * 16;
            long ga = (bm + row) * lda + kc + seg * 8;
            long gb = (bn + row) * ldb + kc + seg * 8;
            cp16(base + so,             A  + ga);
            cp16(base + G_MAT + so,     Bh + gb);
            cp16(base + 2 * G_MAT + so, Bl + gb);
        }
    };

    const int nchunk = K >> 5;
    load_chunk(0, 0);
    CP_COMMIT();

    for (int ch = 0; ch < nchunk; ch++) {
        CP_WAIT(0);
        __syncthreads();
        if (ch + 1 < nchunk) {
            load_chunk((ch + 1) << 5, (ch + 1) & 1);
            CP_COMMIT();
        }

        const uint32_t base = sb + (ch & 1) * G_STG;
#pragma unroll
        for (int k16 = 0; k16 < 2; k16++) {
            const uint32_t kb = k16 * 32;
            uint32_t ah[2][4], bh[8][2], bl[8][2];
#pragma unroll
            for (int m = 0; m < 2; m++) {
                uint32_t ra = base + (uint32_t)(wm * 32 + m * 16) * ROWB + kb + a_rb;
                LDSM4(ah[m][0], ah[m][1], ah[m][2], ah[m][3], ra);
            }
#pragma unroll
            for (int p = 0; p < 4; p++) {
                uint32_t rb = base + G_MAT + (uint32_t)(wn * 64 + p * 16) * ROWB + kb + b4_rb;
                LDSM4(bh[2*p][0], bh[2*p][1], bh[2*p+1][0], bh[2*p+1][1], rb);
                LDSM4(bl[2*p][0], bl[2*p][1], bl[2*p+1][0], bl[2*p+1][1], rb + G_MAT);
            }
#pragma unroll
            for (int m = 0; m < 2; m++)
#pragma unroll
                for (int n = 0; n < 8; n++) {
                    mma_f16(c[m][n], ah[m], bh[n]);
                    mma_f16(c[m][n], ah[m], bl[n]);
                }
        }
    }

#pragma unroll
    for (int m = 0; m < 2; m++) {
        long r0 = bm + wm * 32 + m * 16 + (lane >> 2);
        long r1 = r0 + 8;
#pragma unroll
        for (int n = 0; n < 8; n++) {
            long col = bn + wn * 64 + n * 8 + (lane & 3) * 2;
            float bx = bias[col], by = bias[col + 1];
            float2 v0 = { c[m][n][0] + bx, c[m][n][1] + by };
            float2 v1 = { c[m][n][2] + bx, c[m][n][3] + by };
            *(float2*)(C + r0 * ldc + col) = v0;
            *(float2*)(C + r1 * ldc + col) = v1;
        }
    }
}

// ---------------------------------------------------------------------------
// Per-group barrier (16 CTAs); groups fully decoupled closed systems.
// ---------------------------------------------------------------------------
__device__ __forceinline__ void group_bar(int g, unsigned& lgen)
{
    __syncthreads();
    if (threadIdx.x == 0) {
        __threadfence();
        if (atomicAdd(&g_gcnt[g * 32], 1u) == GRP_CTAS - 1) {
            atomicExch(&g_gcnt[g * 32], 0u);
            __threadfence();
            atomicAdd(&g_ggen[g * 32], 1u);
        } else {
            while (*(volatile unsigned*)&g_ggen[g * 32] == lgen) { __nanosleep(32); }
            __threadfence();
        }
        lgen++;
    }
    __syncthreads();
}

// ---------------------------------------------------------------------------
// Persistent recurrence (fp16 x1: h_hi @ W_hi, W fully resident):
//   h_t = tanh(g_A[t] + h_{t-1} @ W_h^T)
// 128 CTAs = 8 groups x 16; CTA tile 32(batch) x 64(hidden); warps 2M x 4N.
// Streams ONLY A hi per BK=128 chunk (8 KB), double-buffered; 8 syncs/step.
// ---------------------------------------------------------------------------
#define A_RB      272                        // 256B data + 16 pad (streamed A)
#define RB_ROWB   2064                       // 2048B data + 16 pad (resident W)
#define RBH_SZ    (64 * RB_ROWB)             // 132096
#define RA_SZ     (32 * A_RB)                // 8704 per stage
#define R2_SMEM   (RBH_SZ + 2 * RA_SZ)       // 149504

__global__ void __launch_bounds__(256, 1)
rnn_recur()
{
    extern __shared__ char smem[];
    const uint32_t sb = smem_to_u32(smem);
    const int tid = threadIdx.x, lane = tid & 31, wid = tid >> 5;
    const int wm = wid & 1, wn = wid >> 1;       // 2 x 4 warp grid
    const int grp = blockIdx.x >> 4;             // group (0..7)
    const int bm  = grp * 32;                    // batch rows [bm, bm+32)
    const int bn  = (blockIdx.x & 15) * 64;      // hidden cols [bn, bn+64)

    const uint32_t a_rb   = (uint32_t)(lane & 15) * A_RB + (uint32_t)(lane >> 4) * 16;
    const uint32_t b4h_rb = (uint32_t)((lane & 7) + ((lane >> 4) << 3)) * RB_ROWB
                            + (uint32_t)((lane >> 3) & 1) * 16;

    // ---- Resident W_h hi tile: 64 rows x 1024 fp16 (8192 x 16B units)
    for (int u = tid; u < 8192; u += 256) {
        int row = u >> 7, seg = u & 127;
        cp16(sb + row * RB_ROWB + seg * 16,
             g_Wih_h + (size_t)(bn + row) * WROW + INF + seg * 8);
    }
    CP_COMMIT();

    unsigned lgen = *(volatile unsigned*)&g_ggen[grp * 32];

    for (int t = 0; t < T_STEPS; t++) {
        const __half* hh = (t == 0) ? g_h0h : (g_Hh + (size_t)(t - 1) * BH);
        const size_t ob = (size_t)t * BH;

        float c[2][4];
#pragma unroll
        for (int n = 0; n < 2; n++)
#pragma unroll
            for (int j = 0; j < 4; j++) c[n][j] = 0.0f;

        // Stream A hi chunk: 32 rows x 128 cols fp16 = 512 x 16B units (2/thread)
        auto load_chunk = [&](int kc, int stage) {
            uint32_t base = sb + RBH_SZ + stage * RA_SZ;
#pragma unroll
            for (int it = 0; it < 2; it++) {
                int u = tid + it * 256;
                int row = u >> 4, seg = u & 15;
                cp16(base + row * A_RB + seg * 16,
                     hh + (size_t)(bm + row) * HIDDEN + kc + seg * 8);
            }
        };

        load_chunk(0, 0);
        CP_COMMIT();

        for (int ch = 0; ch < HIDDEN / 128; ch++) {    // 8 chunks (BK=128)
            CP_WAIT(0);
            __syncthreads();       // chunk ch visible; all warps done with ch-1
            if (ch + 1 < HIDDEN / 128) {
                load_chunk((ch + 1) << 7, (ch + 1) & 1);
                CP_COMMIT();
            }

            const uint32_t abase = sb + RBH_SZ + (ch & 1) * RA_SZ
                                   + (uint32_t)(wm * 16) * A_RB + a_rb;
            const uint32_t bhb   = sb + (uint32_t)(wn * 16) * RB_ROWB
                                   + (uint32_t)(ch << 8) + b4h_rb;

            // Fragment-pipelined k16 loop (8 iters, double-buffered)
            uint32_t ah[2][4], bh[2][2][2];

#define R_LD(k16, buf) do { \
        LDSM4(ah[buf][0], ah[buf][1], ah[buf][2], ah[buf][3], \
              abase + (uint32_t)((k16) * 32)); \
        LDSM4(bh[buf][0][0], bh[buf][0][1], bh[buf][1][0], bh[buf][1][1], \
              bhb + (uint32_t)((k16) * 32)); \
    } while (0)

            R_LD(0, 0);
#pragma unroll
            for (int k16 = 0; k16 < 8; k16++) {
                if (k16 < 7) R_LD(k16 + 1, (k16 + 1) & 1);
                const int b = k16 & 1;
#pragma unroll
                for (int n = 0; n < 2; n++)
                    mma_f16(c[n], ah[b], bh[b][n]);
            }
#undef R_LD
        }

        // Epilogue: tanh(acc + pre), store fp16 hi
        {
            const int r0 = bm + wm * 16 + (lane >> 2);
            const int r1 = r0 + 8;
#pragma unroll
            for (int n = 0; n < 2; n++) {
                const int col = bn + wn * 16 + n * 8 + (lane & 3) * 2;
                float2 p0 = *(const float2*)(g_A + ob + (size_t)r0 * HIDDEN + col);
                float2 p1 = *(const float2*)(g_A + ob + (size_t)r1 * HIDDEN + col);
                float h00 = tanhf(c[n][0] + p0.x);
                float h01 = tanhf(c[n][1] + p0.y);
                float h10 = tanhf(c[n][2] + p1.x);
                float h11 = tanhf(c[n][3] + p1.y);

                __half2 th;
                th.x = __float2half_rn(h00); th.y = __float2half_rn(h01);
                *(__half2*)(g_Hh + ob + (size_t)r0 * HIDDEN + col) = th;
                th.x = __float2half_rn(h10); th.y = __float2half_rn(h11);
                *(__half2*)(g_Hh + ob + (size_t)r1 * HIDDEN + col) = th;

                if (t == T_STEPS - 1) {
                    float2 f0 = { h00, h01 }, f1 = { h10, h11 };
                    *(float2*)(g_Hlast + (size_t)r0 * HIDDEN + col) = f0;
                    *(float2*)(g_Hlast + (size_t)r1 * HIDDEN + col) = f1;
                }
            }
        }

        group_bar(grp, lgen);   // 16-CTA rendezvous; groups fully decoupled
    }
}

// ---------------------------------------------------------------------------
// In-place softmax over rows of 512 floats
// ---------------------------------------------------------------------------
__global__ void softmax512(float* __restrict__ O)
{
    __shared__ float red[4];
    long row = blockIdx.x;
    float4* p = (float4*)(O + row * (long)NCLS);
    float4 v = p[threadIdx.x];

    float m = fmaxf(fmaxf(v.x, v.y), fmaxf(v.z, v.w));
#pragma unroll
    for (int o = 16; o > 0; o >>= 1)
        m = fmaxf(m, __shfl_xor_sync(0xffffffffu, m, o));
    int warp = threadIdx.x >> 5;
    if ((threadIdx.x & 31) == 0) red[warp] = m;
    __syncthreads();
    m = fmaxf(fmaxf(red[0], red[1]), fmaxf(red[2], red[3]));

    float4 e;
    e.x = __expf(v.x - m);
    e.y = __expf(v.y - m);
    e.z = __expf(v.z - m);
    e.w = __expf(v.w - m);
    float s = e.x + e.y + e.z + e.w;
#pragma unroll
    for (int o = 16; o > 0; o >>= 1)
        s += __shfl_xor_sync(0xffffffffu, s, o);
    __syncthreads();
    if ((threadIdx.x & 31) == 0) red[warp] = s;
    __syncthreads();
    s = red[0] + red[1] + red[2] + red[3];

    float inv = 1.0f / s;
    e.x *= inv; e.y *= inv; e.z *= inv; e.w *= inv;
    p[threadIdx.x] = e;
}

// ---------------------------------------------------------------------------
// Launch (7 graph nodes)
// ---------------------------------------------------------------------------
extern "C" void kernel_launch(void* const* d_in, const int* in_sizes, int n_in,
                              void* d_out, int out_size)
{
    const float* x    = (const float*)d_in[0];
    const float* h0   = (const float*)d_in[1];
    const float* W_ih = (const float*)d_in[2];
    const float* b_ih = (const float*)d_in[3];
    const float* W_ho = (const float*)d_in[4];
    const float* b_ho = (const float*)d_in[5];
    float*       out  = (float*)d_out;

    float *pA, *pHlast;
    __half *pXh, *pHh, *pWih_h, *pWih_l, *pWoh, *pWol;
    cudaGetSymbolAddress((void**)&pA,     g_A);
    cudaGetSymbolAddress((void**)&pHlast, g_Hlast);
    cudaGetSymbolAddress((void**)&pXh,    g_Xh);
    cudaGetSymbolAddress((void**)&pHh,    g_Hh);
    cudaGetSymbolAddress((void**)&pWih_h, g_Wih_h);
    cudaGetSymbolAddress((void**)&pWih_l, g_Wih_l);
    cudaGetSymbolAddress((void**)&pWoh,   g_Who_h);
    cudaGetSymbolAddress((void**)&pWol,   g_Who_l);

    cudaFuncSetAttribute(gemm_mma_x2,
                         cudaFuncAttributeMaxDynamicSharedMemorySize, G_SMEM);
    cudaFuncSetAttribute(rnn_recur,
                         cudaFuncAttributeMaxDynamicSharedMemorySize, R2_SMEM);

    // #1: X hi-split; #2: fused param splits
    split_hi<<<4096, 256>>>(x, (long)TB * INF, pXh);
    split_params<<<1024, 256>>>(W_ih, W_ho, h0);

    // #3: Phase 1 -- g_A = Xh @ (Wx_h + Wx_l)^T + b_ih   (fp16 x2)
    {
        dim3 grid(HIDDEN / 128, TB / 128);   // (8, 1024)
        gemm_mma_x2<<<grid, 256, G_SMEM>>>(pXh, INF,
                                           pWih_h, pWih_l, WROW,
                                           b_ih, pA, HIDDEN, INF);
    }

    // #4: Phase 2 -- persistent recurrence (fp16 x1, W resident, 8 groups)
    rnn_recur<<<NCTAS, 256, R2_SMEM>>>();

    // #5/#6: Phase 3 -- out = Hh @ (Who_h + Who_l)^T + b_ho (fp16 x2), softmax
    {
        dim3 grid(NCLS / 128, TB / 128);     // (4, 1024)
        gemm_mma_x2<<<grid, 256, G_SMEM>>>(pHh, HIDDEN,
                                           pWoh, pWol, HIDDEN,
                                           b_ho, out, NCLS, HIDDEN);
        softmax512<<<TB, 128>>>(out);
    }

    // #7: h_last
    cudaMemcpyAsync(out + (long)TB * NCLS, pHlast,
                    (size_t)BH * sizeof(float), cudaMemcpyDeviceToDevice);
}

// round 13
// speedup vs baseline: 2.7620x; 1.2463x over previous
#include <cuda_runtime.h>
#include <cuda_fp16.h>
#include <math.h>
#include <stdint.h>

// ---------------------------------------------------------------------------
// Problem constants
// ---------------------------------------------------------------------------
#define T_STEPS 512
#define BATCH   256
#define INF     1024
#define HIDDEN  1024
#define WROW    (INF + HIDDEN)
#define NCLS    512
#define BH      (BATCH * HIDDEN)      // 262144
#define TB      (T_STEPS * BATCH)     // 131072
#define NCTAS   128                   // persistent recurrence grid
#define NGRP    8                     // independent recurrence groups
#define GRP_CTAS 16                   // CTAs per group

// ---------------------------------------------------------------------------
// Device-global scratch (allocation-free rule)
// ---------------------------------------------------------------------------
__device__ float g_A[(size_t)T_STEPS * BH];       // x-projection + b_ih (fp32)
__device__ float g_Hlast[BH];                      // final hidden state (fp32)
__device__ __half g_Xh[(size_t)TB * INF];         // X hi (fp16)
__device__ __half g_Hh[(size_t)T_STEPS * BH];     // H hi (fp16)
__device__ __half g_Wih_h[HIDDEN * WROW];         // W_ih hi (row stride WROW)
__device__ __half g_Who_h[NCLS * HIDDEN];         // W_ho hi
__device__ __half g_h0h[BH];                      // h0 hi
// Per-group barrier state, line-padded; gens monotonic across graph replays.
__device__ unsigned g_gcnt[NGRP * 32];
__device__ unsigned g_ggen[NGRP * 32];

// ---------------------------------------------------------------------------
// Portable PTX helpers (sm_80+ features only)
// ---------------------------------------------------------------------------
__device__ __forceinline__ uint32_t smem_to_u32(const void* p) {
    uint32_t a;
    asm("{ .reg .u64 t; cvta.to.shared.u64 t, %1; cvt.u32.u64 %0, t; }"
        : "=r"(a) : "l"(p));
    return a;
}

__device__ __forceinline__ void cp16(uint32_t dst, const void* src) {
    asm volatile("cp.async.cg.shared.global [%0], [%1], 16;"
                 :: "r"(dst), "l"(__cvta_generic_to_global(src)));
}
#define CP_COMMIT()  asm volatile("cp.async.commit_group;" ::: "memory")
#define CP_WAIT(n)   asm volatile("cp.async.wait_group %0;" :: "n"(n) : "memory")

#define LDSM4(r0, r1, r2, r3, addr) \
    asm volatile("ldmatrix.sync.aligned.m8n8.x4.shared.b16 {%0,%1,%2,%3}, [%4];" \
                 : "=r"(r0), "=r"(r1), "=r"(r2), "=r"(r3) : "r"(addr))

// D[16x8] += A[16x16] * B[16x8]^(col)  -- fp16 in, fp32 accum
__device__ __forceinline__ void mma_f16(float* c, const uint32_t* a, const uint32_t* b) {
    asm volatile(
        "mma.sync.aligned.m16n8k16.row.col.f32.f16.f16.f32 "
        "{%0,%1,%2,%3}, {%4,%5,%6,%7}, {%8,%9}, {%0,%1,%2,%3};"
        : "+f"(c[0]), "+f"(c[1]), "+f"(c[2]), "+f"(c[3])
        : "r"(a[0]), "r"(a[1]), "r"(a[2]), "r"(a[3]), "r"(b[0]), "r"(b[1]));
}

// ---------------------------------------------------------------------------
// hi-only fp16 conversion (X)
// ---------------------------------------------------------------------------
__global__ void split_hi(const float* __restrict__ src, long n, __half* __restrict__ hi)
{
    for (long i = blockIdx.x * (long)blockDim.x + threadIdx.x; i < n / 4;
         i += (long)gridDim.x * blockDim.x) {
        long e = i * 4;
        float4 v = *(const float4*)(src + e);
        __half2 a, b;
        a.x = __float2half_rn(v.x); a.y = __float2half_rn(v.y);
        b.x = __float2half_rn(v.z); b.y = __float2half_rn(v.w);
        *(__half2*)(hi + e)     = a;
        *(__half2*)(hi + e + 2) = b;
    }
}

// Fused parameter conversion: W_ih + W_ho + h0, hi-only, one launch
__global__ void split_params(const float* __restrict__ W_ih,
                             const float* __restrict__ W_ho,
                             const float* __restrict__ h0)
{
    const long n1 = (long)HIDDEN * WROW / 4;
    const long n2 = (long)NCLS * HIDDEN / 4;
    const long n3 = (long)BH / 4;
    for (long i = blockIdx.x * (long)blockDim.x + threadIdx.x; i < n1 + n2 + n3;
         i += (long)gridDim.x * blockDim.x) {
        const float* s; __half* hi; long e;
        if (i < n1)           { s = W_ih; hi = g_Wih_h; e = i * 4; }
        else if (i < n1 + n2) { s = W_ho; hi = g_Who_h; e = (i - n1) * 4; }
        else                  { s = h0;   hi = g_h0h;   e = (i - n1 - n2) * 4; }
        float4 v = *(const float4*)(s + e);
        __half2 a, b;
        a.x = __float2half_rn(v.x); a.y = __float2half_rn(v.y);
        b.x = __float2half_rn(v.z); b.y = __float2half_rn(v.w);
        *(__half2*)(hi + e)     = a;
        *(__half2*)(hi + e + 2) = b;
    }
}

// ---------------------------------------------------------------------------
// mma.sync pure-fp16 GEMM (phases 1 & 3):
//   C[m,n] = sum_k A[m,k] * B[n,k] + bias[n]
// CTA tile 128x128, BK=64, 8 warps (4M x 2N), 2-stage cp.async,
// 1 sync/chunk, x4-B ldmatrix.
// ---------------------------------------------------------------------------
#define GROWB  144                   // 128B data + 16 pad
#define G_MAT  (128 * GROWB)         // 18432
#define G_STG  (2 * G_MAT)           // A | B = 36864
#define G_SMEM (2 * G_STG)           // 73728

__global__ void __launch_bounds__(256, 1)
gemm_f16(const __half* __restrict__ A, long lda,
         const __half* __restrict__ B, long ldb,
         const float* __restrict__ bias, float* __restrict__ C, long ldc, int K)
{
    extern __shared__ char smem[];
    const uint32_t sb = smem_to_u32(smem);
    const int tid = threadIdx.x, lane = tid & 31, wid = tid >> 5;
    const int wm = wid & 3, wn = wid >> 2;
    const long bm = (long)blockIdx.y * 128;
    const long bn = (long)blockIdx.x * 128;

    float c[2][8][4];
#pragma unroll
    for (int m = 0; m < 2; m++)
#pragma unroll
        for (int n = 0; n < 8; n++)
#pragma unroll
            for (int j = 0; j < 4; j++) c[m][n][j] = 0.0f;

    const uint32_t a_rb  = (uint32_t)(lane & 15) * GROWB + (uint32_t)(lane >> 4) * 16;
    const uint32_t b4_rb = (uint32_t)((lane & 7) + ((lane >> 4) << 3)) * GROWB
                           + (uint32_t)((lane >> 3) & 1) * 16;

    // Per chunk: each matrix = 128 rows x 8 segs(16B) = 1024 units -> 4/thread
    auto load_chunk = [&](int kc, int stage) {
        uint32_t base = sb + stage * G_STG;
#pragma unroll
        for (int it = 0; it < 4; it++) {
            int u = tid + it * 256;
            int row = u >> 3, seg = u & 7;
            uint32_t so = row * GROWB + seg * 16;
            cp16(base + so,         A + (bm + row) * lda + kc + seg * 8);
            cp16(base + G_MAT + so, B + (bn + row) * ldb + kc + seg * 8);
        }
    };

    const int nchunk = K >> 6;      // BK = 64
    load_chunk(0, 0);
    CP_COMMIT();

    for (int ch = 0; ch < nchunk; ch++) {
        CP_WAIT(0);
        __syncthreads();
        if (ch + 1 < nchunk) {
            load_chunk((ch + 1) << 6, (ch + 1) & 1);
            CP_COMMIT();
        }

        const uint32_t base = sb + (ch & 1) * G_STG;
#pragma unroll
        for (int k16 = 0; k16 < 4; k16++) {
            const uint32_t kb = k16 * 32;
            uint32_t ah[2][4], bh[8][2];
#pragma unroll
            for (int m = 0; m < 2; m++) {
                uint32_t ra = base + (uint32_t)(wm * 32 + m * 16) * GROWB + kb + a_rb;
                LDSM4(ah[m][0], ah[m][1], ah[m][2], ah[m][3], ra);
            }
#pragma unroll
            for (int p = 0; p < 4; p++) {
                uint32_t rb = base + G_MAT + (uint32_t)(wn * 64 + p * 16) * GROWB + kb + b4_rb;
                LDSM4(bh[2*p][0], bh[2*p][1], bh[2*p+1][0], bh[2*p+1][1], rb);
            }
#pragma unroll
            for (int m = 0; m < 2; m++)
#pragma unroll
                for (int n = 0; n < 8; n++)
                    mma_f16(c[m][n], ah[m], bh[n]);
        }
    }

#pragma unroll
    for (int m = 0; m < 2; m++) {
        long r0 = bm + wm * 32 + m * 16 + (lane >> 2);
        long r1 = r0 + 8;
#pragma unroll
        for (int n = 0; n < 8; n++) {
            long col = bn + wn * 64 + n * 8 + (lane & 3) * 2;
            float bx = bias[col], by = bias[col + 1];
            float2 v0 = { c[m][n][0] + bx, c[m][n][1] + by };
            float2 v1 = { c[m][n][2] + bx, c[m][n][3] + by };
            *(float2*)(C + r0 * ldc + col) = v0;
            *(float2*)(C + r1 * ldc + col) = v1;
        }
    }
}

// ---------------------------------------------------------------------------
// Per-group barrier (16 CTAs); groups fully decoupled closed systems.
// ---------------------------------------------------------------------------
__device__ __forceinline__ void group_bar(int g, unsigned& lgen)
{
    __syncthreads();
    if (threadIdx.x == 0) {
        __threadfence();
        if (atomicAdd(&g_gcnt[g * 32], 1u) == GRP_CTAS - 1) {
            atomicExch(&g_gcnt[g * 32], 0u);
            __threadfence();
            atomicAdd(&g_ggen[g * 32], 1u);
        } else {
            while (*(volatile unsigned*)&g_ggen[g * 32] == lgen) { __nanosleep(32); }
            __threadfence();
        }
        lgen++;
    }
    __syncthreads();
}

// ---------------------------------------------------------------------------
// Persistent recurrence (fp16 x1, W resident) -- unchanged from R12 WIN:
//   h_t = tanh(g_A[t] + h_{t-1} @ W_h^T)
// 128 CTAs = 8 groups x 16; CTA tile 32(batch) x 64(hidden); warps 2M x 4N.
// Streams ONLY A hi per BK=128 chunk (8 KB), double-buffered; 8 syncs/step.
// ---------------------------------------------------------------------------
#define A_RB      272                        // 256B data + 16 pad (streamed A)
#define RB_ROWB   2064                       // 2048B data + 16 pad (resident W)
#define RBH_SZ    (64 * RB_ROWB)             // 132096
#define RA_SZ     (32 * A_RB)                // 8704 per stage
#define R2_SMEM   (RBH_SZ + 2 * RA_SZ)       // 149504

__global__ void __launch_bounds__(256, 1)
rnn_recur()
{
    extern __shared__ char smem[];
    const uint32_t sb = smem_to_u32(smem);
    const int tid = threadIdx.x, lane = tid & 31, wid = tid >> 5;
    const int wm = wid & 1, wn = wid >> 1;       // 2 x 4 warp grid
    const int grp = blockIdx.x >> 4;             // group (0..7)
    const int bm  = grp * 32;                    // batch rows [bm, bm+32)
    const int bn  = (blockIdx.x & 15) * 64;      // hidden cols [bn, bn+64)

    const uint32_t a_rb   = (uint32_t)(lane & 15) * A_RB + (uint32_t)(lane >> 4) * 16;
    const uint32_t b4h_rb = (uint32_t)((lane & 7) + ((lane >> 4) << 3)) * RB_ROWB
                            + (uint32_t)((lane >> 3) & 1) * 16;

    // ---- Resident W_h hi tile: 64 rows x 1024 fp16 (8192 x 16B units)
    for (int u = tid; u < 8192; u += 256) {
        int row = u >> 7, seg = u & 127;
        cp16(sb + row * RB_ROWB + seg * 16,
             g_Wih_h + (size_t)(bn + row) * WROW + INF + seg * 8);
    }
    CP_COMMIT();

    unsigned lgen = *(volatile unsigned*)&g_ggen[grp * 32];

    for (int t = 0; t < T_STEPS; t++) {
        const __half* hh = (t == 0) ? g_h0h : (g_Hh + (size_t)(t - 1) * BH);
        const size_t ob = (size_t)t * BH;

        float c[2][4];
#pragma unroll
        for (int n = 0; n < 2; n++)
#pragma unroll
            for (int j = 0; j < 4; j++) c[n][j] = 0.0f;

        // Stream A hi chunk: 32 rows x 128 cols fp16 = 512 x 16B units (2/thread)
        auto load_chunk = [&](int kc, int stage) {
            uint32_t base = sb + RBH_SZ + stage * RA_SZ;
#pragma unroll
            for (int it = 0; it < 2; it++) {
                int u = tid + it * 256;
                int row = u >> 4, seg = u & 15;
                cp16(base + row * A_RB + seg * 16,
                     hh + (size_t)(bm + row) * HIDDEN + kc + seg * 8);
            }
        };

        load_chunk(0, 0);
        CP_COMMIT();

        for (int ch = 0; ch < HIDDEN / 128; ch++) {    // 8 chunks (BK=128)
            CP_WAIT(0);
            __syncthreads();       // chunk ch visible; all warps done with ch-1
            if (ch + 1 < HIDDEN / 128) {
                load_chunk((ch + 1) << 7, (ch + 1) & 1);
                CP_COMMIT();
            }

            const uint32_t abase = sb + RBH_SZ + (ch & 1) * RA_SZ
                                   + (uint32_t)(wm * 16) * A_RB + a_rb;
            const uint32_t bhb   = sb + (uint32_t)(wn * 16) * RB_ROWB
                                   + (uint32_t)(ch << 8) + b4h_rb;

            // Fragment-pipelined k16 loop (8 iters, double-buffered)
            uint32_t ah[2][4], bh[2][2][2];

#define R_LD(k16, buf) do { \
        LDSM4(ah[buf][0], ah[buf][1], ah[buf][2], ah[buf][3], \
              abase + (uint32_t)((k16) * 32)); \
        LDSM4(bh[buf][0][0], bh[buf][0][1], bh[buf][1][0], bh[buf][1][1], \
              bhb + (uint32_t)((k16) * 32)); \
    } while (0)

            R_LD(0, 0);
#pragma unroll
            for (int k16 = 0; k16 < 8; k16++) {
                if (k16 < 7) R_LD(k16 + 1, (k16 + 1) & 1);
                const int b = k16 & 1;
#pragma unroll
                for (int n = 0; n < 2; n++)
                    mma_f16(c[n], ah[b], bh[b][n]);
            }
#undef R_LD
        }

        // Epilogue: tanh(acc + pre), store fp16 hi
        {
            const int r0 = bm + wm * 16 + (lane >> 2);
            const int r1 = r0 + 8;
#pragma unroll
            for (int n = 0; n < 2; n++) {
                const int col = bn + wn * 16 + n * 8 + (lane & 3) * 2;
                float2 p0 = *(const float2*)(g_A + ob + (size_t)r0 * HIDDEN + col);
                float2 p1 = *(const float2*)(g_A + ob + (size_t)r1 * HIDDEN + col);
                float h00 = tanhf(c[n][0] + p0.x);
                float h01 = tanhf(c[n][1] + p0.y);
                float h10 = tanhf(c[n][2] + p1.x);
                float h11 = tanhf(c[n][3] + p1.y);

                __half2 th;
                th.x = __float2half_rn(h00); th.y = __float2half_rn(h01);
                *(__half2*)(g_Hh + ob + (size_t)r0 * HIDDEN + col) = th;
                th.x = __float2half_rn(h10); th.y = __float2half_rn(h11);
                *(__half2*)(g_Hh + ob + (size_t)r1 * HIDDEN + col) = th;

                if (t == T_STEPS - 1) {
                    float2 f0 = { h00, h01 }, f1 = { h10, h11 };
                    *(float2*)(g_Hlast + (size_t)r0 * HIDDEN + col) = f0;
                    *(float2*)(g_Hlast + (size_t)r1 * HIDDEN + col) = f1;
                }
            }
        }

        group_bar(grp, lgen);   // 16-CTA rendezvous; groups fully decoupled
    }
}

// ---------------------------------------------------------------------------
// In-place softmax over rows of 512 floats
// ---------------------------------------------------------------------------
__global__ void softmax512(float* __restrict__ O)
{
    __shared__ float red[4];
    long row = blockIdx.x;
    float4* p = (float4*)(O + row * (long)NCLS);
    float4 v = p[threadIdx.x];

    float m = fmaxf(fmaxf(v.x, v.y), fmaxf(v.z, v.w));
#pragma unroll
    for (int o = 16; o > 0; o >>= 1)
        m = fmaxf(m, __shfl_xor_sync(0xffffffffu, m, o));
    int warp = threadIdx.x >> 5;
    if ((threadIdx.x & 31) == 0) red[warp] = m;
    __syncthreads();
    m = fmaxf(fmaxf(red[0], red[1]), fmaxf(red[2], red[3]));

    float4 e;
    e.x = __expf(v.x - m);
    e.y = __expf(v.y - m);
    e.z = __expf(v.z - m);
    e.w = __expf(v.w - m);
    float s = e.x + e.y + e.z + e.w;
#pragma unroll
    for (int o = 16; o > 0; o >>= 1)
        s += __shfl_xor_sync(0xffffffffu, s, o);
    __syncthreads();
    if ((threadIdx.x & 31) == 0) red[warp] = s;
    __syncthreads();
    s = red[0] + red[1] + red[2] + red[3];

    float inv = 1.0f / s;
    e.x *= inv; e.y *= inv; e.z *= inv; e.w *= inv;
    p[threadIdx.x] = e;
}

// ---------------------------------------------------------------------------
// Launch (7 graph nodes)
// ---------------------------------------------------------------------------
extern "C" void kernel_launch(void* const* d_in, const int* in_sizes, int n_in,
                              void* d_out, int out_size)
{
    const float* x    = (const float*)d_in[0];
    const float* h0   = (const float*)d_in[1];
    const float* W_ih = (const float*)d_in[2];
    const float* b_ih = (const float*)d_in[3];
    const float* W_ho = (const float*)d_in[4];
    const float* b_ho = (const float*)d_in[5];
    float*       out  = (float*)d_out;

    float *pA, *pHlast;
    __half *pXh, *pHh, *pWih_h, *pWoh;
    cudaGetSymbolAddress((void**)&pA,     g_A);
    cudaGetSymbolAddress((void**)&pHlast, g_Hlast);
    cudaGetSymbolAddress((void**)&pXh,    g_Xh);
    cudaGetSymbolAddress((void**)&pHh,    g_Hh);
    cudaGetSymbolAddress((void**)&pWih_h, g_Wih_h);
    cudaGetSymbolAddress((void**)&pWoh,   g_Who_h);

    cudaFuncSetAttribute(gemm_f16,
                         cudaFuncAttributeMaxDynamicSharedMemorySize, G_SMEM);
    cudaFuncSetAttribute(rnn_recur,
                         cudaFuncAttributeMaxDynamicSharedMemorySize, R2_SMEM);

    // #1: X hi conversion; #2: fused param conversions (hi only)
    split_hi<<<4096, 256>>>(x, (long)TB * INF, pXh);
    split_params<<<1024, 256>>>(W_ih, W_ho, h0);

    // #3: Phase 1 -- g_A = Xh @ Wx_h^T + b_ih   (pure fp16)
    {
        dim3 grid(HIDDEN / 128, TB / 128);   // (8, 1024)
        gemm_f16<<<grid, 256, G_SMEM>>>(pXh, INF, pWih_h, WROW,
                                        b_ih, pA, HIDDEN, INF);
    }

    // #4: Phase 2 -- persistent recurrence (fp16 x1, W resident, 8 groups)
    rnn_recur<<<NCTAS, 256, R2_SMEM>>>();

    // #5/#6: Phase 3 -- out = Hh @ Who_h^T + b_ho (pure fp16), softmax
    {
        dim3 grid(NCLS / 128, TB / 128);     // (4, 1024)
        gemm_f16<<<grid, 256, G_SMEM>>>(pHh, HIDDEN, pWoh, HIDDEN,
                                        b_ho, out, NCLS, HIDDEN);
        softmax512<<<TB, 128>>>(out);
    }

    // #7: h_last
    cudaMemcpyAsync(out + (long)TB * NCLS, pHlast,
                    (size_t)BH * sizeof(float), cudaMemcpyDeviceToDevice);
}

// round 14
// speedup vs baseline: 3.0910x; 1.1191x over previous
#include <cuda_runtime.h>
#include <cuda_fp16.h>
#include <math.h>
#include <stdint.h>

// ---------------------------------------------------------------------------
// Problem constants
// ---------------------------------------------------------------------------
#define T_STEPS 512
#define BATCH   256
#define INF     1024
#define HIDDEN  1024
#define WROW    (INF + HIDDEN)
#define NCLS    512
#define BH      (BATCH * HIDDEN)      // 262144
#define TB      (T_STEPS * BATCH)     // 131072
#define NCTAS   128                   // persistent recurrence grid
#define NGRP    8                     // independent recurrence groups
#define GRP_CTAS 16                   // CTAs per group

// ---------------------------------------------------------------------------
// Device-global scratch (allocation-free rule)
// ---------------------------------------------------------------------------
__device__ float g_A[(size_t)T_STEPS * BH];       // x-projection + b_ih (fp32)
__device__ float g_Hlast[BH];                      // final hidden state (fp32)
__device__ __half g_Xh[(size_t)TB * INF];         // X hi (fp16)
__device__ __half g_Hh[(size_t)T_STEPS * BH];     // H hi (fp16)
__device__ __half g_Wih_h[HIDDEN * WROW];         // W_ih hi (row stride WROW)
__device__ __half g_Who_h[NCLS * HIDDEN];         // W_ho hi
__device__ __half g_h0h[BH];                      // h0 hi
// Per-group barrier state, line-padded; gens monotonic across graph replays.
__device__ unsigned g_gcnt[NGRP * 32];
__device__ unsigned g_ggen[NGRP * 32];

// ---------------------------------------------------------------------------
// Portable PTX helpers (sm_80+ features only)
// ---------------------------------------------------------------------------
__device__ __forceinline__ uint32_t smem_to_u32(const void* p) {
    uint32_t a;
    asm("{ .reg .u64 t; cvta.to.shared.u64 t, %1; cvt.u32.u64 %0, t; }"
        : "=r"(a) : "l"(p));
    return a;
}

__device__ __forceinline__ void cp16(uint32_t dst, const void* src) {
    asm volatile("cp.async.cg.shared.global [%0], [%1], 16;"
                 :: "r"(dst), "l"(__cvta_generic_to_global(src)));
}
#define CP_COMMIT()  asm volatile("cp.async.commit_group;" ::: "memory")
#define CP_WAIT(n)   asm volatile("cp.async.wait_group %0;" :: "n"(n) : "memory")

#define LDSM4(r0, r1, r2, r3, addr) \
    asm volatile("ldmatrix.sync.aligned.m8n8.x4.shared.b16 {%0,%1,%2,%3}, [%4];" \
                 : "=r"(r0), "=r"(r1), "=r"(r2), "=r"(r3) : "r"(addr))

// D[16x8] += A[16x16] * B[16x8]^(col)  -- fp16 in, fp32 accum
__device__ __forceinline__ void mma_f16(float* c, const uint32_t* a, const uint32_t* b) {
    asm volatile(
        "mma.sync.aligned.m16n8k16.row.col.f32.f16.f16.f32 "
        "{%0,%1,%2,%3}, {%4,%5,%6,%7}, {%8,%9}, {%0,%1,%2,%3};"
        : "+f"(c[0]), "+f"(c[1]), "+f"(c[2]), "+f"(c[3])
        : "r"(a[0]), "r"(a[1]), "r"(a[2]), "r"(a[3]), "r"(b[0]), "r"(b[1]));
}

// ---------------------------------------------------------------------------
// hi-only fp16 conversion (X)
// ---------------------------------------------------------------------------
__global__ void split_hi(const float* __restrict__ src, long n, __half* __restrict__ hi)
{
    for (long i = blockIdx.x * (long)blockDim.x + threadIdx.x; i < n / 4;
         i += (long)gridDim.x * blockDim.x) {
        long e = i * 4;
        float4 v = *(const float4*)(src + e);
        __half2 a, b;
        a.x = __float2half_rn(v.x); a.y = __float2half_rn(v.y);
        b.x = __float2half_rn(v.z); b.y = __float2half_rn(v.w);
        *(__half2*)(hi + e)     = a;
        *(__half2*)(hi + e + 2) = b;
    }
}

// Fused parameter conversion: W_ih + W_ho + h0, hi-only, one launch
__global__ void split_params(const float* __restrict__ W_ih,
                             const float* __restrict__ W_ho,
                             const float* __restrict__ h0)
{
    const long n1 = (long)HIDDEN * WROW / 4;
    const long n2 = (long)NCLS * HIDDEN / 4;
    const long n3 = (long)BH / 4;
    for (long i = blockIdx.x * (long)blockDim.x + threadIdx.x; i < n1 + n2 + n3;
         i += (long)gridDim.x * blockDim.x) {
        const float* s; __half* hi; long e;
        if (i < n1)           { s = W_ih; hi = g_Wih_h; e = i * 4; }
        else if (i < n1 + n2) { s = W_ho; hi = g_Who_h; e = (i - n1) * 4; }
        else                  { s = h0;   hi = g_h0h;   e = (i - n1 - n2) * 4; }
        float4 v = *(const float4*)(s + e);
        __half2 a, b;
        a.x = __float2half_rn(v.x); a.y = __float2half_rn(v.y);
        b.x = __float2half_rn(v.z); b.y = __float2half_rn(v.w);
        *(__half2*)(hi + e)     = a;
        *(__half2*)(hi + e + 2) = b;
    }
}

// ---------------------------------------------------------------------------
// mma.sync pure-fp16 GEMM (phases 1 & 3) -- unchanged from R13 (at ceiling)
// ---------------------------------------------------------------------------
#define GROWB  144                   // 128B data + 16 pad
#define G_MAT  (128 * GROWB)         // 18432
#define G_STG  (2 * G_MAT)           // A | B = 36864
#define G_SMEM (2 * G_STG)           // 73728

__global__ void __launch_bounds__(256, 1)
gemm_f16(const __half* __restrict__ A, long lda,
         const __half* __restrict__ B, long ldb,
         const float* __restrict__ bias, float* __restrict__ C, long ldc, int K)
{
    extern __shared__ char smem[];
    const uint32_t sb = smem_to_u32(smem);
    const int tid = threadIdx.x, lane = tid & 31, wid = tid >> 5;
    const int wm = wid & 3, wn = wid >> 2;
    const long bm = (long)blockIdx.y * 128;
    const long bn = (long)blockIdx.x * 128;

    float c[2][8][4];
#pragma unroll
    for (int m = 0; m < 2; m++)
#pragma unroll
        for (int n = 0; n < 8; n++)
#pragma unroll
            for (int j = 0; j < 4; j++) c[m][n][j] = 0.0f;

    const uint32_t a_rb  = (uint32_t)(lane & 15) * GROWB + (uint32_t)(lane >> 4) * 16;
    const uint32_t b4_rb = (uint32_t)((lane & 7) + ((lane >> 4) << 3)) * GROWB
                           + (uint32_t)((lane >> 3) & 1) * 16;

    auto load_chunk = [&](int kc, int stage) {
        uint32_t base = sb + stage * G_STG;
#pragma unroll
        for (int it = 0; it < 4; it++) {
            int u = tid + it * 256;
            int row = u >> 3, seg = u & 7;
            uint32_t so = row * GROWB + seg * 16;
            cp16(base + so,         A + (bm + row) * lda + kc + seg * 8);
            cp16(base + G_MAT + so, B + (bn + row) * ldb + kc + seg * 8);
        }
    };

    const int nchunk = K >> 6;      // BK = 64
    load_chunk(0, 0);
    CP_COMMIT();

    for (int ch = 0; ch < nchunk; ch++) {
        CP_WAIT(0);
        __syncthreads();
        if (ch + 1 < nchunk) {
            load_chunk((ch + 1) << 6, (ch + 1) & 1);
            CP_COMMIT();
        }

        const uint32_t base = sb + (ch & 1) * G_STG;
#pragma unroll
        for (int k16 = 0; k16 < 4; k16++) {
            const uint32_t kb = k16 * 32;
            uint32_t ah[2][4], bh[8][2];
#pragma unroll
            for (int m = 0; m < 2; m++) {
                uint32_t ra = base + (uint32_t)(wm * 32 + m * 16) * GROWB + kb + a_rb;
                LDSM4(ah[m][0], ah[m][1], ah[m][2], ah[m][3], ra);
            }
#pragma unroll
            for (int p = 0; p < 4; p++) {
                uint32_t rb = base + G_MAT + (uint32_t)(wn * 64 + p * 16) * GROWB + kb + b4_rb;
                LDSM4(bh[2*p][0], bh[2*p][1], bh[2*p+1][0], bh[2*p+1][1], rb);
            }
#pragma unroll
            for (int m = 0; m < 2; m++)
#pragma unroll
                for (int n = 0; n < 8; n++)
                    mma_f16(c[m][n], ah[m], bh[n]);
        }
    }

#pragma unroll
    for (int m = 0; m < 2; m++) {
        long r0 = bm + wm * 32 + m * 16 + (lane >> 2);
        long r1 = r0 + 8;
#pragma unroll
        for (int n = 0; n < 8; n++) {
            long col = bn + wn * 64 + n * 8 + (lane & 3) * 2;
            float bx = bias[col], by = bias[col + 1];
            float2 v0 = { c[m][n][0] + bx, c[m][n][1] + by };
            float2 v1 = { c[m][n][2] + bx, c[m][n][3] + by };
            *(float2*)(C + r0 * ldc + col) = v0;
            *(float2*)(C + r1 * ldc + col) = v1;
        }
    }
}

// ---------------------------------------------------------------------------
// Per-group barrier (16 CTAs); groups fully decoupled closed systems.
// ---------------------------------------------------------------------------
__device__ __forceinline__ void group_bar(int g, unsigned& lgen)
{
    __syncthreads();
    if (threadIdx.x == 0) {
        __threadfence();
        if (atomicAdd(&g_gcnt[g * 32], 1u) == GRP_CTAS - 1) {
            atomicExch(&g_gcnt[g * 32], 0u);
            __threadfence();
            atomicAdd(&g_ggen[g * 32], 1u);
        } else {
            while (*(volatile unsigned*)&g_ggen[g * 32] == lgen) { __nanosleep(16); }
            __threadfence();
        }
        lgen++;
    }
    __syncthreads();
}

// ---------------------------------------------------------------------------
// Persistent recurrence (fp16 x1, W resident, 4-deep h pipeline, rotation):
//   h_t = tanh(g_A[t] + h_{t-1} @ W_h^T)
// 128 CTAs = 8 groups x 16; CTA tile 32(batch) x 64(hidden); warps 2M x 4N.
// Streams ONLY A hi per BK=128 chunk (8 KB) into a 4-stage ring; chunks are
// consumed in rotated order (own columns first -> L2-hot after barrier);
// g_A pre-activations for step t+1 prefetched before the barrier.
// ---------------------------------------------------------------------------
#define A_RB      272                        // 256B data + 16 pad (streamed A)
#define RB_ROWB   2064                       // 2048B data + 16 pad (resident W)
#define RBH_SZ    (64 * RB_ROWB)             // 132096
#define RA_SZ     (32 * A_RB)                // 8704 per stage
#define R_STAGES  4
#define R2_SMEM   (RBH_SZ + R_STAGES * RA_SZ)  // 166912

__global__ void __launch_bounds__(256, 1)
rnn_recur()
{
    extern __shared__ char smem[];
    const uint32_t sb = smem_to_u32(smem);
    const int tid = threadIdx.x, lane = tid & 31, wid = tid >> 5;
    const int wm = wid & 1, wn = wid >> 1;       // 2 x 4 warp grid
    const int grp = blockIdx.x >> 4;             // group (0..7)
    const int gn  = blockIdx.x & 15;             // n tile within group
    const int bm  = grp * 32;                    // batch rows [bm, bm+32)
    const int bn  = gn * 64;                     // hidden cols [bn, bn+64)
    const int start = gn >> 1;                   // rotation: own-column chunk first

    const uint32_t a_rb   = (uint32_t)(lane & 15) * A_RB + (uint32_t)(lane >> 4) * 16;
    const uint32_t b4h_rb = (uint32_t)((lane & 7) + ((lane >> 4) << 3)) * RB_ROWB
                            + (uint32_t)((lane >> 3) & 1) * 16;

    // ---- Resident W_h hi tile: 64 rows x 1024 fp16 (8192 x 16B units)
    for (int u = tid; u < 8192; u += 256) {
        int row = u >> 7, seg = u & 127;
        cp16(sb + row * RB_ROWB + seg * 16,
             g_Wih_h + (size_t)(bn + row) * WROW + INF + seg * 8);
    }
    CP_COMMIT();

    unsigned lgen = *(volatile unsigned*)&g_ggen[grp * 32];

    // Epilogue coordinates + first-step pre-activation prefetch
    const int er0 = bm + wm * 16 + (lane >> 2);
    const int ec0 = bn + wn * 16 + (lane & 3) * 2;
    float2 pre[2][2];
#pragma unroll
    for (int n = 0; n < 2; n++) {
        pre[n][0] = *(const float2*)(g_A + (size_t)er0       * HIDDEN + ec0 + n * 8);
        pre[n][1] = *(const float2*)(g_A + (size_t)(er0 + 8) * HIDDEN + ec0 + n * 8);
    }

    for (int t = 0; t < T_STEPS; t++) {
        const __half* hh = (t == 0) ? g_h0h : (g_Hh + (size_t)(t - 1) * BH);
        const size_t ob = (size_t)t * BH;

        float c[2][4];
#pragma unroll
        for (int n = 0; n < 2; n++)
#pragma unroll
            for (int j = 0; j < 4; j++) c[n][j] = 0.0f;

        // Stream A hi chunk cc (BK=128): 512 x 16B units (2/thread)
        auto load_chunk = [&](int cc, int stage) {
            uint32_t base = sb + RBH_SZ + stage * RA_SZ;
            const int kc = cc << 7;
#pragma unroll
            for (int it = 0; it < 2; it++) {
                int u = tid + it * 256;
                int row = u >> 4, seg = u & 15;
                cp16(base + row * A_RB + seg * 16,
                     hh + (size_t)(bm + row) * HIDDEN + kc + seg * 8);
            }
        };

        // Prologue: fill 3 stages
#pragma unroll
        for (int i = 0; i < 3; i++) {
            load_chunk((start + i) & 7, i);
            CP_COMMIT();
        }

#pragma unroll
        for (int i = 0; i < 8; i++) {
            const int cc = (start + i) & 7;
            // Wait until chunk i has landed (groups complete FIFO)
            if (i <= 5)      CP_WAIT(2);
            else if (i == 6) CP_WAIT(1);
            else             CP_WAIT(0);
            __syncthreads();       // all warps done with chunk i-1 (stage reuse)
            if (i < 5) {
                load_chunk((start + i + 3) & 7, (i + 3) & 3);
                CP_COMMIT();
            }

            const uint32_t abase = sb + RBH_SZ + (i & 3) * RA_SZ
                                   + (uint32_t)(wm * 16) * A_RB + a_rb;
            const uint32_t bhb   = sb + (uint32_t)(wn * 16) * RB_ROWB
                                   + (uint32_t)(cc << 8) + b4h_rb;

            // Fragment-pipelined k16 loop (8 iters, double-buffered)
            uint32_t ah[2][4], bh[2][2][2];

#define R_LD(k16, buf) do { \
        LDSM4(ah[buf][0], ah[buf][1], ah[buf][2], ah[buf][3], \
              abase + (uint32_t)((k16) * 32)); \
        LDSM4(bh[buf][0][0], bh[buf][0][1], bh[buf][1][0], bh[buf][1][1], \
              bhb + (uint32_t)((k16) * 32)); \
    } while (0)

            R_LD(0, 0);
#pragma unroll
            for (int k16 = 0; k16 < 8; k16++) {
                if (k16 < 7) R_LD(k16 + 1, (k16 + 1) & 1);
                const int b = k16 & 1;
#pragma unroll
                for (int n = 0; n < 2; n++)
                    mma_f16(c[n], ah[b], bh[b][n]);
            }
#undef R_LD
        }

        // Epilogue: tanh(acc + pre), store fp16 hi
        {
            const int r0 = er0, r1 = er0 + 8;
#pragma unroll
            for (int n = 0; n < 2; n++) {
                const int col = ec0 + n * 8;
                float h00 = tanhf(c[n][0] + pre[n][0].x);
                float h01 = tanhf(c[n][1] + pre[n][0].y);
                float h10 = tanhf(c[n][2] + pre[n][1].x);
                float h11 = tanhf(c[n][3] + pre[n][1].y);

                __half2 th;
                th.x = __float2half_rn(h00); th.y = __float2half_rn(h01);
                *(__half2*)(g_Hh + ob + (size_t)r0 * HIDDEN + col) = th;
                th.x = __float2half_rn(h10); th.y = __float2half_rn(h11);
                *(__half2*)(g_Hh + ob + (size_t)r1 * HIDDEN + col) = th;

                if (t == T_STEPS - 1) {
                    float2 f0 = { h00, h01 }, f1 = { h10, h11 };
                    *(float2*)(g_Hlast + (size_t)r0 * HIDDEN + col) = f0;
                    *(float2*)(g_Hlast + (size_t)r1 * HIDDEN + col) = f1;
                }
            }
        }

        // Prefetch next step's pre-activations BEFORE the barrier (independent
        // of h_t -- hides the gmem latency behind the rendezvous wait).
        if (t + 1 < T_STEPS) {
            const size_t ob1 = (size_t)(t + 1) * BH;
#pragma unroll
            for (int n = 0; n < 2; n++) {
                pre[n][0] = *(const float2*)(g_A + ob1 + (size_t)er0       * HIDDEN + ec0 + n * 8);
                pre[n][1] = *(const float2*)(g_A + ob1 + (size_t)(er0 + 8) * HIDDEN + ec0 + n * 8);
            }
        }

        group_bar(grp, lgen);   // 16-CTA rendezvous; groups fully decoupled
    }
}

// ---------------------------------------------------------------------------
// In-place softmax over rows of 512 floats
// ---------------------------------------------------------------------------
__global__ void softmax512(float* __restrict__ O)
{
    __shared__ float red[4];
    long row = blockIdx.x;
    float4* p = (float4*)(O + row * (long)NCLS);
    float4 v = p[threadIdx.x];

    float m = fmaxf(fmaxf(v.x, v.y), fmaxf(v.z, v.w));
#pragma unroll
    for (int o = 16; o > 0; o >>= 1)
        m = fmaxf(m, __shfl_xor_sync(0xffffffffu, m, o));
    int warp = threadIdx.x >> 5;
    if ((threadIdx.x & 31) == 0) red[warp] = m;
    __syncthreads();
    m = fmaxf(fmaxf(red[0], red[1]), fmaxf(red[2], red[3]));

    float4 e;
    e.x = __expf(v.x - m);
    e.y = __expf(v.y - m);
    e.z = __expf(v.z - m);
    e.w = __expf(v.w - m);
    float s = e.x + e.y + e.z + e.w;
#pragma unroll
    for (int o = 16; o > 0; o >>= 1)
        s += __shfl_xor_sync(0xffffffffu, s, o);
    __syncthreads();
    if ((threadIdx.x & 31) == 0) red[warp] = s;
    __syncthreads();
    s = red[0] + red[1] + red[2] + red[3];

    float inv = 1.0f / s;
    e.x *= inv; e.y *= inv; e.z *= inv; e.w *= inv;
    p[threadIdx.x] = e;
}

// ---------------------------------------------------------------------------
// Launch (7 graph nodes)
// ---------------------------------------------------------------------------
extern "C" void kernel_launch(void* const* d_in, const int* in_sizes, int n_in,
                              void* d_out, int out_size)
{
    const float* x    = (const float*)d_in[0];
    const float* h0   = (const float*)d_in[1];
    const float* W_ih = (const float*)d_in[2];
    const float* b_ih = (const float*)d_in[3];
    const float* W_ho = (const float*)d_in[4];
    const float* b_ho = (const float*)d_in[5];
    float*       out  = (float*)d_out;

    float *pA, *pHlast;
    __half *pXh, *pHh, *pWih_h, *pWoh;
    cudaGetSymbolAddress((void**)&pA,     g_A);
    cudaGetSymbolAddress((void**)&pHlast, g_Hlast);
    cudaGetSymbolAddress((void**)&pXh,    g_Xh);
    cudaGetSymbolAddress((void**)&pHh,    g_Hh);
    cudaGetSymbolAddress((void**)&pWih_h, g_Wih_h);
    cudaGetSymbolAddress((void**)&pWoh,   g_Who_h);

    cudaFuncSetAttribute(gemm_f16,
                         cudaFuncAttributeMaxDynamicSharedMemorySize, G_SMEM);
    cudaFuncSetAttribute(rnn_recur,
                         cudaFuncAttributeMaxDynamicSharedMemorySize, R2_SMEM);

    // #1: X hi conversion; #2: fused param conversions (hi only)
    split_hi<<<4096, 256>>>(x, (long)TB * INF, pXh);
    split_params<<<1024, 256>>>(W_ih, W_ho, h0);

    // #3: Phase 1 -- g_A = Xh @ Wx_h^T + b_ih   (pure fp16)
    {
        dim3 grid(HIDDEN / 128, TB / 128);   // (8, 1024)
        gemm_f16<<<grid, 256, G_SMEM>>>(pXh, INF, pWih_h, WROW,
                                        b_ih, pA, HIDDEN, INF);
    }

    // #4: Phase 2 -- persistent recurrence (fp16 x1, 4-stage pipe, rotation)
    rnn_recur<<<NCTAS, 256, R2_SMEM>>>();

    // #5/#6: Phase 3 -- out = Hh @ Who_h^T + b_ho (pure fp16), softmax
    {
        dim3 grid(NCLS / 128, TB / 128);     // (4, 1024)
        gemm_f16<<<grid, 256, G_SMEM>>>(pHh, HIDDEN, pWoh, HIDDEN,
                                        b_ho, out, NCLS, HIDDEN);
        softmax512<<<TB, 128>>>(out);
    }

    // #7: h_last
    cudaMemcpyAsync(out + (long)TB * NCLS, pHlast,
                    (size_t)BH * sizeof(float), cudaMemcpyDeviceToDevice);
}

// round 16
// speedup vs baseline: 3.3684x; 1.0898x over previous
#include <cuda_runtime.h>
#include <cuda_fp16.h>
#include <math.h>
#include <stdint.h>

// ---------------------------------------------------------------------------
// Problem constants
// ---------------------------------------------------------------------------
#define T_STEPS 512
#define BATCH   256
#define INF     1024
#define HIDDEN  1024
#define WROW    (INF + HIDDEN)
#define NCLS    512
#define BH      (BATCH * HIDDEN)      // 262144
#define TB      (T_STEPS * BATCH)     // 131072
#define NCTAS   128                   // persistent recurrence grid
#define NGRP    8                     // independent recurrence groups
#define GRP_CTAS 16                   // CTAs per group

// ---------------------------------------------------------------------------
// Device-global scratch (allocation-free rule)
// ---------------------------------------------------------------------------
__device__ float g_A[(size_t)T_STEPS * BH];       // x-projection + b_ih (fp32)
__device__ __half g_Xh[(size_t)TB * INF];         // X hi (fp16)
__device__ __half g_Hh[(size_t)T_STEPS * BH];     // H hi (fp16)
__device__ __half g_Wih_h[HIDDEN * WROW];         // W_ih hi (row stride WROW)
__device__ __half g_Who_h[NCLS * HIDDEN];         // W_ho hi
__device__ __half g_h0h[BH];                      // h0 hi
// Per-group barrier state, line-padded; gens monotonic across graph replays.
__device__ unsigned g_gcnt[NGRP * 32];
__device__ unsigned g_ggen[NGRP * 32];

// ---------------------------------------------------------------------------
// Portable PTX helpers (sm_80+ features only)
// ---------------------------------------------------------------------------
__device__ __forceinline__ uint32_t smem_to_u32(const void* p) {
    uint32_t a;
    asm("{ .reg .u64 t; cvta.to.shared.u64 t, %1; cvt.u32.u64 %0, t; }"
        : "=r"(a) : "l"(p));
    return a;
}

__device__ __forceinline__ void cp16(uint32_t dst, const void* src) {
    asm volatile("cp.async.cg.shared.global [%0], [%1], 16;"
                 :: "r"(dst), "l"(__cvta_generic_to_global(src)));
}
#define CP_COMMIT()  asm volatile("cp.async.commit_group;" ::: "memory")
#define CP_WAIT(n)   asm volatile("cp.async.wait_group %0;" :: "n"(n) : "memory")

#define LDSM4(r0, r1, r2, r3, addr) \
    asm volatile("ldmatrix.sync.aligned.m8n8.x4.shared.b16 {%0,%1,%2,%3}, [%4];" \
                 : "=r"(r0), "=r"(r1), "=r"(r2), "=r"(r3) : "r"(addr))

// D[16x8] += A[16x16] * B[16x8]^(col)  -- fp16 in, fp32 accum
__device__ __forceinline__ void mma_f16(float* c, const uint32_t* a, const uint32_t* b) {
    asm volatile(
        "mma.sync.aligned.m16n8k16.row.col.f32.f16.f16.f32 "
        "{%0,%1,%2,%3}, {%4,%5,%6,%7}, {%8,%9}, {%0,%1,%2,%3};"
        : "+f"(c[0]), "+f"(c[1]), "+f"(c[2]), "+f"(c[3])
        : "r"(a[0]), "r"(a[1]), "r"(a[2]), "r"(a[3]), "r"(b[0]), "r"(b[1]));
}

// ---------------------------------------------------------------------------
// Fused hi-only fp16 conversion: X + W_ih + W_ho + h0 in ONE launch
// ---------------------------------------------------------------------------
__global__ void convert_all(const float* __restrict__ x,
                            const float* __restrict__ W_ih,
                            const float* __restrict__ W_ho,
                            const float* __restrict__ h0)
{
    const long nx = (long)TB * INF / 4;
    const long n1 = (long)HIDDEN * WROW / 4;
    const long n2 = (long)NCLS * HIDDEN / 4;
    const long n3 = (long)BH / 4;
    const long tot = nx + n1 + n2 + n3;
    for (long i = blockIdx.x * (long)blockDim.x + threadIdx.x; i < tot;
         i += (long)gridDim.x * blockDim.x) {
        const float* s; __half* hi; long e;
        if (i < nx)                { s = x;    hi = g_Xh;    e = i * 4; }
        else if (i < nx + n1)      { s = W_ih; hi = g_Wih_h; e = (i - nx) * 4; }
        else if (i < nx + n1 + n2) { s = W_ho; hi = g_Who_h; e = (i - nx - n1) * 4; }
        else                       { s = h0;   hi = g_h0h;   e = (i - nx - n1 - n2) * 4; }
        float4 v = *(const float4*)(s + e);
        __half2 a, b;
        a.x = __float2half_rn(v.x); a.y = __float2half_rn(v.y);
        b.x = __float2half_rn(v.z); b.y = __float2half_rn(v.w);
        *(__half2*)(hi + e)     = a;
        *(__half2*)(hi + e + 2) = b;
    }
}

// ---------------------------------------------------------------------------
// mma.sync pure-fp16 GEMM (phases 1 & 3), 2 CTAs/SM occupancy.
// CTA tile 128x128, BK=64, 8 warps (4M x 2N), 2-stage cp.async, 1 sync/chunk.
// ---------------------------------------------------------------------------
#define GROWB  144                   // 128B data + 16 pad
#define G_MAT  (128 * GROWB)         // 18432
#define G_STG  (2 * G_MAT)           // A | B = 36864
#define G_SMEM (2 * G_STG)           // 73728  (x2 CTAs = 147456 < 227KB)

__global__ void __launch_bounds__(256, 2)
gemm_f16(const __half* __restrict__ A, long lda,
         const __half* __restrict__ B, long ldb,
         const float* __restrict__ bias, float* __restrict__ C, long ldc, int K)
{
    extern __shared__ char smem[];
    const uint32_t sb = smem_to_u32(smem);
    const int tid = threadIdx.x, lane = tid & 31, wid = tid >> 5;
    const int wm = wid & 3, wn = wid >> 2;
    const long bm = (long)blockIdx.y * 128;
    const long bn = (long)blockIdx.x * 128;

    float c[2][8][4];
#pragma unroll
    for (int m = 0; m < 2; m++)
#pragma unroll
        for (int n = 0; n < 8; n++)
#pragma unroll
            for (int j = 0; j < 4; j++) c[m][n][j] = 0.0f;

    const uint32_t a_rb  = (uint32_t)(lane & 15) * GROWB + (uint32_t)(lane >> 4) * 16;
    const uint32_t b4_rb = (uint32_t)((lane & 7) + ((lane >> 4) << 3)) * GROWB
                           + (uint32_t)((lane >> 3) & 1) * 16;

    auto load_chunk = [&](int kc, int stage) {
        uint32_t base = sb + stage * G_STG;
#pragma unroll
        for (int it = 0; it < 4; it++) {
            int u = tid + it * 256;
            int row = u >> 3, seg = u & 7;
            uint32_t so = row * GROWB + seg * 16;
            cp16(base + so,         A + (bm + row) * lda + kc + seg * 8);
            cp16(base + G_MAT + so, B + (bn + row) * ldb + kc + seg * 8);
        }
    };

    const int nchunk = K >> 6;      // BK = 64
    load_chunk(0, 0);
    CP_COMMIT();

    for (int ch = 0; ch < nchunk; ch++) {
        CP_WAIT(0);
        __syncthreads();          // chunk ch landed + visible to all threads
        if (ch + 1 < nchunk) {
            load_chunk((ch + 1) << 6, (ch + 1) & 1);
            CP_COMMIT();
        }

        const uint32_t base = sb + (ch & 1) * G_STG;
#pragma unroll
        for (int k16 = 0; k16 < 4; k16++) {
            const uint32_t kb = k16 * 32;
            uint32_t ah[2][4], bh[8][2];
#pragma unroll
            for (int m = 0; m < 2; m++) {
                uint32_t ra = base + (uint32_t)(wm * 32 + m * 16) * GROWB + kb + a_rb;
                LDSM4(ah[m][0], ah[m][1], ah[m][2], ah[m][3], ra);
            }
#pragma unroll
            for (int p = 0; p < 4; p++) {
                uint32_t rb = base + G_MAT + (uint32_t)(wn * 64 + p * 16) * GROWB + kb + b4_rb;
                LDSM4(bh[2*p][0], bh[2*p][1], bh[2*p+1][0], bh[2*p+1][1], rb);
            }
#pragma unroll
            for (int m = 0; m < 2; m++)
#pragma unroll
                for (int n = 0; n < 8; n++)
                    mma_f16(c[m][n], ah[m], bh[n]);
        }
    }

#pragma unroll
    for (int m = 0; m < 2; m++) {
        long r0 = bm + wm * 32 + m * 16 + (lane >> 2);
        long r1 = r0 + 8;
#pragma unroll
        for (int n = 0; n < 8; n++) {
            long col = bn + wn * 64 + n * 8 + (lane & 3) * 2;
            float bx = bias[col], by = bias[col + 1];
            float2 v0 = { c[m][n][0] + bx, c[m][n][1] + by };
            float2 v1 = { c[m][n][2] + bx, c[m][n][3] + by };
            *(float2*)(C + r0 * ldc + col) = v0;
            *(float2*)(C + r1 * ldc + col) = v1;
        }
    }
}

// ---------------------------------------------------------------------------
// Per-group barrier (16 CTAs); groups fully decoupled closed systems.
// ---------------------------------------------------------------------------
__device__ __forceinline__ void group_bar(int g, unsigned& lgen)
{
    __syncthreads();
    if (threadIdx.x == 0) {
        __threadfence();
        if (atomicAdd(&g_gcnt[g * 32], 1u) == GRP_CTAS - 1) {
            atomicExch(&g_gcnt[g * 32], 0u);
            __threadfence();
            atomicAdd(&g_ggen[g * 32], 1u);
        } else {
            while (*(volatile unsigned*)&g_ggen[g * 32] == lgen) { __nanosleep(16); }
            __threadfence();
        }
        lgen++;
    }
    __syncthreads();
}

// ---------------------------------------------------------------------------
// Persistent recurrence (fp16 x1, W resident, 4-stage pipe, rotation):
//   h_t = tanh(g_A[t] + h_{t-1} @ W_h^T)
// R14-proven pipeline ordering: CP_WAIT -> __syncthreads -> compute every
// iteration (cp.async wait only orders the ISSUING thread's copies; the sync
// after the wait is what makes them visible across threads -- the R15 bug).
// h_last (t = T-1) written directly to the output buffer (no memcpy node).
// ---------------------------------------------------------------------------
#define A_RB      272                        // 256B data + 16 pad (streamed A)
#define RB_ROWB   2064                       // 2048B data + 16 pad (resident W)
#define RBH_SZ    (64 * RB_ROWB)             // 132096
#define RA_SZ     (32 * A_RB)                // 8704 per stage
#define R_STAGES  4
#define R2_SMEM   (RBH_SZ + R_STAGES * RA_SZ)  // 166912

__global__ void __launch_bounds__(256, 1)
rnn_recur(float* __restrict__ hlast_out)
{
    extern __shared__ char smem[];
    const uint32_t sb = smem_to_u32(smem);
    const int tid = threadIdx.x, lane = tid & 31, wid = tid >> 5;
    const int wm = wid & 1, wn = wid >> 1;       // 2 x 4 warp grid
    const int grp = blockIdx.x >> 4;             // group (0..7)
    const int gn  = blockIdx.x & 15;             // n tile within group
    const int bm  = grp * 32;                    // batch rows [bm, bm+32)
    const int bn  = gn * 64;                     // hidden cols [bn, bn+64)
    const int start = gn >> 1;                   // rotation: own-column chunk first

    const uint32_t a_rb   = (uint32_t)(lane & 15) * A_RB + (uint32_t)(lane >> 4) * 16;
    const uint32_t b4h_rb = (uint32_t)((lane & 7) + ((lane >> 4) << 3)) * RB_ROWB
                            + (uint32_t)((lane >> 3) & 1) * 16;

    // ---- Resident W_h hi tile: 64 rows x 1024 fp16 (8192 x 16B units)
    for (int u = tid; u < 8192; u += 256) {
        int row = u >> 7, seg = u & 127;
        cp16(sb + row * RB_ROWB + seg * 16,
             g_Wih_h + (size_t)(bn + row) * WROW + INF + seg * 8);
    }
    CP_COMMIT();

    unsigned lgen = *(volatile unsigned*)&g_ggen[grp * 32];

    // Epilogue coordinates + first-step pre-activation prefetch
    const int er0 = bm + wm * 16 + (lane >> 2);
    const int ec0 = bn + wn * 16 + (lane & 3) * 2;
    float2 pre[2][2];
#pragma unroll
    for (int n = 0; n < 2; n++) {
        pre[n][0] = *(const float2*)(g_A + (size_t)er0       * HIDDEN + ec0 + n * 8);
        pre[n][1] = *(const float2*)(g_A + (size_t)(er0 + 8) * HIDDEN + ec0 + n * 8);
    }

    for (int t = 0; t < T_STEPS; t++) {
        const __half* hh = (t == 0) ? g_h0h : (g_Hh + (size_t)(t - 1) * BH);
        const size_t ob = (size_t)t * BH;

        float c[2][4];
#pragma unroll
        for (int n = 0; n < 2; n++)
#pragma unroll
            for (int j = 0; j < 4; j++) c[n][j] = 0.0f;

        // Stream A hi chunk cc (BK=128): 512 x 16B units (2/thread)
        auto load_chunk = [&](int cc, int stage) {
            uint32_t base = sb + RBH_SZ + stage * RA_SZ;
            const int kc = cc << 7;
#pragma unroll
            for (int it = 0; it < 2; it++) {
                int u = tid + it * 256;
                int row = u >> 4, seg = u & 15;
                cp16(base + row * A_RB + seg * 16,
                     hh + (size_t)(bm + row) * HIDDEN + kc + seg * 8);
            }
        };

        // Prologue: fill 3 stages
#pragma unroll
        for (int i = 0; i < 3; i++) {
            load_chunk((start + i) & 7, i);
            CP_COMMIT();
        }

#pragma unroll
        for (int i = 0; i < 8; i++) {
            const int cc = (start + i) & 7;
            // Wait until chunk i has landed (groups complete FIFO)
            if (i <= 5)      CP_WAIT(2);
            else if (i == 6) CP_WAIT(1);
            else             CP_WAIT(0);
            __syncthreads();       // landing visible to ALL threads; stage reuse safe
            if (i < 5) {
                load_chunk((start + i + 3) & 7, (i + 3) & 3);
                CP_COMMIT();
            }

            const uint32_t abase = sb + RBH_SZ + (i & 3) * RA_SZ
                                   + (uint32_t)(wm * 16) * A_RB + a_rb;
            const uint32_t bhb   = sb + (uint32_t)(wn * 16) * RB_ROWB
                                   + (uint32_t)(cc << 8) + b4h_rb;

            // Fragment-pipelined k16 loop (8 iters, double-buffered)
            uint32_t ah[2][4], bh[2][2][2];

#define R_LD(k16, buf) do { \
        LDSM4(ah[buf][0], ah[buf][1], ah[buf][2], ah[buf][3], \
              abase + (uint32_t)((k16) * 32)); \
        LDSM4(bh[buf][0][0], bh[buf][0][1], bh[buf][1][0], bh[buf][1][1], \
              bhb + (uint32_t)((k16) * 32)); \
    } while (0)

            R_LD(0, 0);
#pragma unroll
            for (int k16 = 0; k16 < 8; k16++) {
                if (k16 < 7) R_LD(k16 + 1, (k16 + 1) & 1);
                const int b = k16 & 1;
#pragma unroll
                for (int n = 0; n < 2; n++)
                    mma_f16(c[n], ah[b], bh[b][n]);
            }
#undef R_LD
        }

        // Epilogue: tanh(acc + pre), store fp16 hi (+ fp32 h_last at t=T-1)
        {
            const int r0 = er0, r1 = er0 + 8;
#pragma unroll
            for (int n = 0; n < 2; n++) {
                const int col = ec0 + n * 8;
                float h00 = tanhf(c[n][0] + pre[n][0].x);
                float h01 = tanhf(c[n][1] + pre[n][0].y);
                float h10 = tanhf(c[n][2] + pre[n][1].x);
                float h11 = tanhf(c[n][3] + pre[n][1].y);

                __half2 th;
                th.x = __float2half_rn(h00); th.y = __float2half_rn(h01);
                *(__half2*)(g_Hh + ob + (size_t)r0 * HIDDEN + col) = th;
                th.x = __float2half_rn(h10); th.y = __float2half_rn(h11);
                *(__half2*)(g_Hh + ob + (size_t)r1 * HIDDEN + col) = th;

                if (t == T_STEPS - 1) {
                    float2 f0 = { h00, h01 }, f1 = { h10, h11 };
                    *(float2*)(hlast_out + (size_t)r0 * HIDDEN + col) = f0;
                    *(float2*)(hlast_out + (size_t)r1 * HIDDEN + col) = f1;
                }
            }
        }

        // Prefetch next step's pre-activations BEFORE the barrier (independent
        // of h_t -- hides the gmem latency behind the rendezvous wait).
        if (t + 1 < T_STEPS) {
            const size_t ob1 = (size_t)(t + 1) * BH;
#pragma unroll
            for (int n = 0; n < 2; n++) {
                pre[n][0] = *(const float2*)(g_A + ob1 + (size_t)er0       * HIDDEN + ec0 + n * 8);
                pre[n][1] = *(const float2*)(g_A + ob1 + (size_t)(er0 + 8) * HIDDEN + ec0 + n * 8);
            }
        }

        group_bar(grp, lgen);   // 16-CTA rendezvous; groups fully decoupled
    }
}

// ---------------------------------------------------------------------------
// In-place softmax over rows of 512 floats
// ---------------------------------------------------------------------------
__global__ void softmax512(float* __restrict__ O)
{
    __shared__ float red[4];
    long row = blockIdx.x;
    float4* p = (float4*)(O + row * (long)NCLS);
    float4 v = p[threadIdx.x];

    float m = fmaxf(fmaxf(v.x, v.y), fmaxf(v.z, v.w));
#pragma unroll
    for (int o = 16; o > 0; o >>= 1)
        m = fmaxf(m, __shfl_xor_sync(0xffffffffu, m, o));
    int warp = threadIdx.x >> 5;
    if ((threadIdx.x & 31) == 0) red[warp] = m;
    __syncthreads();
    m = fmaxf(fmaxf(red[0], red[1]), fmaxf(red[2], red[3]));

    float4 e;
    e.x = __expf(v.x - m);
    e.y = __expf(v.y - m);
    e.z = __expf(v.z - m);
    e.w = __expf(v.w - m);
    float s = e.x + e.y + e.z + e.w;
#pragma unroll
    for (int o = 16; o > 0; o >>= 1)
        s += __shfl_xor_sync(0xffffffffu, s, o);
    __syncthreads();
    if ((threadIdx.x & 31) == 0) red[warp] = s;
    __syncthreads();
    s = red[0] + red[1] + red[2] + red[3];

    float inv = 1.0f / s;
    e.x *= inv; e.y *= inv; e.z *= inv; e.w *= inv;
    p[threadIdx.x] = e;
}

// ---------------------------------------------------------------------------
// Launch (5 graph nodes)
// ---------------------------------------------------------------------------
extern "C" void kernel_launch(void* const* d_in, const int* in_sizes, int n_in,
                              void* d_out, int out_size)
{
    const float* x    = (const float*)d_in[0];
    const float* h0   = (const float*)d_in[1];
    const float* W_ih = (const float*)d_in[2];
    const float* b_ih = (const float*)d_in[3];
    const float* W_ho = (const float*)d_in[4];
    const float* b_ho = (const float*)d_in[5];
    float*       out  = (float*)d_out;

    float* pA;
    __half *pXh, *pHh, *pWih_h, *pWoh;
    cudaGetSymbolAddress((void**)&pA,     g_A);
    cudaGetSymbolAddress((void**)&pXh,    g_Xh);
    cudaGetSymbolAddress((void**)&pHh,    g_Hh);
    cudaGetSymbolAddress((void**)&pWih_h, g_Wih_h);
    cudaGetSymbolAddress((void**)&pWoh,   g_Who_h);

    cudaFuncSetAttribute(gemm_f16,
                         cudaFuncAttributeMaxDynamicSharedMemorySize, G_SMEM);
    cudaFuncSetAttribute(rnn_recur,
                         cudaFuncAttributeMaxDynamicSharedMemorySize, R2_SMEM);

    // #1: all fp16 conversions in one launch
    convert_all<<<4096, 256>>>(x, W_ih, W_ho, h0);

    // #2: Phase 1 -- g_A = Xh @ Wx_h^T + b_ih   (pure fp16, 2 CTAs/SM)
    {
        dim3 grid(HIDDEN / 128, TB / 128);   // (8, 1024)
        gemm_f16<<<grid, 256, G_SMEM>>>(pXh, INF, pWih_h, WROW,
                                        b_ih, pA, HIDDEN, INF);
    }

    // #3: Phase 2 -- persistent recurrence; writes h_last directly to out
    rnn_recur<<<NCTAS, 256, R2_SMEM>>>(out + (long)TB * NCLS);

    // #4/#5: Phase 3 -- out = Hh @ Who_h^T + b_ho (pure fp16), softmax
    {
        dim3 grid(NCLS / 128, TB / 128);     // (4, 1024)
        gemm_f16<<<grid, 256, G_SMEM>>>(pHh, HIDDEN, pWoh, HIDDEN,
                                        b_ho, out, NCLS, HIDDEN);
        softmax512<<<TB, 128>>>(out);
    }
}